// round 2
// baseline (speedup 1.0000x reference)
#include <cuda_runtime.h>

#define S 2048
#define F 1024
#define H 16
#define DH 64
#define NHD 1024  // H*DH

// Scratch (device globals: allocation-free per harness rules)
__device__ float g_q[S * NHD];
__device__ float g_k[S * NHD];
__device__ float g_v[S * NHD];
__device__ float g_r[S * NHD];
__device__ float g_attn[S * NHD];
__device__ float g_ck[H * S];   // ck[h][j] = r_w_bias[h] . k[j,h,:]
__device__ float g_cr[H * S];   // cr[h][m] = r_r_bias[h] . r_key[m,h,:]

// ---------------------------------------------------------------------------
// fp32 SGEMM: C[M,N] = A[M,K] @ B[K,N] + bias[N]
// 128x128 block tile, K-tile 8, 256 threads, 8x8 micro-tile, double-buffered.
// ---------------------------------------------------------------------------
__device__ __forceinline__ void sgemm_body(
    const float* __restrict__ A, const float* __restrict__ B,
    const float* __restrict__ bias, float* __restrict__ C,
    int M, int N, int K)
{
    __shared__ float As[2][8][128];
    __shared__ float Bs[2][8][128];

    const int t  = threadIdx.x;
    const int tx = t & 15;
    const int ty = t >> 4;
    const int m0 = blockIdx.y * 128;
    const int n0 = blockIdx.x * 128;

    float acc[8][8];
#pragma unroll
    for (int r = 0; r < 8; r++)
#pragma unroll
        for (int c = 0; c < 8; c++) acc[r][c] = 0.f;

    const int arow = t >> 1;          // 0..127
    const int acol = (t & 1) * 4;     // 0 or 4
    const int brow = t >> 5;          // 0..7
    const int bcol = (t & 31) * 4;    // 0..124

    const float* Aptr = A + (size_t)(m0 + arow) * K + acol;
    const float* Bptr = B + (size_t)brow * N + n0 + bcol;

    // preload k0 = 0
    float4 av = *(const float4*)Aptr;
    float4 bv = *(const float4*)Bptr;
    As[0][acol + 0][arow] = av.x;
    As[0][acol + 1][arow] = av.y;
    As[0][acol + 2][arow] = av.z;
    As[0][acol + 3][arow] = av.w;
    *(float4*)&Bs[0][brow][bcol] = bv;
    __syncthreads();

    int buf = 0;
    for (int k0 = 0; k0 < K; k0 += 8) {
        const bool has = (k0 + 8) < K;
        if (has) {
            av = *(const float4*)(Aptr + k0 + 8);
            bv = *(const float4*)(Bptr + (size_t)(k0 + 8) * N);
        }
#pragma unroll
        for (int kk = 0; kk < 8; kk++) {
            float a[8], b[8];
            *(float4*)&a[0] = *(const float4*)&As[buf][kk][ty * 8];
            *(float4*)&a[4] = *(const float4*)&As[buf][kk][ty * 8 + 4];
            *(float4*)&b[0] = *(const float4*)&Bs[buf][kk][tx * 8];
            *(float4*)&b[4] = *(const float4*)&Bs[buf][kk][tx * 8 + 4];
#pragma unroll
            for (int r = 0; r < 8; r++)
#pragma unroll
                for (int c = 0; c < 8; c++)
                    acc[r][c] = fmaf(a[r], b[c], acc[r][c]);
        }
        if (has) {
            As[buf ^ 1][acol + 0][arow] = av.x;
            As[buf ^ 1][acol + 1][arow] = av.y;
            As[buf ^ 1][acol + 2][arow] = av.z;
            As[buf ^ 1][acol + 3][arow] = av.w;
            *(float4*)&Bs[buf ^ 1][brow][bcol] = bv;
            __syncthreads();
            buf ^= 1;
        }
    }

#pragma unroll
    for (int r = 0; r < 8; r++) {
        const int row = m0 + ty * 8 + r;
#pragma unroll
        for (int c = 0; c < 8; c += 4) {
            const int col = n0 + tx * 8 + c;
            float4 o;
            o.x = acc[r][c + 0] + bias[col + 0];
            o.y = acc[r][c + 1] + bias[col + 1];
            o.z = acc[r][c + 2] + bias[col + 2];
            o.w = acc[r][c + 3] + bias[col + 3];
            *(float4*)(C + (size_t)row * N + col) = o;
        }
    }
}

// Batched q/k/v/r projection: z selects which GEMM.
__global__ __launch_bounds__(256, 2) void proj_kernel(
    const float* __restrict__ Xq, const float* __restrict__ Xr,
    const float* __restrict__ Wq, const float* __restrict__ Wk,
    const float* __restrict__ Wv, const float* __restrict__ Wr,
    const float* __restrict__ bq, const float* __restrict__ bk,
    const float* __restrict__ bv, const float* __restrict__ br)
{
    const float* A;
    const float* B;
    const float* bias;
    float* C;
    switch (blockIdx.z) {
        case 0:  A = Xq; B = Wq; bias = bq; C = g_q; break;
        case 1:  A = Xq; B = Wk; bias = bk; C = g_k; break;
        case 2:  A = Xq; B = Wv; bias = bv; C = g_v; break;
        default: A = Xr; B = Wr; bias = br; C = g_r; break;
    }
    sgemm_body(A, B, bias, C, S, NHD, F);
}

// Output projection: d_out = g_attn @ Wo + bo
__global__ __launch_bounds__(256, 2) void out_kernel(
    const float* __restrict__ Wo, const float* __restrict__ bo,
    float* __restrict__ out)
{
    sgemm_body(g_attn, Wo, bo, out, S, F, NHD);
}

// ---------------------------------------------------------------------------
// Precompute ck[h][j] = rw[h].k[j,h,:] and cr[h][m] = rr[h].r[m,h,:].
// One warp per dot product; lane d handles elements d and d+32.
// ---------------------------------------------------------------------------
__global__ __launch_bounds__(256) void bias_dots_kernel(
    const float* __restrict__ rwb, const float* __restrict__ rrb)
{
    const int gw   = (blockIdx.x * blockDim.x + threadIdx.x) >> 5;
    const int lane = threadIdx.x & 31;
    const int which = gw >= H * S;          // 0 -> ck, 1 -> cr
    const int idx   = which ? gw - H * S : gw;
    const int hh = idx >> 11;               // / S
    const int j  = idx & (S - 1);
    const float* bias = which ? rrb : rwb;
    const float* mat  = which ? g_r : g_k;
    const float b0 = bias[hh * DH + lane];
    const float b1 = bias[hh * DH + 32 + lane];
    const float* row = mat + (size_t)j * NHD + hh * DH;
    float s = fmaf(b0, row[lane], b1 * row[32 + lane]);
#pragma unroll
    for (int off = 16; off > 0; off >>= 1)
        s += __shfl_xor_sync(0xffffffffu, s, off);
    if (lane == 0) {
        float* dst = which ? g_cr : g_ck;
        dst[hh * S + j] = s;
    }
}

// ---------------------------------------------------------------------------
// Causal flash attention with Transformer-XL relative position term.
// score[i,j] = (q_i.k_j + q_i.r_m + ck[j] + cr[m]) / 8,  m = S-1+j-i, j <= i
// Grid: (S/64 qtiles, H). 256 threads, 4x4 micro-tile of the 64x64 score tile.
// smem = 82432 B -> 2 CTAs/SM.
// ---------------------------------------------------------------------------
__global__ __launch_bounds__(256, 2) void attn_kernel()
{
    const int h = blockIdx.y;
    // heavier query tiles first for better tail behavior
    const int qi0 = (gridDim.x - 1 - blockIdx.x) * 64;

    extern __shared__ float sm[];
    float* qt  = sm;              // 64x64 query tile
    float* kt  = qt + 4096;       // 64x64 key tile; reused as P tile
    float* vt  = kt + 4096;       // 64x64 value tile
    float* rs  = vt + 4096;       // 127x64 r_key diagonal slab
    float* cks = rs + 127 * 64;   // 64
    float* crs = cks + 64;        // 128 (127 used)

    const int t    = threadIdx.x;
    const int tx   = t & 15;
    const int ty   = t >> 4;
    const int row0 = ty * 4;
    const int col0 = tx * 4;
    const int hb   = h * DH;

    // load q tile (raw q; biases folded into ck/cr)
    for (int idx = t; idx < 64 * 16; idx += 256) {
        const int r = idx >> 4;
        const int d = (idx & 15) << 2;
        *(float4*)&qt[r * 64 + d] =
            *(const float4*)&g_q[(size_t)(qi0 + r) * NHD + hb + d];
    }

    float m_i[4], l_i[4], oa[4][4];
#pragma unroll
    for (int r = 0; r < 4; r++) {
        m_i[r] = -1e30f;
        l_i[r] = 0.f;
#pragma unroll
        for (int c = 0; c < 4; c++) oa[r][c] = 0.f;
    }

    const int nkt = qi0 / 64 + 1;
    const int mmb = 63 + col0 - row0;  // rs/cr row for (r,c) is mmb + c - r

    for (int ktile = 0; ktile < nkt; ++ktile) {
        const int kj0 = ktile * 64;
        __syncthreads();  // protect kt/vt/rs (and first-iter q stores)

        // load key/value tiles
        for (int idx = t; idx < 64 * 16; idx += 256) {
            const int r = idx >> 4;
            const int d = (idx & 15) << 2;
            *(float4*)&kt[r * 64 + d] =
                *(const float4*)&g_k[(size_t)(kj0 + r) * NHD + hb + d];
            *(float4*)&vt[r * 64 + d] =
                *(const float4*)&g_v[(size_t)(kj0 + r) * NHD + hb + d];
        }
        // load r_key slab rows base..base+126 (clamped; overflow rows masked)
        const int base = (S - 1) + kj0 - qi0 - 63;
        for (int idx = t; idx < 127 * 16; idx += 256) {
            const int mm = idx >> 4;
            const int d  = (idx & 15) << 2;
            int mg = base + mm;
            if (mg > S - 1) mg = S - 1;
            *(float4*)&rs[mm * 64 + d] =
                *(const float4*)&g_r[(size_t)mg * NHD + hb + d];
        }
        // load scalar correction rows
        if (t < 64) {
            cks[t] = g_ck[h * S + kj0 + t];
        } else if (t < 192) {
            const int mm = t - 64;
            if (mm < 127) {
                int mg = base + mm;
                if (mg > S - 1) mg = S - 1;
                crs[mm] = g_cr[h * S + mg];
            }
        }
        __syncthreads();

        // ---- scores: q.k + q.r (diagonal gather) + ck + cr ----
        float sc[4][4];
#pragma unroll
        for (int r = 0; r < 4; r++)
#pragma unroll
            for (int c = 0; c < 4; c++)
                sc[r][c] = cks[col0 + c] + crs[mmb + c - r];

        for (int d = 0; d < 64; d += 4) {
            float qv[4][4], bk[4][4], rv[7][4];
#pragma unroll
            for (int r = 0; r < 4; r++) {
                *(float4*)qv[r] = *(const float4*)&qt[(row0 + r) * 64 + d];
                *(float4*)bk[r] = *(const float4*)&kt[(col0 + r) * 64 + d];
            }
#pragma unroll
            for (int u = 0; u < 7; u++)
                *(float4*)rv[u] = *(const float4*)&rs[(mmb - 3 + u) * 64 + d];
#pragma unroll
            for (int r = 0; r < 4; r++)
#pragma unroll
                for (int c = 0; c < 4; c++) {
                    float s = sc[r][c];
#pragma unroll
                    for (int e = 0; e < 4; e++)
                        s = fmaf(qv[r][e], bk[c][e],
                                 fmaf(qv[r][e], rv[3 + c - r][e], s));
                    sc[r][c] = s;
                }
        }

        // ---- online softmax (scale 1/8, causal mask on diagonal tile) ----
        const bool diag = (ktile == nkt - 1);
#pragma unroll
        for (int r = 0; r < 4; r++) {
            float rmax = -1e30f;
#pragma unroll
            for (int c = 0; c < 4; c++) {
                float s = sc[r][c] * 0.125f;
                if (diag && (col0 + c) > (row0 + r)) s = -1e30f;
                sc[r][c] = s;
                rmax = fmaxf(rmax, s);
            }
#pragma unroll
            for (int off = 8; off > 0; off >>= 1)
                rmax = fmaxf(rmax, __shfl_xor_sync(0xffffffffu, rmax, off));
            const float newm  = fmaxf(m_i[r], rmax);
            const float alpha = __expf(m_i[r] - newm);
            m_i[r] = newm;
            float psum = 0.f;
#pragma unroll
            for (int c = 0; c < 4; c++) {
                const float p = __expf(sc[r][c] - newm);
                sc[r][c] = p;
                psum += p;
            }
#pragma unroll
            for (int off = 8; off > 0; off >>= 1)
                psum += __shfl_xor_sync(0xffffffffu, psum, off);
            l_i[r] = l_i[r] * alpha + psum;
#pragma unroll
            for (int c = 0; c < 4; c++) oa[r][c] *= alpha;
        }

        // ---- P @ V (P reuses the kt buffer) ----
        __syncthreads();  // everyone done reading kt
        float* ps = kt;
#pragma unroll
        for (int r = 0; r < 4; r++)
            *(float4*)&ps[(row0 + r) * 64 + col0] = *(float4*)sc[r];
        __syncthreads();

#pragma unroll 8
        for (int k = 0; k < 64; k++) {
            const float4 vv = *(const float4*)&vt[k * 64 + col0];
            float p[4];
#pragma unroll
            for (int r = 0; r < 4; r++) p[r] = ps[(row0 + r) * 64 + k];
#pragma unroll
            for (int r = 0; r < 4; r++) {
                oa[r][0] = fmaf(p[r], vv.x, oa[r][0]);
                oa[r][1] = fmaf(p[r], vv.y, oa[r][1]);
                oa[r][2] = fmaf(p[r], vv.z, oa[r][2]);
                oa[r][3] = fmaf(p[r], vv.w, oa[r][3]);
            }
        }
    }

    // ---- epilogue: normalize and store [s, h*64+d] ----
#pragma unroll
    for (int r = 0; r < 4; r++) {
        const float inv = 1.f / l_i[r];
        float4 o;
        o.x = oa[r][0] * inv;
        o.y = oa[r][1] * inv;
        o.z = oa[r][2] * inv;
        o.w = oa[r][3] * inv;
        *(float4*)&g_attn[(size_t)(qi0 + row0 + r) * NHD + hb + col0] = o;
    }
}

// ---------------------------------------------------------------------------
extern "C" void kernel_launch(void* const* d_in, const int* in_sizes, int n_in,
                              void* d_out, int out_size)
{
    const float* inputs_q = (const float*)d_in[0];
    const float* pos_emb  = (const float*)d_in[1];
    const float* r_w_bias = (const float*)d_in[2];
    const float* r_r_bias = (const float*)d_in[3];
    const float* Wq = (const float*)d_in[4];
    const float* bq = (const float*)d_in[5];
    const float* Wk = (const float*)d_in[6];
    const float* bk = (const float*)d_in[7];
    const float* Wv = (const float*)d_in[8];
    const float* bv = (const float*)d_in[9];
    const float* Wr = (const float*)d_in[10];
    const float* br = (const float*)d_in[11];
    const float* Wo = (const float*)d_in[12];
    const float* bo = (const float*)d_in[13];
    float* out = (float*)d_out;

    const int smem_attn = (3 * 64 * 64 + 127 * 64 + 64 + 128) * (int)sizeof(float);
    cudaFuncSetAttribute(attn_kernel,
                         cudaFuncAttributeMaxDynamicSharedMemorySize, smem_attn);

    // 1) q/k/v/r projections (one batched launch, 512 blocks)
    proj_kernel<<<dim3(NHD / 128, S / 128, 4), 256>>>(
        inputs_q, pos_emb, Wq, Wk, Wv, Wr, bq, bk, bv, br);

    // 2) per-(head,row) bias dot products ck/cr
    bias_dots_kernel<<<(2 * H * S * 32) / 256, 256>>>(r_w_bias, r_r_bias);

    // 3) fused causal attention with relative-shift BD term
    attn_kernel<<<dim3(S / 64, H), 256, smem_attn>>>();

    // 4) output projection
    out_kernel<<<dim3(F / 128, S / 128), 256>>>(Wo, bo, out);
}

// round 3
// speedup vs baseline: 2.3507x; 2.3507x over previous
#include <cuda_runtime.h>

#define S 2048
#define F 1024
#define H 16
#define DH 64
#define NHD 1024  // H*DH

typedef unsigned long long u64;

// ---- packed fp32x2 helpers (Blackwell FFMA2 path) ----
__device__ __forceinline__ u64 pk2(float lo, float hi) {
    u64 r;
    asm("mov.b64 %0, {%1, %2};" : "=l"(r) : "f"(lo), "f"(hi));
    return r;
}
__device__ __forceinline__ void upk2(u64 v, float& lo, float& hi) {
    asm("mov.b64 {%0, %1}, %2;" : "=f"(lo), "=f"(hi) : "l"(v));
}
__device__ __forceinline__ u64 ffma2(u64 a, u64 b, u64 c) {
    u64 d;
    asm("fma.rn.f32x2 %0, %1, %2, %3;" : "=l"(d) : "l"(a), "l"(b), "l"(c));
    return d;
}
__device__ __forceinline__ u64 fmul2(u64 a, u64 b) {
    u64 d;
    asm("mul.rn.f32x2 %0, %1, %2;" : "=l"(d) : "l"(a), "l"(b));
    return d;
}

// Scratch (device globals: allocation-free per harness rules)
__device__ float g_q[S * NHD];
__device__ float g_k[S * NHD];
__device__ float g_v[S * NHD];
__device__ float g_r[S * NHD];
__device__ float g_attn[S * NHD];
__device__ float g_ck[H * S];   // ck[h][j] = r_w_bias[h] . k[j,h,:]
__device__ float g_cr[H * S];   // cr[h][m] = r_r_bias[h] . r_key[m,h,:]

// ---------------------------------------------------------------------------
// fp32 SGEMM: C[M,N] = A[M,K] @ B[K,N] + bias[N]
// 128x128 tile, K-tile 8, 256 threads, 8x8 micro-tile, double-buffered,
// FFMA2-packed accumulators (row pairs).
// ---------------------------------------------------------------------------
__device__ __forceinline__ void sgemm_body(
    const float* __restrict__ A, const float* __restrict__ B,
    const float* __restrict__ bias, float* __restrict__ C,
    int M, int N, int K)
{
    __shared__ float As[2][8][128];
    __shared__ float Bs[2][8][128];

    const int t  = threadIdx.x;
    const int tx = t & 15;
    const int ty = t >> 4;
    const int m0 = blockIdx.y * 128;
    const int n0 = blockIdx.x * 128;

    u64 acc2[4][8];
#pragma unroll
    for (int i = 0; i < 4; i++)
#pragma unroll
        for (int c = 0; c < 8; c++) acc2[i][c] = 0ULL;

    const int arow = t >> 1;          // 0..127
    const int acol = (t & 1) * 4;     // 0 or 4
    const int brow = t >> 5;          // 0..7
    const int bcol = (t & 31) * 4;    // 0..124

    const float* Aptr = A + (size_t)(m0 + arow) * K + acol;
    const float* Bptr = B + (size_t)brow * N + n0 + bcol;

    float4 av = *(const float4*)Aptr;
    float4 bv = *(const float4*)Bptr;
    As[0][acol + 0][arow] = av.x;
    As[0][acol + 1][arow] = av.y;
    As[0][acol + 2][arow] = av.z;
    As[0][acol + 3][arow] = av.w;
    *(float4*)&Bs[0][brow][bcol] = bv;
    __syncthreads();

    int buf = 0;
    for (int k0 = 0; k0 < K; k0 += 8) {
        const bool has = (k0 + 8) < K;
        if (has) {
            av = *(const float4*)(Aptr + k0 + 8);
            bv = *(const float4*)(Bptr + (size_t)(k0 + 8) * N);
        }
#pragma unroll
        for (int kk = 0; kk < 8; kk++) {
            // a: row pairs (ty*8+2i, ty*8+2i+1) packed directly from smem
            ulonglong2 a01 = *(const ulonglong2*)&As[buf][kk][ty * 8];
            ulonglong2 a23 = *(const ulonglong2*)&As[buf][kk][ty * 8 + 4];
            u64 ap[4] = {a01.x, a01.y, a23.x, a23.y};
            float bs[8];
            *(float4*)&bs[0] = *(const float4*)&Bs[buf][kk][tx * 4];
            *(float4*)&bs[4] = *(const float4*)&Bs[buf][kk][64 + tx * 4];
            u64 bd[8];
#pragma unroll
            for (int c = 0; c < 8; c++) bd[c] = pk2(bs[c], bs[c]);
#pragma unroll
            for (int i = 0; i < 4; i++)
#pragma unroll
                for (int c = 0; c < 8; c++)
                    acc2[i][c] = ffma2(ap[i], bd[c], acc2[i][c]);
        }
        if (has) {
            As[buf ^ 1][acol + 0][arow] = av.x;
            As[buf ^ 1][acol + 1][arow] = av.y;
            As[buf ^ 1][acol + 2][arow] = av.z;
            As[buf ^ 1][acol + 3][arow] = av.w;
            *(float4*)&Bs[buf ^ 1][brow][bcol] = bv;
            __syncthreads();
            buf ^= 1;
        }
    }

    const int ca = n0 + tx * 4;
    const int cb = n0 + 64 + tx * 4;
    float4 ba = *(const float4*)&bias[ca];
    float4 bb = *(const float4*)&bias[cb];
#pragma unroll
    for (int i = 0; i < 4; i++) {
        const int r0 = m0 + ty * 8 + 2 * i;
        float lo[8], hi[8];
#pragma unroll
        for (int c = 0; c < 8; c++) upk2(acc2[i][c], lo[c], hi[c]);
        float4 o;
        o.x = lo[0] + ba.x; o.y = lo[1] + ba.y; o.z = lo[2] + ba.z; o.w = lo[3] + ba.w;
        *(float4*)(C + (size_t)r0 * N + ca) = o;
        o.x = lo[4] + bb.x; o.y = lo[5] + bb.y; o.z = lo[6] + bb.z; o.w = lo[7] + bb.w;
        *(float4*)(C + (size_t)r0 * N + cb) = o;
        o.x = hi[0] + ba.x; o.y = hi[1] + ba.y; o.z = hi[2] + ba.z; o.w = hi[3] + ba.w;
        *(float4*)(C + (size_t)(r0 + 1) * N + ca) = o;
        o.x = hi[4] + bb.x; o.y = hi[5] + bb.y; o.z = hi[6] + bb.z; o.w = hi[7] + bb.w;
        *(float4*)(C + (size_t)(r0 + 1) * N + cb) = o;
    }
}

__global__ __launch_bounds__(256, 2) void proj_kernel(
    const float* __restrict__ Xq, const float* __restrict__ Xr,
    const float* __restrict__ Wq, const float* __restrict__ Wk,
    const float* __restrict__ Wv, const float* __restrict__ Wr,
    const float* __restrict__ bq, const float* __restrict__ bk,
    const float* __restrict__ bv, const float* __restrict__ br)
{
    const float* A;
    const float* B;
    const float* bias;
    float* C;
    switch (blockIdx.z) {
        case 0:  A = Xq; B = Wq; bias = bq; C = g_q; break;
        case 1:  A = Xq; B = Wk; bias = bk; C = g_k; break;
        case 2:  A = Xq; B = Wv; bias = bv; C = g_v; break;
        default: A = Xr; B = Wr; bias = br; C = g_r; break;
    }
    sgemm_body(A, B, bias, C, S, NHD, F);
}

__global__ __launch_bounds__(256, 2) void out_kernel(
    const float* __restrict__ Wo, const float* __restrict__ bo,
    float* __restrict__ out)
{
    sgemm_body(g_attn, Wo, bo, out, S, F, NHD);
}

// ---------------------------------------------------------------------------
// ck[h][j] = rw[h].k[j,h,:],  cr[h][m] = rr[h].r[m,h,:]
// ---------------------------------------------------------------------------
__global__ __launch_bounds__(256) void bias_dots_kernel(
    const float* __restrict__ rwb, const float* __restrict__ rrb)
{
    const int gw   = (blockIdx.x * blockDim.x + threadIdx.x) >> 5;
    const int lane = threadIdx.x & 31;
    const int which = gw >= H * S;
    const int idx   = which ? gw - H * S : gw;
    const int hh = idx >> 11;
    const int j  = idx & (S - 1);
    const float* bias = which ? rrb : rwb;
    const float* mat  = which ? g_r : g_k;
    const float b0 = bias[hh * DH + lane];
    const float b1 = bias[hh * DH + 32 + lane];
    const float* row = mat + (size_t)j * NHD + hh * DH;
    float s = fmaf(b0, row[lane], b1 * row[32 + lane]);
#pragma unroll
    for (int off = 16; off > 0; off >>= 1)
        s += __shfl_xor_sync(0xffffffffu, s, off);
    if (lane == 0) {
        float* dst = which ? g_cr : g_ck;
        dst[hh * S + j] = s;
    }
}

// ---------------------------------------------------------------------------
// Swizzled smem addressing for 64-float rows: granule = (d>>2) ^ (row>>2).
// Conflict-free for both tile-fill stores and score-loop loads.
// ---------------------------------------------------------------------------
__device__ __forceinline__ int SW(int row, int d) {
    return (row << 6) + (((((d >> 2) ^ (row >> 2)) & 15)) << 2);
}
__device__ __forceinline__ int SWe(int row, int k) {   // scalar element
    return SW(row, k) + (k & 3);
}

// ---------------------------------------------------------------------------
// Causal flash attention with Transformer-XL relative position term.
// score[i,j] = (q_i.k_j + q_i.r_m + ck[j] + cr[m]) / 8,  m = S-1+j-i, j <= i
// ---------------------------------------------------------------------------
__global__ __launch_bounds__(256, 2) void attn_kernel()
{
    const int h = blockIdx.y;
    const int qi0 = (gridDim.x - 1 - blockIdx.x) * 64;  // heavy tiles first

    extern __shared__ float sm[];
    float* qt  = sm;              // 64x64 query tile (swizzled)
    float* kt  = qt + 4096;       // 64x64 key tile (swizzled); reused as P
    float* vt  = kt + 4096;       // 64x64 value tile (swizzled)
    float* rs  = vt + 4096;       // 127x64 r_key slab (swizzled)
    float* cks = rs + 127 * 64;   // 64
    float* crs = cks + 64;        // 128 (127 used)

    const int t    = threadIdx.x;
    const int tx   = t & 15;
    const int ty   = t >> 4;
    const int row0 = ty * 4;
    const int col0 = tx * 4;
    const int hb   = h * DH;

    for (int idx = t; idx < 64 * 16; idx += 256) {
        const int r = idx >> 4;
        const int d = (idx & 15) << 2;
        *(float4*)&qt[SW(r, d)] =
            *(const float4*)&g_q[(size_t)(qi0 + r) * NHD + hb + d];
    }

    float m_i[4], l_i[4];
    u64 oa2[4][2];
#pragma unroll
    for (int r = 0; r < 4; r++) {
        m_i[r] = -1e30f;
        l_i[r] = 0.f;
        oa2[r][0] = 0ULL;
        oa2[r][1] = 0ULL;
    }

    const int nkt = qi0 / 64 + 1;
    const int mmb = 63 + col0 - row0;  // cr/rs row for (r,c): mmb + c - r

    for (int ktile = 0; ktile < nkt; ++ktile) {
        const int kj0 = ktile * 64;
        __syncthreads();

        for (int idx = t; idx < 64 * 16; idx += 256) {
            const int r = idx >> 4;
            const int d = (idx & 15) << 2;
            *(float4*)&kt[SW(r, d)] =
                *(const float4*)&g_k[(size_t)(kj0 + r) * NHD + hb + d];
            *(float4*)&vt[SW(r, d)] =
                *(const float4*)&g_v[(size_t)(kj0 + r) * NHD + hb + d];
        }
        const int base = (S - 1) + kj0 - qi0 - 63;
        for (int idx = t; idx < 127 * 16; idx += 256) {
            const int mm = idx >> 4;
            const int d  = (idx & 15) << 2;
            int mg = base + mm;
            if (mg > S - 1) mg = S - 1;
            *(float4*)&rs[SW(mm, d)] =
                *(const float4*)&g_r[(size_t)mg * NHD + hb + d];
        }
        if (t < 64) {
            cks[t] = g_ck[h * S + kj0 + t];
        } else if (t < 192) {
            const int mm = t - 64;
            if (mm < 127) {
                int mg = base + mm;
                if (mg > S - 1) mg = S - 1;
                crs[mm] = g_cr[h * S + mg];
            }
        }
        __syncthreads();

        // ---- scores (packed over head-dim pairs) ----
        u64 sc2[4][4];
#pragma unroll
        for (int r = 0; r < 4; r++)
#pragma unroll
            for (int c = 0; c < 4; c++)
                sc2[r][c] = pk2(cks[col0 + c] + crs[mmb + c - r], 0.f);

        // pass 1: q . k
        for (int d = 0; d < 64; d += 4) {
            u64 bk2[4][2];
#pragma unroll
            for (int c = 0; c < 4; c++) {
                ulonglong2 v = *(const ulonglong2*)&kt[SW(col0 + c, d)];
                bk2[c][0] = v.x;
                bk2[c][1] = v.y;
            }
#pragma unroll
            for (int r = 0; r < 4; r++) {
                ulonglong2 q = *(const ulonglong2*)&qt[SW(row0 + r, d)];
#pragma unroll
                for (int c = 0; c < 4; c++) {
                    sc2[r][c] = ffma2(q.x, bk2[c][0], sc2[r][c]);
                    sc2[r][c] = ffma2(q.y, bk2[c][1], sc2[r][c]);
                }
            }
        }
        // pass 2: q . r (diagonal gather)
        for (int d = 0; d < 64; d += 4) {
            u64 rv2[7][2];
#pragma unroll
            for (int u = 0; u < 7; u++) {
                ulonglong2 v = *(const ulonglong2*)&rs[SW(mmb - 3 + u, d)];
                rv2[u][0] = v.x;
                rv2[u][1] = v.y;
            }
#pragma unroll
            for (int r = 0; r < 4; r++) {
                ulonglong2 q = *(const ulonglong2*)&qt[SW(row0 + r, d)];
#pragma unroll
                for (int c = 0; c < 4; c++) {
                    const int u = 3 + c - r;
                    sc2[r][c] = ffma2(q.x, rv2[u][0], sc2[r][c]);
                    sc2[r][c] = ffma2(q.y, rv2[u][1], sc2[r][c]);
                }
            }
        }

        float sc[4][4];
#pragma unroll
        for (int r = 0; r < 4; r++)
#pragma unroll
            for (int c = 0; c < 4; c++) {
                float lo, hi;
                upk2(sc2[r][c], lo, hi);
                sc[r][c] = lo + hi;
            }

        // ---- online softmax ----
        const bool diag = (ktile == nkt - 1);
#pragma unroll
        for (int r = 0; r < 4; r++) {
            float rmax = -1e30f;
#pragma unroll
            for (int c = 0; c < 4; c++) {
                float s = sc[r][c] * 0.125f;
                if (diag && (col0 + c) > (row0 + r)) s = -1e30f;
                sc[r][c] = s;
                rmax = fmaxf(rmax, s);
            }
#pragma unroll
            for (int off = 8; off > 0; off >>= 1)
                rmax = fmaxf(rmax, __shfl_xor_sync(0xffffffffu, rmax, off));
            const float newm  = fmaxf(m_i[r], rmax);
            const float alpha = __expf(m_i[r] - newm);
            m_i[r] = newm;
            float psum = 0.f;
#pragma unroll
            for (int c = 0; c < 4; c++) {
                const float p = __expf(sc[r][c] - newm);
                sc[r][c] = p;
                psum += p;
            }
#pragma unroll
            for (int off = 8; off > 0; off >>= 1)
                psum += __shfl_xor_sync(0xffffffffu, psum, off);
            l_i[r] = l_i[r] * alpha + psum;
            const u64 a2 = pk2(alpha, alpha);
            oa2[r][0] = fmul2(oa2[r][0], a2);
            oa2[r][1] = fmul2(oa2[r][1], a2);
        }

        // ---- P @ V (P reuses kt buffer, swizzled) ----
        __syncthreads();
        float* ps = kt;
#pragma unroll
        for (int r = 0; r < 4; r++)
            *(float4*)&ps[SW(row0 + r, col0)] = *(float4*)sc[r];
        __syncthreads();

#pragma unroll 4
        for (int k = 0; k < 64; k++) {
            ulonglong2 vv = *(const ulonglong2*)&vt[SW(k, col0)];
#pragma unroll
            for (int r = 0; r < 4; r++) {
                const float p = ps[SWe(row0 + r, k)];
                const u64 p2 = pk2(p, p);
                oa2[r][0] = ffma2(p2, vv.x, oa2[r][0]);
                oa2[r][1] = ffma2(p2, vv.y, oa2[r][1]);
            }
        }
    }

    // ---- epilogue ----
#pragma unroll
    for (int r = 0; r < 4; r++) {
        const float inv = 1.f / l_i[r];
        float4 o;
        upk2(oa2[r][0], o.x, o.y);
        upk2(oa2[r][1], o.z, o.w);
        o.x *= inv; o.y *= inv; o.z *= inv; o.w *= inv;
        *(float4*)&g_attn[(size_t)(qi0 + row0 + r) * NHD + hb + col0] = o;
    }
}

// ---------------------------------------------------------------------------
extern "C" void kernel_launch(void* const* d_in, const int* in_sizes, int n_in,
                              void* d_out, int out_size)
{
    const float* inputs_q = (const float*)d_in[0];
    const float* pos_emb  = (const float*)d_in[1];
    const float* r_w_bias = (const float*)d_in[2];
    const float* r_r_bias = (const float*)d_in[3];
    const float* Wq = (const float*)d_in[4];
    const float* bq = (const float*)d_in[5];
    const float* Wk = (const float*)d_in[6];
    const float* bk = (const float*)d_in[7];
    const float* Wv = (const float*)d_in[8];
    const float* bv = (const float*)d_in[9];
    const float* Wr = (const float*)d_in[10];
    const float* br = (const float*)d_in[11];
    const float* Wo = (const float*)d_in[12];
    const float* bo = (const float*)d_in[13];
    float* out = (float*)d_out;

    const int smem_attn = (3 * 64 * 64 + 127 * 64 + 64 + 128) * (int)sizeof(float);
    cudaFuncSetAttribute(attn_kernel,
                         cudaFuncAttributeMaxDynamicSharedMemorySize, smem_attn);

    proj_kernel<<<dim3(NHD / 128, S / 128, 4), 256>>>(
        inputs_q, pos_emb, Wq, Wk, Wv, Wr, bq, bk, bv, br);

    bias_dots_kernel<<<(2 * H * S * 32) / 256, 256>>>(r_w_bias, r_r_bias);

    attn_kernel<<<dim3(S / 64, H), 256, smem_attn>>>();

    out_kernel<<<dim3(F / 128, S / 128), 256>>>(Wo, bo, out);
}

// round 4
// speedup vs baseline: 3.8377x; 1.6326x over previous
#include <cuda_runtime.h>

#define S 2048
#define F 1024
#define H 16
#define DH 64
#define NHD 1024  // H*DH

typedef unsigned long long u64;
typedef unsigned int u32;

// ---- packed fp32x2 helpers (Blackwell FFMA2 path) ----
__device__ __forceinline__ u64 pk2(float lo, float hi) {
    u64 r;
    asm("mov.b64 %0, {%1, %2};" : "=l"(r) : "f"(lo), "f"(hi));
    return r;
}
__device__ __forceinline__ void upk2(u64 v, float& lo, float& hi) {
    asm("mov.b64 {%0, %1}, %2;" : "=f"(lo), "=f"(hi) : "l"(v));
}
__device__ __forceinline__ u64 ffma2(u64 a, u64 b, u64 c) {
    u64 d;
    asm("fma.rn.f32x2 %0, %1, %2, %3;" : "=l"(d) : "l"(a), "l"(b), "l"(c));
    return d;
}

// ---- tf32 helpers ----
__device__ __forceinline__ u32 f2tf32(float x) {
    u32 r;
    asm("cvt.rna.tf32.f32 %0, %1;" : "=r"(r) : "f"(x));
    return r;
}
__device__ __forceinline__ float f2tf32f(float x) {
    return __uint_as_float(f2tf32(x));
}
// D += A(16x8,row) * B(8x8,col);  fp32 accum
__device__ __forceinline__ void mma_tf32(float c[4], const u32 a[4], u32 b0, u32 b1) {
    asm volatile(
        "mma.sync.aligned.m16n8k8.row.col.f32.tf32.tf32.f32 "
        "{%0,%1,%2,%3}, {%4,%5,%6,%7}, {%8,%9}, {%0,%1,%2,%3};\n"
        : "+f"(c[0]), "+f"(c[1]), "+f"(c[2]), "+f"(c[3])
        : "r"(a[0]), "r"(a[1]), "r"(a[2]), "r"(a[3]), "r"(b0), "r"(b1));
}

// Scratch (device globals: allocation-free per harness rules)
__device__ float g_q[S * NHD];
__device__ float g_k[S * NHD];
__device__ float g_v[S * NHD];
__device__ float g_r[S * NHD];
__device__ float g_attn[S * NHD];
__device__ float g_ck[H * S];   // ck[h][j] = r_w_bias[h] . k[j,h,:]
__device__ float g_cr[H * S];   // cr[h][m] = r_r_bias[h] . r_key[m,h,:]

// ---------------------------------------------------------------------------
// fp32 SGEMM (FFMA2): C[M,N] = A[M,K] @ B[K,N] + bias[N]   (unchanged, works)
// ---------------------------------------------------------------------------
__device__ __forceinline__ void sgemm_body(
    const float* __restrict__ A, const float* __restrict__ B,
    const float* __restrict__ bias, float* __restrict__ C,
    int M, int N, int K)
{
    __shared__ float As[2][8][128];
    __shared__ float Bs[2][8][128];

    const int t  = threadIdx.x;
    const int tx = t & 15;
    const int ty = t >> 4;
    const int m0 = blockIdx.y * 128;
    const int n0 = blockIdx.x * 128;

    u64 acc2[4][8];
#pragma unroll
    for (int i = 0; i < 4; i++)
#pragma unroll
        for (int c = 0; c < 8; c++) acc2[i][c] = 0ULL;

    const int arow = t >> 1;
    const int acol = (t & 1) * 4;
    const int brow = t >> 5;
    const int bcol = (t & 31) * 4;

    const float* Aptr = A + (size_t)(m0 + arow) * K + acol;
    const float* Bptr = B + (size_t)brow * N + n0 + bcol;

    float4 av = *(const float4*)Aptr;
    float4 bv = *(const float4*)Bptr;
    As[0][acol + 0][arow] = av.x;
    As[0][acol + 1][arow] = av.y;
    As[0][acol + 2][arow] = av.z;
    As[0][acol + 3][arow] = av.w;
    *(float4*)&Bs[0][brow][bcol] = bv;
    __syncthreads();

    int buf = 0;
    for (int k0 = 0; k0 < K; k0 += 8) {
        const bool has = (k0 + 8) < K;
        if (has) {
            av = *(const float4*)(Aptr + k0 + 8);
            bv = *(const float4*)(Bptr + (size_t)(k0 + 8) * N);
        }
#pragma unroll
        for (int kk = 0; kk < 8; kk++) {
            ulonglong2 a01 = *(const ulonglong2*)&As[buf][kk][ty * 8];
            ulonglong2 a23 = *(const ulonglong2*)&As[buf][kk][ty * 8 + 4];
            u64 ap[4] = {a01.x, a01.y, a23.x, a23.y};
            float bs[8];
            *(float4*)&bs[0] = *(const float4*)&Bs[buf][kk][tx * 4];
            *(float4*)&bs[4] = *(const float4*)&Bs[buf][kk][64 + tx * 4];
            u64 bd[8];
#pragma unroll
            for (int c = 0; c < 8; c++) bd[c] = pk2(bs[c], bs[c]);
#pragma unroll
            for (int i = 0; i < 4; i++)
#pragma unroll
                for (int c = 0; c < 8; c++)
                    acc2[i][c] = ffma2(ap[i], bd[c], acc2[i][c]);
        }
        if (has) {
            As[buf ^ 1][acol + 0][arow] = av.x;
            As[buf ^ 1][acol + 1][arow] = av.y;
            As[buf ^ 1][acol + 2][arow] = av.z;
            As[buf ^ 1][acol + 3][arow] = av.w;
            *(float4*)&Bs[buf ^ 1][brow][bcol] = bv;
            __syncthreads();
            buf ^= 1;
        }
    }

    const int ca = n0 + tx * 4;
    const int cb = n0 + 64 + tx * 4;
    float4 ba = *(const float4*)&bias[ca];
    float4 bb = *(const float4*)&bias[cb];
#pragma unroll
    for (int i = 0; i < 4; i++) {
        const int r0 = m0 + ty * 8 + 2 * i;
        float lo[8], hi[8];
#pragma unroll
        for (int c = 0; c < 8; c++) upk2(acc2[i][c], lo[c], hi[c]);
        float4 o;
        o.x = lo[0] + ba.x; o.y = lo[1] + ba.y; o.z = lo[2] + ba.z; o.w = lo[3] + ba.w;
        *(float4*)(C + (size_t)r0 * N + ca) = o;
        o.x = lo[4] + bb.x; o.y = lo[5] + bb.y; o.z = lo[6] + bb.z; o.w = lo[7] + bb.w;
        *(float4*)(C + (size_t)r0 * N + cb) = o;
        o.x = hi[0] + ba.x; o.y = hi[1] + ba.y; o.z = hi[2] + ba.z; o.w = hi[3] + ba.w;
        *(float4*)(C + (size_t)(r0 + 1) * N + ca) = o;
        o.x = hi[4] + bb.x; o.y = hi[5] + bb.y; o.z = hi[6] + bb.z; o.w = hi[7] + bb.w;
        *(float4*)(C + (size_t)(r0 + 1) * N + cb) = o;
    }
}

__global__ __launch_bounds__(256, 2) void proj_kernel(
    const float* __restrict__ Xq, const float* __restrict__ Xr,
    const float* __restrict__ Wq, const float* __restrict__ Wk,
    const float* __restrict__ Wv, const float* __restrict__ Wr,
    const float* __restrict__ bq, const float* __restrict__ bk,
    const float* __restrict__ bv, const float* __restrict__ br)
{
    const float* A;
    const float* B;
    const float* bias;
    float* C;
    switch (blockIdx.z) {
        case 0:  A = Xq; B = Wq; bias = bq; C = g_q; break;
        case 1:  A = Xq; B = Wk; bias = bk; C = g_k; break;
        case 2:  A = Xq; B = Wv; bias = bv; C = g_v; break;
        default: A = Xr; B = Wr; bias = br; C = g_r; break;
    }
    sgemm_body(A, B, bias, C, S, NHD, F);
}

__global__ __launch_bounds__(256, 2) void out_kernel(
    const float* __restrict__ Wo, const float* __restrict__ bo,
    float* __restrict__ out)
{
    sgemm_body(g_attn, Wo, bo, out, S, F, NHD);
}

// ---------------------------------------------------------------------------
// ck[h][j] = rw[h].k[j,h,:],  cr[h][m] = rr[h].r[m,h,:]
// ---------------------------------------------------------------------------
__global__ __launch_bounds__(256) void bias_dots_kernel(
    const float* __restrict__ rwb, const float* __restrict__ rrb)
{
    const int gw   = (blockIdx.x * blockDim.x + threadIdx.x) >> 5;
    const int lane = threadIdx.x & 31;
    const int which = gw >= H * S;
    const int idx   = which ? gw - H * S : gw;
    const int hh = idx >> 11;
    const int j  = idx & (S - 1);
    const float* bias = which ? rrb : rwb;
    const float* mat  = which ? g_r : g_k;
    const float b0 = bias[hh * DH + lane];
    const float b1 = bias[hh * DH + 32 + lane];
    const float* row = mat + (size_t)j * NHD + hh * DH;
    float s = fmaf(b0, row[lane], b1 * row[32 + lane]);
#pragma unroll
    for (int off = 16; off > 0; off >>= 1)
        s += __shfl_xor_sync(0xffffffffu, s, off);
    if (lane == 0) {
        float* dst = which ? g_cr : g_ck;
        dst[hh * S + j] = s;
    }
}

// ---------------------------------------------------------------------------
// Causal flash attention, tensor-core (mma.sync tf32) version.
// score[i,j] = (q_i.k_j + q_i.r_m + ck[j] + cr[m]) / 8,  m = S-1+j-i, j <= i
// Per CTA: (head, 64 q-rows), 128 threads, 4 warps x 16 rows.
//   AC  = Q @ K^T                  (acc preloaded with ck)
//   G   = Q @ RSL^T  -> smem       (acc preloaded with cr); BD = G[i, 63+j-i]
//   PV  = P @ V   (P via smem, tf32)
// ---------------------------------------------------------------------------
#define KPAD 68
#define VPAD 72
#define GPAD 132
#define SMEM_ATTN ((64*KPAD + 64*VPAD + 127*KPAD + 64*GPAD + 128 + 64) * 4)

__global__ __launch_bounds__(128) void attn_kernel()
{
    const int h   = blockIdx.y;
    const int qi0 = (gridDim.x - 1 - blockIdx.x) * 64;  // heavy tiles first

    extern __shared__ float sm[];
    float* ks    = sm;                 // 64 x KPAD  (tf32); reused as P tile
    float* vs    = ks + 64 * KPAD;     // 64 x VPAD  (tf32)
    float* rsl   = vs + 64 * VPAD;     // 127 x KPAD (tf32)
    float* G     = rsl + 127 * KPAD;   // 64 x GPAD  (fp32)
    float* crs_s = G + 64 * GPAD;      // 128
    float* cks_s = crs_s + 128;        // 64

    const int t    = threadIdx.x;
    const int lane = t & 31;
    const int w    = t >> 5;        // warp id: rows w*16 .. w*16+15
    const int g    = lane >> 2;     // 0..7
    const int tg   = lane & 3;      // 0..3
    const int i0   = w * 16 + g;    // local row (upper half of c-frag)
    const int hb   = h * DH;

    // ---- persistent Q a-frags (tf32) ----
    u32 qa[8][4];
    {
        const float* q0 = &g_q[(size_t)(qi0 + i0) * NHD + hb];
        const float* q1 = q0 + 8 * NHD;
#pragma unroll
        for (int k0 = 0; k0 < 8; k0++) {
            qa[k0][0] = f2tf32(q0[k0 * 8 + tg]);
            qa[k0][1] = f2tf32(q1[k0 * 8 + tg]);
            qa[k0][2] = f2tf32(q0[k0 * 8 + tg + 4]);
            qa[k0][3] = f2tf32(q1[k0 * 8 + tg + 4]);
        }
    }

    float O[8][4];
#pragma unroll
    for (int nt = 0; nt < 8; nt++) {
        O[nt][0] = 0.f; O[nt][1] = 0.f; O[nt][2] = 0.f; O[nt][3] = 0.f;
    }
    float m0 = -1e30f, m1 = -1e30f, l0 = 0.f, l1 = 0.f;

    const int nkt = qi0 / 64 + 1;
    for (int kt = 0; kt < nkt; kt++) {
        const int kj0  = kt * 64;
        const int base = (S - 1) + kj0 - qi0 - 63;
        __syncthreads();  // previous PV/G consumers done before refill

        // ---- fills (fp32 -> tf32) ----
        for (int idx = t; idx < 64 * 16; idx += 128) {
            const int r  = idx >> 4;
            const int d4 = (idx & 15) << 2;
            float4 kv = *(const float4*)&g_k[(size_t)(kj0 + r) * NHD + hb + d4];
            float4 vv = *(const float4*)&g_v[(size_t)(kj0 + r) * NHD + hb + d4];
            float* kd = &ks[r * KPAD + d4];
            kd[0] = f2tf32f(kv.x); kd[1] = f2tf32f(kv.y);
            kd[2] = f2tf32f(kv.z); kd[3] = f2tf32f(kv.w);
            float* vd = &vs[r * VPAD + d4];
            vd[0] = f2tf32f(vv.x); vd[1] = f2tf32f(vv.y);
            vd[2] = f2tf32f(vv.z); vd[3] = f2tf32f(vv.w);
        }
        for (int idx = t; idx < 127 * 16; idx += 128) {
            const int mm = idx >> 4;
            const int d4 = (idx & 15) << 2;
            int mg = base + mm;
            if (mg > S - 1) mg = S - 1;
            float4 rv = *(const float4*)&g_r[(size_t)mg * NHD + hb + d4];
            float* rd = &rsl[mm * KPAD + d4];
            rd[0] = f2tf32f(rv.x); rd[1] = f2tf32f(rv.y);
            rd[2] = f2tf32f(rv.z); rd[3] = f2tf32f(rv.w);
        }
        if (t < 64) cks_s[t] = g_ck[h * S + kj0 + t];
        {
            int mg = base + t;
            if (mg > S - 1) mg = S - 1;
            crs_s[t] = (t < 127) ? g_cr[h * S + mg] : 0.f;
        }
        __syncthreads();

        // ---- G = Q @ RSL^T (+cr), 2 halves of 64 cols ----
#pragma unroll
        for (int half = 0; half < 2; half++) {
            float gc[8][4];
#pragma unroll
            for (int nt = 0; nt < 8; nt++) {
                const int col = half * 64 + nt * 8 + 2 * tg;
                gc[nt][0] = crs_s[col];
                gc[nt][1] = crs_s[col + 1];
                gc[nt][2] = gc[nt][0];
                gc[nt][3] = gc[nt][1];
            }
#pragma unroll
            for (int k0 = 0; k0 < 8; k0++) {
#pragma unroll
                for (int nt = 0; nt < 8; nt++) {
                    const int n0 = half * 64 + nt * 8;
                    u32 b0 = __float_as_uint(rsl[(n0 + g) * KPAD + k0 * 8 + tg]);
                    u32 b1 = __float_as_uint(rsl[(n0 + g) * KPAD + k0 * 8 + tg + 4]);
                    mma_tf32(gc[nt], qa[k0], b0, b1);
                }
            }
#pragma unroll
            for (int nt = 0; nt < 8; nt++) {
                const int col = half * 64 + nt * 8 + 2 * tg;
                *(float2*)&G[i0 * GPAD + col]       = make_float2(gc[nt][0], gc[nt][1]);
                *(float2*)&G[(i0 + 8) * GPAD + col] = make_float2(gc[nt][2], gc[nt][3]);
            }
        }
        __syncwarp();  // G rows are warp-private; make stores visible in-warp

        // ---- AC = Q @ K^T (+ck) ----
        float sc[8][4];
#pragma unroll
        for (int nt = 0; nt < 8; nt++) {
            const int col = nt * 8 + 2 * tg;
            sc[nt][0] = cks_s[col];
            sc[nt][1] = cks_s[col + 1];
            sc[nt][2] = sc[nt][0];
            sc[nt][3] = sc[nt][1];
        }
#pragma unroll
        for (int k0 = 0; k0 < 8; k0++) {
#pragma unroll
            for (int nt = 0; nt < 8; nt++) {
                u32 b0 = __float_as_uint(ks[(nt * 8 + g) * KPAD + k0 * 8 + tg]);
                u32 b1 = __float_as_uint(ks[(nt * 8 + g) * KPAD + k0 * 8 + tg + 4]);
                mma_tf32(sc[nt], qa[k0], b0, b1);
            }
        }
        __syncthreads();  // all warps done reading ks before P overwrites it

        // ---- BD gather + online softmax ----
        const bool diag = (kt == nkt - 1);
        float rmax0 = -1e30f, rmax1 = -1e30f;
#pragma unroll
        for (int nt = 0; nt < 8; nt++) {
            const int j = nt * 8 + 2 * tg;
            float s00 = (sc[nt][0] + G[i0 * GPAD + 63 + j - i0]) * 0.125f;
            float s01 = (sc[nt][1] + G[i0 * GPAD + 64 + j - i0]) * 0.125f;
            float s10 = (sc[nt][2] + G[(i0 + 8) * GPAD + 55 + j - i0]) * 0.125f;
            float s11 = (sc[nt][3] + G[(i0 + 8) * GPAD + 56 + j - i0]) * 0.125f;
            if (diag) {
                if (kj0 + j     > qi0 + i0)     s00 = -1e30f;
                if (kj0 + j + 1 > qi0 + i0)     s01 = -1e30f;
                if (kj0 + j     > qi0 + i0 + 8) s10 = -1e30f;
                if (kj0 + j + 1 > qi0 + i0 + 8) s11 = -1e30f;
            }
            sc[nt][0] = s00; sc[nt][1] = s01; sc[nt][2] = s10; sc[nt][3] = s11;
            rmax0 = fmaxf(rmax0, fmaxf(s00, s01));
            rmax1 = fmaxf(rmax1, fmaxf(s10, s11));
        }
        rmax0 = fmaxf(rmax0, __shfl_xor_sync(0xffffffffu, rmax0, 1));
        rmax0 = fmaxf(rmax0, __shfl_xor_sync(0xffffffffu, rmax0, 2));
        rmax1 = fmaxf(rmax1, __shfl_xor_sync(0xffffffffu, rmax1, 1));
        rmax1 = fmaxf(rmax1, __shfl_xor_sync(0xffffffffu, rmax1, 2));

        const float newm0 = fmaxf(m0, rmax0);
        const float newm1 = fmaxf(m1, rmax1);
        const float a0 = __expf(m0 - newm0);
        const float a1 = __expf(m1 - newm1);
        m0 = newm0; m1 = newm1;

        float psum0 = 0.f, psum1 = 0.f;
#pragma unroll
        for (int nt = 0; nt < 8; nt++) {
            sc[nt][0] = __expf(sc[nt][0] - m0);
            sc[nt][1] = __expf(sc[nt][1] - m0);
            sc[nt][2] = __expf(sc[nt][2] - m1);
            sc[nt][3] = __expf(sc[nt][3] - m1);
            psum0 += sc[nt][0] + sc[nt][1];
            psum1 += sc[nt][2] + sc[nt][3];
        }
        psum0 += __shfl_xor_sync(0xffffffffu, psum0, 1);
        psum0 += __shfl_xor_sync(0xffffffffu, psum0, 2);
        psum1 += __shfl_xor_sync(0xffffffffu, psum1, 1);
        psum1 += __shfl_xor_sync(0xffffffffu, psum1, 2);
        l0 = l0 * a0 + psum0;
        l1 = l1 * a1 + psum1;
#pragma unroll
        for (int nt = 0; nt < 8; nt++) {
            O[nt][0] *= a0; O[nt][1] *= a0;
            O[nt][2] *= a1; O[nt][3] *= a1;
        }

        // ---- store P (tf32) into ks buffer ----
        float* psb = ks;
#pragma unroll
        for (int nt = 0; nt < 8; nt++) {
            const int j = nt * 8 + 2 * tg;
            *(float2*)&psb[i0 * KPAD + j] =
                make_float2(f2tf32f(sc[nt][0]), f2tf32f(sc[nt][1]));
            *(float2*)&psb[(i0 + 8) * KPAD + j] =
                make_float2(f2tf32f(sc[nt][2]), f2tf32f(sc[nt][3]));
        }
        __syncwarp();  // P rows are warp-private

        // ---- PV: O += P @ V ----
#pragma unroll
        for (int k0 = 0; k0 < 8; k0++) {
            u32 pa[4];
            pa[0] = __float_as_uint(psb[i0 * KPAD + k0 * 8 + tg]);
            pa[1] = __float_as_uint(psb[(i0 + 8) * KPAD + k0 * 8 + tg]);
            pa[2] = __float_as_uint(psb[i0 * KPAD + k0 * 8 + tg + 4]);
            pa[3] = __float_as_uint(psb[(i0 + 8) * KPAD + k0 * 8 + tg + 4]);
#pragma unroll
            for (int nt = 0; nt < 8; nt++) {
                u32 b0 = __float_as_uint(vs[(k0 * 8 + tg) * VPAD + nt * 8 + g]);
                u32 b1 = __float_as_uint(vs[(k0 * 8 + tg + 4) * VPAD + nt * 8 + g]);
                mma_tf32(O[nt], pa, b0, b1);
            }
        }
    }

    // ---- epilogue ----
    const float inv0 = 1.f / l0;
    const float inv1 = 1.f / l1;
#pragma unroll
    for (int nt = 0; nt < 8; nt++) {
        const int col = nt * 8 + 2 * tg;
        *(float2*)&g_attn[(size_t)(qi0 + i0) * NHD + hb + col] =
            make_float2(O[nt][0] * inv0, O[nt][1] * inv0);
        *(float2*)&g_attn[(size_t)(qi0 + i0 + 8) * NHD + hb + col] =
            make_float2(O[nt][2] * inv1, O[nt][3] * inv1);
    }
}

// ---------------------------------------------------------------------------
extern "C" void kernel_launch(void* const* d_in, const int* in_sizes, int n_in,
                              void* d_out, int out_size)
{
    const float* inputs_q = (const float*)d_in[0];
    const float* pos_emb  = (const float*)d_in[1];
    const float* r_w_bias = (const float*)d_in[2];
    const float* r_r_bias = (const float*)d_in[3];
    const float* Wq = (const float*)d_in[4];
    const float* bq = (const float*)d_in[5];
    const float* Wk = (const float*)d_in[6];
    const float* bk = (const float*)d_in[7];
    const float* Wv = (const float*)d_in[8];
    const float* bv = (const float*)d_in[9];
    const float* Wr = (const float*)d_in[10];
    const float* br = (const float*)d_in[11];
    const float* Wo = (const float*)d_in[12];
    const float* bo = (const float*)d_in[13];
    float* out = (float*)d_out;

    cudaFuncSetAttribute(attn_kernel,
                         cudaFuncAttributeMaxDynamicSharedMemorySize, SMEM_ATTN);

    proj_kernel<<<dim3(NHD / 128, S / 128, 4), 256>>>(
        inputs_q, pos_emb, Wq, Wk, Wv, Wr, bq, bk, bv, br);

    bias_dots_kernel<<<(2 * H * S * 32) / 256, 256>>>(r_w_bias, r_r_bias);

    attn_kernel<<<dim3(S / 64, H), 128, SMEM_ATTN>>>();

    out_kernel<<<dim3(F / 128, S / 128), 256>>>(Wo, bo, out);
}

// round 5
// speedup vs baseline: 4.9382x; 1.2867x over previous
#include <cuda_runtime.h>
#include <cuda_bf16.h>

#define S 2048
#define F 1024
#define H 16
#define DH 64
#define NHD 1024  // H*DH

typedef unsigned long long u64;
typedef unsigned int u32;

// ---- tf32 helpers (attention) ----
__device__ __forceinline__ u32 f2tf32(float x) {
    u32 r;
    asm("cvt.rna.tf32.f32 %0, %1;" : "=r"(r) : "f"(x));
    return r;
}
__device__ __forceinline__ float f2tf32f(float x) {
    return __uint_as_float(f2tf32(x));
}
__device__ __forceinline__ void mma_tf32(float c[4], const u32 a[4], u32 b0, u32 b1) {
    asm volatile(
        "mma.sync.aligned.m16n8k8.row.col.f32.tf32.tf32.f32 "
        "{%0,%1,%2,%3}, {%4,%5,%6,%7}, {%8,%9}, {%0,%1,%2,%3};\n"
        : "+f"(c[0]), "+f"(c[1]), "+f"(c[2]), "+f"(c[3])
        : "r"(a[0]), "r"(a[1]), "r"(a[2]), "r"(a[3]), "r"(b0), "r"(b1));
}

// ---- bf16 helpers (GEMMs) ----
__device__ __forceinline__ void mma_bf16(float c[4], const u32 a[4], u32 b0, u32 b1) {
    asm volatile(
        "mma.sync.aligned.m16n8k16.row.col.f32.bf16.bf16.f32 "
        "{%0,%1,%2,%3}, {%4,%5,%6,%7}, {%8,%9}, {%0,%1,%2,%3};\n"
        : "+f"(c[0]), "+f"(c[1]), "+f"(c[2]), "+f"(c[3])
        : "r"(a[0]), "r"(a[1]), "r"(a[2]), "r"(a[3]), "r"(b0), "r"(b1));
}
__device__ __forceinline__ void ldm2t(u32& d0, u32& d1, u32 saddr) {
    asm volatile("ldmatrix.sync.aligned.m8n8.x2.trans.shared.b16 {%0,%1}, [%2];"
                 : "=r"(d0), "=r"(d1) : "r"(saddr));
}
__device__ __forceinline__ u32 sptr(const void* p) {
    return (u32)__cvta_generic_to_shared(p);
}

// Scratch (device globals: allocation-free per harness rules)
__device__ float g_q[S * NHD];
__device__ float g_k[S * NHD];
__device__ float g_v[S * NHD];
__device__ float g_r[S * NHD];
__device__ float g_ck[H * S];
__device__ float g_cr[H * S];
// bf16 hi/lo split panels
__device__ __nv_bfloat16 g_xq_h[S * F],   g_xq_l[S * F];
__device__ __nv_bfloat16 g_xr_h[S * F],   g_xr_l[S * F];
__device__ __nv_bfloat16 g_wh[5 * F * NHD], g_wl[5 * F * NHD];  // Wq,Wk,Wv,Wr,Wo
__device__ __nv_bfloat16 g_at_h[S * NHD], g_at_l[S * NHD];

// ---------------------------------------------------------------------------
// Split fp32 -> (bf16 hi, bf16 lo) for all GEMM operands in ONE launch.
// Segments (float4 units): xq [0,524288), xr [524288,1048576),
// weights w=0..4 each 262144.
// ---------------------------------------------------------------------------
__global__ __launch_bounds__(256) void split_kernel(
    const float* __restrict__ xq, const float* __restrict__ xr,
    const float* __restrict__ w0, const float* __restrict__ w1,
    const float* __restrict__ w2, const float* __restrict__ w3,
    const float* __restrict__ w4)
{
    const int i = blockIdx.x * 256 + threadIdx.x;  // float4 index, < 2359296
    const float* src;
    __nv_bfloat16 *h, *l;
    int off;  // float4 offset within segment
    if (i < 524288)        { src = xq; h = g_xq_h; l = g_xq_l; off = i; }
    else if (i < 1048576)  { src = xr; h = g_xr_h; l = g_xr_l; off = i - 524288; }
    else {
        const int j = i - 1048576;
        const int w = j >> 18;          // /262144
        off = j & 262143;
        const float* ws[5] = {w0, w1, w2, w3, w4};
        src = ws[w];
        h = g_wh + (size_t)w * (F * NHD);
        l = g_wl + (size_t)w * (F * NHD);
    }
    float4 v = ((const float4*)src)[off];
    __nv_bfloat162 h0 = __floats2bfloat162_rn(v.x, v.y);
    __nv_bfloat162 h1 = __floats2bfloat162_rn(v.z, v.w);
    __nv_bfloat162 l0 = __floats2bfloat162_rn(v.x - __bfloat162float(h0.x),
                                              v.y - __bfloat162float(h0.y));
    __nv_bfloat162 l1 = __floats2bfloat162_rn(v.z - __bfloat162float(h1.x),
                                              v.w - __bfloat162float(h1.y));
    ((__nv_bfloat162*)h)[off * 2]     = h0;
    ((__nv_bfloat162*)h)[off * 2 + 1] = h1;
    ((__nv_bfloat162*)l)[off * 2]     = l0;
    ((__nv_bfloat162*)l)[off * 2 + 1] = l1;
}

// ---------------------------------------------------------------------------
// bf16 split-GEMM: C[M,N] = (Ah+Al)@(Bh+Bl) + bias  (drop Al*Bl term)
// CTA 128x128, 256 thr, 8 warps (4m x 2n), warp tile 32x64, K-chunk 32,
// double-buffered smem, 3 bf16 MMAs per operand pair per k16.
// smem layout (bf16 units): Ah[2][128*40] @0, Al @10240,
//                           Bh[2][32*136] @20480, Bl @29184. 75776 bytes.
// ---------------------------------------------------------------------------
#define GEMM_SMEM_BYTES 75776

__device__ __forceinline__ void gemm_bf16_body(
    const __nv_bfloat16* __restrict__ Ah, const __nv_bfloat16* __restrict__ Al,
    const __nv_bfloat16* __restrict__ Bh, const __nv_bfloat16* __restrict__ Bl,
    const float* __restrict__ bias, float* __restrict__ C,
    int M, int N, int K)
{
    extern __shared__ __nv_bfloat16 sb[];
    __nv_bfloat16* As_h = sb;
    __nv_bfloat16* As_l = sb + 10240;
    __nv_bfloat16* Bs_h = sb + 20480;
    __nv_bfloat16* Bs_l = sb + 29184;

    const int t    = threadIdx.x;
    const int lane = t & 31;
    const int w    = t >> 5;
    const int wm   = (w & 3) * 32;
    const int wn   = (w >> 2) * 64;
    const int g    = lane >> 2;
    const int tg   = lane & 3;
    const int m0   = blockIdx.y * 128;
    const int n0   = blockIdx.x * 128;

    float Cr[2][8][4];
#pragma unroll
    for (int mt = 0; mt < 2; mt++)
#pragma unroll
        for (int nt = 0; nt < 8; nt++) {
            Cr[mt][nt][0] = 0.f; Cr[mt][nt][1] = 0.f;
            Cr[mt][nt][2] = 0.f; Cr[mt][nt][3] = 0.f;
        }

    // fill mapping: A row fm, 16-bf16 half fh;  B row fk, 16-bf16 col fv
    const int fm = t >> 1, fh = (t & 1) * 16;
    const int fk = t >> 3, fv = (t & 7) * 16;

    const __nv_bfloat16* gAh = Ah + (size_t)(m0 + fm) * K + fh;
    const __nv_bfloat16* gAl = Al + (size_t)(m0 + fm) * K + fh;
    const __nv_bfloat16* gBh = Bh + (size_t)fk * N + n0 + fv;
    const __nv_bfloat16* gBl = Bl + (size_t)fk * N + n0 + fv;

    // preload chunk 0 into buf 0
    {
        uint4 r0 = *(const uint4*)gAh;
        uint4 r1 = *(const uint4*)(gAh + 8);
        uint4 r2 = *(const uint4*)gAl;
        uint4 r3 = *(const uint4*)(gAl + 8);
        uint4 r4 = *(const uint4*)gBh;
        uint4 r5 = *(const uint4*)(gBh + 8);
        uint4 r6 = *(const uint4*)gBl;
        uint4 r7 = *(const uint4*)(gBl + 8);
        __nv_bfloat16* sa = As_h + fm * 40 + fh;
        *(uint4*)sa = r0; *(uint4*)(sa + 8) = r1;
        sa = As_l + fm * 40 + fh;
        *(uint4*)sa = r2; *(uint4*)(sa + 8) = r3;
        __nv_bfloat16* sbp = Bs_h + fk * 136 + fv;
        *(uint4*)sbp = r4; *(uint4*)(sbp + 8) = r5;
        sbp = Bs_l + fk * 136 + fv;
        *(uint4*)sbp = r6; *(uint4*)(sbp + 8) = r7;
    }
    __syncthreads();

    int buf = 0;
    const int nkc = K / 32;
    for (int kc = 0; kc < nkc; kc++) {
        uint4 ra[8];
        const bool has = (kc + 1) < nkc;
        if (has) {
            const __nv_bfloat16* pAh = gAh + (kc + 1) * 32;
            const __nv_bfloat16* pAl = gAl + (kc + 1) * 32;
            const __nv_bfloat16* pBh = gBh + (size_t)(kc + 1) * 32 * N;
            const __nv_bfloat16* pBl = gBl + (size_t)(kc + 1) * 32 * N;
            ra[0] = *(const uint4*)pAh; ra[1] = *(const uint4*)(pAh + 8);
            ra[2] = *(const uint4*)pAl; ra[3] = *(const uint4*)(pAl + 8);
            ra[4] = *(const uint4*)pBh; ra[5] = *(const uint4*)(pBh + 8);
            ra[6] = *(const uint4*)pBl; ra[7] = *(const uint4*)(pBl + 8);
        }
        const __nv_bfloat16* Ab_h = As_h + buf * 5120;
        const __nv_bfloat16* Ab_l = As_l + buf * 5120;
        const __nv_bfloat16* Bb_h = Bs_h + buf * 4352;
        const __nv_bfloat16* Bb_l = Bs_l + buf * 4352;

#pragma unroll
        for (int ks2 = 0; ks2 < 2; ks2++) {
            const int ks = ks2 * 16;
            u32 ah[2][4], al[2][4];
#pragma unroll
            for (int mt = 0; mt < 2; mt++) {
                const __nv_bfloat16* r0 = Ab_h + (wm + mt * 16 + g) * 40 + ks + 2 * tg;
                ah[mt][0] = *(const u32*)r0;
                ah[mt][1] = *(const u32*)(r0 + 8 * 40);
                ah[mt][2] = *(const u32*)(r0 + 8);
                ah[mt][3] = *(const u32*)(r0 + 8 * 40 + 8);
                const __nv_bfloat16* r1 = Ab_l + (wm + mt * 16 + g) * 40 + ks + 2 * tg;
                al[mt][0] = *(const u32*)r1;
                al[mt][1] = *(const u32*)(r1 + 8 * 40);
                al[mt][2] = *(const u32*)(r1 + 8);
                al[mt][3] = *(const u32*)(r1 + 8 * 40 + 8);
            }
            const u32 bbh = sptr(Bb_h + (ks + (lane & 15)) * 136 + wn);
            const u32 bbl = sptr(Bb_l + (ks + (lane & 15)) * 136 + wn);
#pragma unroll
            for (int nt = 0; nt < 8; nt++) {
                u32 bh0, bh1, bl0, bl1;
                ldm2t(bh0, bh1, bbh + nt * 16);
                ldm2t(bl0, bl1, bbl + nt * 16);
#pragma unroll
                for (int mt = 0; mt < 2; mt++) {
                    mma_bf16(Cr[mt][nt], ah[mt], bh0, bh1);
                    mma_bf16(Cr[mt][nt], ah[mt], bl0, bl1);
                    mma_bf16(Cr[mt][nt], al[mt], bh0, bh1);
                }
            }
        }

        if (has) {
            __nv_bfloat16* sa = As_h + (buf ^ 1) * 5120 + fm * 40 + fh;
            *(uint4*)sa = ra[0]; *(uint4*)(sa + 8) = ra[1];
            sa = As_l + (buf ^ 1) * 5120 + fm * 40 + fh;
            *(uint4*)sa = ra[2]; *(uint4*)(sa + 8) = ra[3];
            __nv_bfloat16* sbp = Bs_h + (buf ^ 1) * 4352 + fk * 136 + fv;
            *(uint4*)sbp = ra[4]; *(uint4*)(sbp + 8) = ra[5];
            sbp = Bs_l + (buf ^ 1) * 4352 + fk * 136 + fv;
            *(uint4*)sbp = ra[6]; *(uint4*)(sbp + 8) = ra[7];
            __syncthreads();
            buf ^= 1;
        }
    }

    // epilogue
#pragma unroll
    for (int mt = 0; mt < 2; mt++) {
        const int row = m0 + wm + mt * 16 + g;
#pragma unroll
        for (int nt = 0; nt < 8; nt++) {
            const int col = n0 + wn + nt * 8 + 2 * tg;
            float2 b01 = *(const float2*)&bias[col];
            float2 o;
            o.x = Cr[mt][nt][0] + b01.x;
            o.y = Cr[mt][nt][1] + b01.y;
            *(float2*)(C + (size_t)row * N + col) = o;
            o.x = Cr[mt][nt][2] + b01.x;
            o.y = Cr[mt][nt][3] + b01.y;
            *(float2*)(C + (size_t)(row + 8) * N + col) = o;
        }
    }
}

__global__ __launch_bounds__(256) void proj_bf_kernel(
    const float* __restrict__ bq, const float* __restrict__ bk,
    const float* __restrict__ bv, const float* __restrict__ br)
{
    const int z = blockIdx.z;
    const __nv_bfloat16* Ah = (z < 3) ? g_xq_h : g_xr_h;
    const __nv_bfloat16* Al = (z < 3) ? g_xq_l : g_xr_l;
    const __nv_bfloat16* Bh = g_wh + (size_t)z * (F * NHD);
    const __nv_bfloat16* Bl = g_wl + (size_t)z * (F * NHD);
    const float* bias;
    float* C;
    switch (z) {
        case 0:  bias = bq; C = g_q; break;
        case 1:  bias = bk; C = g_k; break;
        case 2:  bias = bv; C = g_v; break;
        default: bias = br; C = g_r; break;
    }
    gemm_bf16_body(Ah, Al, Bh, Bl, bias, C, S, NHD, F);
}

__global__ __launch_bounds__(256) void out_bf_kernel(
    const float* __restrict__ bo, float* __restrict__ out)
{
    gemm_bf16_body(g_at_h, g_at_l,
                   g_wh + (size_t)4 * (F * NHD), g_wl + (size_t)4 * (F * NHD),
                   bo, out, S, F, NHD);
}

// ---------------------------------------------------------------------------
// ck[h][j] = rw[h].k[j,h,:],  cr[h][m] = rr[h].r[m,h,:]
// ---------------------------------------------------------------------------
__global__ __launch_bounds__(256) void bias_dots_kernel(
    const float* __restrict__ rwb, const float* __restrict__ rrb)
{
    const int gw   = (blockIdx.x * blockDim.x + threadIdx.x) >> 5;
    const int lane = threadIdx.x & 31;
    const int which = gw >= H * S;
    const int idx   = which ? gw - H * S : gw;
    const int hh = idx >> 11;
    const int j  = idx & (S - 1);
    const float* bias = which ? rrb : rwb;
    const float* mat  = which ? g_r : g_k;
    const float b0 = bias[hh * DH + lane];
    const float b1 = bias[hh * DH + 32 + lane];
    const float* row = mat + (size_t)j * NHD + hh * DH;
    float s = fmaf(b0, row[lane], b1 * row[32 + lane]);
#pragma unroll
    for (int off = 16; off > 0; off >>= 1)
        s += __shfl_xor_sync(0xffffffffu, s, off);
    if (lane == 0) {
        float* dst = which ? g_cr : g_ck;
        dst[hh * S + j] = s;
    }
}

// ---------------------------------------------------------------------------
// Causal flash attention, tensor-core tf32 (proven in R4).
// Epilogue now emits bf16 hi/lo split of the output for out_bf_kernel.
// ---------------------------------------------------------------------------
#define KPAD 68
#define VPAD 72
#define GPAD 132
#define SMEM_ATTN ((64*KPAD + 64*VPAD + 127*KPAD + 64*GPAD + 128 + 64) * 4)

__global__ __launch_bounds__(128) void attn_kernel()
{
    const int h   = blockIdx.y;
    const int qi0 = (gridDim.x - 1 - blockIdx.x) * 64;

    extern __shared__ float sm[];
    float* ks    = sm;
    float* vs    = ks + 64 * KPAD;
    float* rsl   = vs + 64 * VPAD;
    float* G     = rsl + 127 * KPAD;
    float* crs_s = G + 64 * GPAD;
    float* cks_s = crs_s + 128;

    const int t    = threadIdx.x;
    const int lane = t & 31;
    const int w    = t >> 5;
    const int g    = lane >> 2;
    const int tg   = lane & 3;
    const int i0   = w * 16 + g;
    const int hb   = h * DH;

    u32 qa[8][4];
    {
        const float* q0 = &g_q[(size_t)(qi0 + i0) * NHD + hb];
        const float* q1 = q0 + 8 * NHD;
#pragma unroll
        for (int k0 = 0; k0 < 8; k0++) {
            qa[k0][0] = f2tf32(q0[k0 * 8 + tg]);
            qa[k0][1] = f2tf32(q1[k0 * 8 + tg]);
            qa[k0][2] = f2tf32(q0[k0 * 8 + tg + 4]);
            qa[k0][3] = f2tf32(q1[k0 * 8 + tg + 4]);
        }
    }

    float O[8][4];
#pragma unroll
    for (int nt = 0; nt < 8; nt++) {
        O[nt][0] = 0.f; O[nt][1] = 0.f; O[nt][2] = 0.f; O[nt][3] = 0.f;
    }
    float m0 = -1e30f, m1 = -1e30f, l0 = 0.f, l1 = 0.f;

    const int nkt = qi0 / 64 + 1;
    for (int kt = 0; kt < nkt; kt++) {
        const int kj0  = kt * 64;
        const int base = (S - 1) + kj0 - qi0 - 63;
        __syncthreads();

        for (int idx = t; idx < 64 * 16; idx += 128) {
            const int r  = idx >> 4;
            const int d4 = (idx & 15) << 2;
            float4 kv = *(const float4*)&g_k[(size_t)(kj0 + r) * NHD + hb + d4];
            float4 vv = *(const float4*)&g_v[(size_t)(kj0 + r) * NHD + hb + d4];
            float* kd = &ks[r * KPAD + d4];
            kd[0] = f2tf32f(kv.x); kd[1] = f2tf32f(kv.y);
            kd[2] = f2tf32f(kv.z); kd[3] = f2tf32f(kv.w);
            float* vd = &vs[r * VPAD + d4];
            vd[0] = f2tf32f(vv.x); vd[1] = f2tf32f(vv.y);
            vd[2] = f2tf32f(vv.z); vd[3] = f2tf32f(vv.w);
        }
        for (int idx = t; idx < 127 * 16; idx += 128) {
            const int mm = idx >> 4;
            const int d4 = (idx & 15) << 2;
            int mg = base + mm;
            if (mg > S - 1) mg = S - 1;
            float4 rv = *(const float4*)&g_r[(size_t)mg * NHD + hb + d4];
            float* rd = &rsl[mm * KPAD + d4];
            rd[0] = f2tf32f(rv.x); rd[1] = f2tf32f(rv.y);
            rd[2] = f2tf32f(rv.z); rd[3] = f2tf32f(rv.w);
        }
        if (t < 64) cks_s[t] = g_ck[h * S + kj0 + t];
        {
            int mg = base + t;
            if (mg > S - 1) mg = S - 1;
            crs_s[t] = (t < 127) ? g_cr[h * S + mg] : 0.f;
        }
        __syncthreads();

#pragma unroll
        for (int half = 0; half < 2; half++) {
            float gc[8][4];
#pragma unroll
            for (int nt = 0; nt < 8; nt++) {
                const int col = half * 64 + nt * 8 + 2 * tg;
                gc[nt][0] = crs_s[col];
                gc[nt][1] = crs_s[col + 1];
                gc[nt][2] = gc[nt][0];
                gc[nt][3] = gc[nt][1];
            }
#pragma unroll
            for (int k0 = 0; k0 < 8; k0++) {
#pragma unroll
                for (int nt = 0; nt < 8; nt++) {
                    const int n0 = half * 64 + nt * 8;
                    u32 b0 = __float_as_uint(rsl[(n0 + g) * KPAD + k0 * 8 + tg]);
                    u32 b1 = __float_as_uint(rsl[(n0 + g) * KPAD + k0 * 8 + tg + 4]);
                    mma_tf32(gc[nt], qa[k0], b0, b1);
                }
            }
#pragma unroll
            for (int nt = 0; nt < 8; nt++) {
                const int col = half * 64 + nt * 8 + 2 * tg;
                *(float2*)&G[i0 * GPAD + col]       = make_float2(gc[nt][0], gc[nt][1]);
                *(float2*)&G[(i0 + 8) * GPAD + col] = make_float2(gc[nt][2], gc[nt][3]);
            }
        }
        __syncwarp();

        float sc[8][4];
#pragma unroll
        for (int nt = 0; nt < 8; nt++) {
            const int col = nt * 8 + 2 * tg;
            sc[nt][0] = cks_s[col];
            sc[nt][1] = cks_s[col + 1];
            sc[nt][2] = sc[nt][0];
            sc[nt][3] = sc[nt][1];
        }
#pragma unroll
        for (int k0 = 0; k0 < 8; k0++) {
#pragma unroll
            for (int nt = 0; nt < 8; nt++) {
                u32 b0 = __float_as_uint(ks[(nt * 8 + g) * KPAD + k0 * 8 + tg]);
                u32 b1 = __float_as_uint(ks[(nt * 8 + g) * KPAD + k0 * 8 + tg + 4]);
                mma_tf32(sc[nt], qa[k0], b0, b1);
            }
        }
        __syncthreads();

        const bool diag = (kt == nkt - 1);
        float rmax0 = -1e30f, rmax1 = -1e30f;
#pragma unroll
        for (int nt = 0; nt < 8; nt++) {
            const int j = nt * 8 + 2 * tg;
            float s00 = (sc[nt][0] + G[i0 * GPAD + 63 + j - i0]) * 0.125f;
            float s01 = (sc[nt][1] + G[i0 * GPAD + 64 + j - i0]) * 0.125f;
            float s10 = (sc[nt][2] + G[(i0 + 8) * GPAD + 55 + j - i0]) * 0.125f;
            float s11 = (sc[nt][3] + G[(i0 + 8) * GPAD + 56 + j - i0]) * 0.125f;
            if (diag) {
                if (kj0 + j     > qi0 + i0)     s00 = -1e30f;
                if (kj0 + j + 1 > qi0 + i0)     s01 = -1e30f;
                if (kj0 + j     > qi0 + i0 + 8) s10 = -1e30f;
                if (kj0 + j + 1 > qi0 + i0 + 8) s11 = -1e30f;
            }
            sc[nt][0] = s00; sc[nt][1] = s01; sc[nt][2] = s10; sc[nt][3] = s11;
            rmax0 = fmaxf(rmax0, fmaxf(s00, s01));
            rmax1 = fmaxf(rmax1, fmaxf(s10, s11));
        }
        rmax0 = fmaxf(rmax0, __shfl_xor_sync(0xffffffffu, rmax0, 1));
        rmax0 = fmaxf(rmax0, __shfl_xor_sync(0xffffffffu, rmax0, 2));
        rmax1 = fmaxf(rmax1, __shfl_xor_sync(0xffffffffu, rmax1, 1));
        rmax1 = fmaxf(rmax1, __shfl_xor_sync(0xffffffffu, rmax1, 2));

        const float newm0 = fmaxf(m0, rmax0);
        const float newm1 = fmaxf(m1, rmax1);
        const float a0 = __expf(m0 - newm0);
        const float a1 = __expf(m1 - newm1);
        m0 = newm0; m1 = newm1;

        float psum0 = 0.f, psum1 = 0.f;
#pragma unroll
        for (int nt = 0; nt < 8; nt++) {
            sc[nt][0] = __expf(sc[nt][0] - m0);
            sc[nt][1] = __expf(sc[nt][1] - m0);
            sc[nt][2] = __expf(sc[nt][2] - m1);
            sc[nt][3] = __expf(sc[nt][3] - m1);
            psum0 += sc[nt][0] + sc[nt][1];
            psum1 += sc[nt][2] + sc[nt][3];
        }
        psum0 += __shfl_xor_sync(0xffffffffu, psum0, 1);
        psum0 += __shfl_xor_sync(0xffffffffu, psum0, 2);
        psum1 += __shfl_xor_sync(0xffffffffu, psum1, 1);
        psum1 += __shfl_xor_sync(0xffffffffu, psum1, 2);
        l0 = l0 * a0 + psum0;
        l1 = l1 * a1 + psum1;
#pragma unroll
        for (int nt = 0; nt < 8; nt++) {
            O[nt][0] *= a0; O[nt][1] *= a0;
            O[nt][2] *= a1; O[nt][3] *= a1;
        }

        float* psb = ks;
#pragma unroll
        for (int nt = 0; nt < 8; nt++) {
            const int j = nt * 8 + 2 * tg;
            *(float2*)&psb[i0 * KPAD + j] =
                make_float2(f2tf32f(sc[nt][0]), f2tf32f(sc[nt][1]));
            *(float2*)&psb[(i0 + 8) * KPAD + j] =
                make_float2(f2tf32f(sc[nt][2]), f2tf32f(sc[nt][3]));
        }
        __syncwarp();

#pragma unroll
        for (int k0 = 0; k0 < 8; k0++) {
            u32 pa[4];
            pa[0] = __float_as_uint(psb[i0 * KPAD + k0 * 8 + tg]);
            pa[1] = __float_as_uint(psb[(i0 + 8) * KPAD + k0 * 8 + tg]);
            pa[2] = __float_as_uint(psb[i0 * KPAD + k0 * 8 + tg + 4]);
            pa[3] = __float_as_uint(psb[(i0 + 8) * KPAD + k0 * 8 + tg + 4]);
#pragma unroll
            for (int nt = 0; nt < 8; nt++) {
                u32 b0 = __float_as_uint(vs[(k0 * 8 + tg) * VPAD + nt * 8 + g]);
                u32 b1 = __float_as_uint(vs[(k0 * 8 + tg + 4) * VPAD + nt * 8 + g]);
                mma_tf32(O[nt], pa, b0, b1);
            }
        }
    }

    // ---- epilogue: normalize + bf16 hi/lo split for the output GEMM ----
    const float inv0 = 1.f / l0;
    const float inv1 = 1.f / l1;
#pragma unroll
    for (int nt = 0; nt < 8; nt++) {
        const int col = nt * 8 + 2 * tg;
        const size_t idx0 = (size_t)(qi0 + i0) * NHD + hb + col;
        const size_t idx1 = (size_t)(qi0 + i0 + 8) * NHD + hb + col;
        float o00 = O[nt][0] * inv0, o01 = O[nt][1] * inv0;
        float o10 = O[nt][2] * inv1, o11 = O[nt][3] * inv1;
        __nv_bfloat162 h0 = __floats2bfloat162_rn(o00, o01);
        __nv_bfloat162 h1 = __floats2bfloat162_rn(o10, o11);
        __nv_bfloat162 L0 = __floats2bfloat162_rn(o00 - __bfloat162float(h0.x),
                                                  o01 - __bfloat162float(h0.y));
        __nv_bfloat162 L1 = __floats2bfloat162_rn(o10 - __bfloat162float(h1.x),
                                                  o11 - __bfloat162float(h1.y));
        *(__nv_bfloat162*)&g_at_h[idx0] = h0;
        *(__nv_bfloat162*)&g_at_l[idx0] = L0;
        *(__nv_bfloat162*)&g_at_h[idx1] = h1;
        *(__nv_bfloat162*)&g_at_l[idx1] = L1;
    }
}

// ---------------------------------------------------------------------------
extern "C" void kernel_launch(void* const* d_in, const int* in_sizes, int n_in,
                              void* d_out, int out_size)
{
    const float* inputs_q = (const float*)d_in[0];
    const float* pos_emb  = (const float*)d_in[1];
    const float* r_w_bias = (const float*)d_in[2];
    const float* r_r_bias = (const float*)d_in[3];
    const float* Wq = (const float*)d_in[4];
    const float* bq = (const float*)d_in[5];
    const float* Wk = (const float*)d_in[6];
    const float* bk = (const float*)d_in[7];
    const float* Wv = (const float*)d_in[8];
    const float* bv = (const float*)d_in[9];
    const float* Wr = (const float*)d_in[10];
    const float* br = (const float*)d_in[11];
    const float* Wo = (const float*)d_in[12];
    const float* bo = (const float*)d_in[13];
    float* out = (float*)d_out;

    cudaFuncSetAttribute(attn_kernel,
                         cudaFuncAttributeMaxDynamicSharedMemorySize, SMEM_ATTN);
    cudaFuncSetAttribute(proj_bf_kernel,
                         cudaFuncAttributeMaxDynamicSharedMemorySize, GEMM_SMEM_BYTES);
    cudaFuncSetAttribute(out_bf_kernel,
                         cudaFuncAttributeMaxDynamicSharedMemorySize, GEMM_SMEM_BYTES);

    // 1) split all GEMM operands to bf16 hi/lo (one launch)
    split_kernel<<<(2 * 524288 + 5 * 262144) / 256, 256>>>(
        inputs_q, pos_emb, Wq, Wk, Wv, Wr, Wo);

    // 2) q/k/v/r projections on tensor cores
    proj_bf_kernel<<<dim3(NHD / 128, S / 128, 4), 256, GEMM_SMEM_BYTES>>>(
        bq, bk, bv, br);

    // 3) per-(head,row) bias dot products
    bias_dots_kernel<<<(2 * H * S * 32) / 256, 256>>>(r_w_bias, r_r_bias);

    // 4) fused causal attention (tf32 tensor cores)
    attn_kernel<<<dim3(S / 64, H), 128, SMEM_ATTN>>>();

    // 5) output projection on tensor cores
    out_bf_kernel<<<dim3(F / 128, S / 128), 256, GEMM_SMEM_BYTES>>>(bo, out);
}

// round 6
// speedup vs baseline: 4.9483x; 1.0020x over previous
#include <cuda_runtime.h>
#include <cuda_bf16.h>

#define S 2048
#define F 1024
#define H 16
#define DH 64
#define NHD 1024  // H*DH

typedef unsigned long long u64;
typedef unsigned int u32;

// ---- tf32 helpers (attention) ----
__device__ __forceinline__ u32 f2tf32(float x) {
    u32 r;
    asm("cvt.rna.tf32.f32 %0, %1;" : "=r"(r) : "f"(x));
    return r;
}
__device__ __forceinline__ float f2tf32f(float x) {
    return __uint_as_float(f2tf32(x));
}
__device__ __forceinline__ void mma_tf32(float c[4], const u32 a[4], u32 b0, u32 b1) {
    asm volatile(
        "mma.sync.aligned.m16n8k8.row.col.f32.tf32.tf32.f32 "
        "{%0,%1,%2,%3}, {%4,%5,%6,%7}, {%8,%9}, {%0,%1,%2,%3};\n"
        : "+f"(c[0]), "+f"(c[1]), "+f"(c[2]), "+f"(c[3])
        : "r"(a[0]), "r"(a[1]), "r"(a[2]), "r"(a[3]), "r"(b0), "r"(b1));
}

// ---- bf16 helpers (GEMMs) ----
__device__ __forceinline__ void mma_bf16(float c[4], const u32 a[4], u32 b0, u32 b1) {
    asm volatile(
        "mma.sync.aligned.m16n8k16.row.col.f32.bf16.bf16.f32 "
        "{%0,%1,%2,%3}, {%4,%5,%6,%7}, {%8,%9}, {%0,%1,%2,%3};\n"
        : "+f"(c[0]), "+f"(c[1]), "+f"(c[2]), "+f"(c[3])
        : "r"(a[0]), "r"(a[1]), "r"(a[2]), "r"(a[3]), "r"(b0), "r"(b1));
}
__device__ __forceinline__ void ldm2t(u32& d0, u32& d1, u32 saddr) {
    asm volatile("ldmatrix.sync.aligned.m8n8.x2.trans.shared.b16 {%0,%1}, [%2];"
                 : "=r"(d0), "=r"(d1) : "r"(saddr));
}
__device__ __forceinline__ u32 sptr(const void* p) {
    return (u32)__cvta_generic_to_shared(p);
}

// Scratch (device globals: allocation-free per harness rules)
__device__ float g_q[S * NHD];
__device__ float g_k[S * NHD];
__device__ float g_v[S * NHD];
__device__ float g_r[S * NHD];
__device__ float g_ck[H * S];
__device__ float g_cr[H * S];
// bf16 hi/lo split panels
__device__ __nv_bfloat16 g_xq_h[S * F],   g_xq_l[S * F];
__device__ __nv_bfloat16 g_xr_h[S * F],   g_xr_l[S * F];
__device__ __nv_bfloat16 g_wh[5 * F * NHD], g_wl[5 * F * NHD];  // Wq,Wk,Wv,Wr,Wo
__device__ __nv_bfloat16 g_at_h[S * NHD], g_at_l[S * NHD];

// ---------------------------------------------------------------------------
// Split fp32 -> (bf16 hi, bf16 lo) for all GEMM operands in ONE launch.
// ---------------------------------------------------------------------------
__global__ __launch_bounds__(256) void split_kernel(
    const float* __restrict__ xq, const float* __restrict__ xr,
    const float* __restrict__ w0, const float* __restrict__ w1,
    const float* __restrict__ w2, const float* __restrict__ w3,
    const float* __restrict__ w4)
{
    const int i = blockIdx.x * 256 + threadIdx.x;
    const float* src;
    __nv_bfloat16 *h, *l;
    int off;
    if (i < 524288)        { src = xq; h = g_xq_h; l = g_xq_l; off = i; }
    else if (i < 1048576)  { src = xr; h = g_xr_h; l = g_xr_l; off = i - 524288; }
    else {
        const int j = i - 1048576;
        const int w = j >> 18;
        off = j & 262143;
        const float* ws[5] = {w0, w1, w2, w3, w4};
        src = ws[w];
        h = g_wh + (size_t)w * (F * NHD);
        l = g_wl + (size_t)w * (F * NHD);
    }
    float4 v = ((const float4*)src)[off];
    __nv_bfloat162 h0 = __floats2bfloat162_rn(v.x, v.y);
    __nv_bfloat162 h1 = __floats2bfloat162_rn(v.z, v.w);
    __nv_bfloat162 l0 = __floats2bfloat162_rn(v.x - __bfloat162float(h0.x),
                                              v.y - __bfloat162float(h0.y));
    __nv_bfloat162 l1 = __floats2bfloat162_rn(v.z - __bfloat162float(h1.x),
                                              v.w - __bfloat162float(h1.y));
    ((__nv_bfloat162*)h)[off * 2]     = h0;
    ((__nv_bfloat162*)h)[off * 2 + 1] = h1;
    ((__nv_bfloat162*)l)[off * 2]     = l0;
    ((__nv_bfloat162*)l)[off * 2 + 1] = l1;
}

// ---------------------------------------------------------------------------
// bf16 split-GEMM (unchanged from R5 — known good)
// ---------------------------------------------------------------------------
#define GEMM_SMEM_BYTES 75776

__device__ __forceinline__ void gemm_bf16_body(
    const __nv_bfloat16* __restrict__ Ah, const __nv_bfloat16* __restrict__ Al,
    const __nv_bfloat16* __restrict__ Bh, const __nv_bfloat16* __restrict__ Bl,
    const float* __restrict__ bias, float* __restrict__ C,
    int M, int N, int K)
{
    extern __shared__ __nv_bfloat16 sb[];
    __nv_bfloat16* As_h = sb;
    __nv_bfloat16* As_l = sb + 10240;
    __nv_bfloat16* Bs_h = sb + 20480;
    __nv_bfloat16* Bs_l = sb + 29184;

    const int t    = threadIdx.x;
    const int lane = t & 31;
    const int w    = t >> 5;
    const int wm   = (w & 3) * 32;
    const int wn   = (w >> 2) * 64;
    const int g    = lane >> 2;
    const int tg   = lane & 3;
    const int m0   = blockIdx.y * 128;
    const int n0   = blockIdx.x * 128;

    float Cr[2][8][4];
#pragma unroll
    for (int mt = 0; mt < 2; mt++)
#pragma unroll
        for (int nt = 0; nt < 8; nt++) {
            Cr[mt][nt][0] = 0.f; Cr[mt][nt][1] = 0.f;
            Cr[mt][nt][2] = 0.f; Cr[mt][nt][3] = 0.f;
        }

    const int fm = t >> 1, fh = (t & 1) * 16;
    const int fk = t >> 3, fv = (t & 7) * 16;

    const __nv_bfloat16* gAh = Ah + (size_t)(m0 + fm) * K + fh;
    const __nv_bfloat16* gAl = Al + (size_t)(m0 + fm) * K + fh;
    const __nv_bfloat16* gBh = Bh + (size_t)fk * N + n0 + fv;
    const __nv_bfloat16* gBl = Bl + (size_t)fk * N + n0 + fv;

    {
        uint4 r0 = *(const uint4*)gAh;
        uint4 r1 = *(const uint4*)(gAh + 8);
        uint4 r2 = *(const uint4*)gAl;
        uint4 r3 = *(const uint4*)(gAl + 8);
        uint4 r4 = *(const uint4*)gBh;
        uint4 r5 = *(const uint4*)(gBh + 8);
        uint4 r6 = *(const uint4*)gBl;
        uint4 r7 = *(const uint4*)(gBl + 8);
        __nv_bfloat16* sa = As_h + fm * 40 + fh;
        *(uint4*)sa = r0; *(uint4*)(sa + 8) = r1;
        sa = As_l + fm * 40 + fh;
        *(uint4*)sa = r2; *(uint4*)(sa + 8) = r3;
        __nv_bfloat16* sbp = Bs_h + fk * 136 + fv;
        *(uint4*)sbp = r4; *(uint4*)(sbp + 8) = r5;
        sbp = Bs_l + fk * 136 + fv;
        *(uint4*)sbp = r6; *(uint4*)(sbp + 8) = r7;
    }
    __syncthreads();

    int buf = 0;
    const int nkc = K / 32;
    for (int kc = 0; kc < nkc; kc++) {
        uint4 ra[8];
        const bool has = (kc + 1) < nkc;
        if (has) {
            const __nv_bfloat16* pAh = gAh + (kc + 1) * 32;
            const __nv_bfloat16* pAl = gAl + (kc + 1) * 32;
            const __nv_bfloat16* pBh = gBh + (size_t)(kc + 1) * 32 * N;
            const __nv_bfloat16* pBl = gBl + (size_t)(kc + 1) * 32 * N;
            ra[0] = *(const uint4*)pAh; ra[1] = *(const uint4*)(pAh + 8);
            ra[2] = *(const uint4*)pAl; ra[3] = *(const uint4*)(pAl + 8);
            ra[4] = *(const uint4*)pBh; ra[5] = *(const uint4*)(pBh + 8);
            ra[6] = *(const uint4*)pBl; ra[7] = *(const uint4*)(pBl + 8);
        }
        const __nv_bfloat16* Ab_h = As_h + buf * 5120;
        const __nv_bfloat16* Ab_l = As_l + buf * 5120;
        const __nv_bfloat16* Bb_h = Bs_h + buf * 4352;
        const __nv_bfloat16* Bb_l = Bs_l + buf * 4352;

#pragma unroll
        for (int ks2 = 0; ks2 < 2; ks2++) {
            const int ks = ks2 * 16;
            u32 ah[2][4], al[2][4];
#pragma unroll
            for (int mt = 0; mt < 2; mt++) {
                const __nv_bfloat16* r0 = Ab_h + (wm + mt * 16 + g) * 40 + ks + 2 * tg;
                ah[mt][0] = *(const u32*)r0;
                ah[mt][1] = *(const u32*)(r0 + 8 * 40);
                ah[mt][2] = *(const u32*)(r0 + 8);
                ah[mt][3] = *(const u32*)(r0 + 8 * 40 + 8);
                const __nv_bfloat16* r1 = Ab_l + (wm + mt * 16 + g) * 40 + ks + 2 * tg;
                al[mt][0] = *(const u32*)r1;
                al[mt][1] = *(const u32*)(r1 + 8 * 40);
                al[mt][2] = *(const u32*)(r1 + 8);
                al[mt][3] = *(const u32*)(r1 + 8 * 40 + 8);
            }
            const u32 bbh = sptr(Bb_h + (ks + (lane & 15)) * 136 + wn);
            const u32 bbl = sptr(Bb_l + (ks + (lane & 15)) * 136 + wn);
#pragma unroll
            for (int nt = 0; nt < 8; nt++) {
                u32 bh0, bh1, bl0, bl1;
                ldm2t(bh0, bh1, bbh + nt * 16);
                ldm2t(bl0, bl1, bbl + nt * 16);
#pragma unroll
                for (int mt = 0; mt < 2; mt++) {
                    mma_bf16(Cr[mt][nt], ah[mt], bh0, bh1);
                    mma_bf16(Cr[mt][nt], ah[mt], bl0, bl1);
                    mma_bf16(Cr[mt][nt], al[mt], bh0, bh1);
                }
            }
        }

        if (has) {
            __nv_bfloat16* sa = As_h + (buf ^ 1) * 5120 + fm * 40 + fh;
            *(uint4*)sa = ra[0]; *(uint4*)(sa + 8) = ra[1];
            sa = As_l + (buf ^ 1) * 5120 + fm * 40 + fh;
            *(uint4*)sa = ra[2]; *(uint4*)(sa + 8) = ra[3];
            __nv_bfloat16* sbp = Bs_h + (buf ^ 1) * 4352 + fk * 136 + fv;
            *(uint4*)sbp = ra[4]; *(uint4*)(sbp + 8) = ra[5];
            sbp = Bs_l + (buf ^ 1) * 4352 + fk * 136 + fv;
            *(uint4*)sbp = ra[6]; *(uint4*)(sbp + 8) = ra[7];
            __syncthreads();
            buf ^= 1;
        }
    }

#pragma unroll
    for (int mt = 0; mt < 2; mt++) {
        const int row = m0 + wm + mt * 16 + g;
#pragma unroll
        for (int nt = 0; nt < 8; nt++) {
            const int col = n0 + wn + nt * 8 + 2 * tg;
            float2 b01 = *(const float2*)&bias[col];
            float2 o;
            o.x = Cr[mt][nt][0] + b01.x;
            o.y = Cr[mt][nt][1] + b01.y;
            *(float2*)(C + (size_t)row * N + col) = o;
            o.x = Cr[mt][nt][2] + b01.x;
            o.y = Cr[mt][nt][3] + b01.y;
            *(float2*)(C + (size_t)(row + 8) * N + col) = o;
        }
    }
}

__global__ __launch_bounds__(256) void proj_bf_kernel(
    const float* __restrict__ bq, const float* __restrict__ bk,
    const float* __restrict__ bv, const float* __restrict__ br)
{
    const int z = blockIdx.z;
    const __nv_bfloat16* Ah = (z < 3) ? g_xq_h : g_xr_h;
    const __nv_bfloat16* Al = (z < 3) ? g_xq_l : g_xr_l;
    const __nv_bfloat16* Bh = g_wh + (size_t)z * (F * NHD);
    const __nv_bfloat16* Bl = g_wl + (size_t)z * (F * NHD);
    const float* bias;
    float* C;
    switch (z) {
        case 0:  bias = bq; C = g_q; break;
        case 1:  bias = bk; C = g_k; break;
        case 2:  bias = bv; C = g_v; break;
        default: bias = br; C = g_r; break;
    }
    gemm_bf16_body(Ah, Al, Bh, Bl, bias, C, S, NHD, F);
}

__global__ __launch_bounds__(256) void out_bf_kernel(
    const float* __restrict__ bo, float* __restrict__ out)
{
    gemm_bf16_body(g_at_h, g_at_l,
                   g_wh + (size_t)4 * (F * NHD), g_wl + (size_t)4 * (F * NHD),
                   bo, out, S, F, NHD);
}

// ---------------------------------------------------------------------------
// ck[h][j] = rw[h].k[j,h,:],  cr[h][m] = rr[h].r[m,h,:]
// ---------------------------------------------------------------------------
__global__ __launch_bounds__(256) void bias_dots_kernel(
    const float* __restrict__ rwb, const float* __restrict__ rrb)
{
    const int gw   = (blockIdx.x * blockDim.x + threadIdx.x) >> 5;
    const int lane = threadIdx.x & 31;
    const int which = gw >= H * S;
    const int idx   = which ? gw - H * S : gw;
    const int hh = idx >> 11;
    const int j  = idx & (S - 1);
    const float* bias = which ? rrb : rwb;
    const float* mat  = which ? g_r : g_k;
    const float b0 = bias[hh * DH + lane];
    const float b1 = bias[hh * DH + 32 + lane];
    const float* row = mat + (size_t)j * NHD + hh * DH;
    float s = fmaf(b0, row[lane], b1 * row[32 + lane]);
#pragma unroll
    for (int off = 16; off > 0; off >>= 1)
        s += __shfl_xor_sync(0xffffffffu, s, off);
    if (lane == 0) {
        float* dst = which ? g_cr : g_ck;
        dst[hh * S + j] = s;
    }
}

// ---------------------------------------------------------------------------
// Causal flash attention, tf32 tensor cores.
// R6: paired-d permuted K/RSL layout (b-frag = one LDS.64) + windowed G
// (each warp computes only the 10 n-tiles its rows gather).
// perm(d) = (d & ~7) + 2*(d & 3) + ((d >> 2) & 1): pos 8m+2t  <- d=8m+t
//                                                  pos 8m+2t+1<- d=8m+t+4
// ---------------------------------------------------------------------------
#define KPAD 72
#define VPAD 72
#define GPAD 132
#define SMEM_ATTN ((64*KPAD + 64*VPAD + 128*KPAD + 64*GPAD + 128 + 64) * 4)

__global__ __launch_bounds__(128) void attn_kernel()
{
    const int h   = blockIdx.y;
    const int qi0 = (gridDim.x - 1 - blockIdx.x) * 64;

    extern __shared__ float sm[];
    float* ks    = sm;                 // 64 x KPAD (perm d); reused as P tile
    float* vs    = ks + 64 * KPAD;     // 64 x VPAD (natural)
    float* rsl   = vs + 64 * VPAD;     // 128 x KPAD (perm d)
    float* G     = rsl + 128 * KPAD;   // 64 x GPAD (fp32)
    float* crs_s = G + 64 * GPAD;      // 128
    float* cks_s = crs_s + 128;        // 64

    const int t    = threadIdx.x;
    const int lane = t & 31;
    const int w    = t >> 5;
    const int g    = lane >> 2;
    const int tg   = lane & 3;
    const int i0   = w * 16 + g;
    const int hb   = h * DH;
    const int tile0 = 6 - 2 * w;       // first G n-tile this warp needs

    u32 qa[8][4];
    {
        const float* q0 = &g_q[(size_t)(qi0 + i0) * NHD + hb];
        const float* q1 = q0 + 8 * NHD;
#pragma unroll
        for (int k0 = 0; k0 < 8; k0++) {
            qa[k0][0] = f2tf32(q0[k0 * 8 + tg]);
            qa[k0][1] = f2tf32(q1[k0 * 8 + tg]);
            qa[k0][2] = f2tf32(q0[k0 * 8 + tg + 4]);
            qa[k0][3] = f2tf32(q1[k0 * 8 + tg + 4]);
        }
    }

    float O[8][4];
#pragma unroll
    for (int nt = 0; nt < 8; nt++) {
        O[nt][0] = 0.f; O[nt][1] = 0.f; O[nt][2] = 0.f; O[nt][3] = 0.f;
    }
    float m0 = -1e30f, m1 = -1e30f, l0 = 0.f, l1 = 0.f;

    const int nkt = qi0 / 64 + 1;
    for (int kt = 0; kt < nkt; kt++) {
        const int kj0  = kt * 64;
        const int base = (S - 1) + kj0 - qi0 - 63;
        __syncthreads();

        // K (perm) + V (natural) fills
        for (int idx = t; idx < 64 * 16; idx += 128) {
            const int r  = idx >> 4;
            const int d4 = (idx & 15) << 2;
            float4 kv = *(const float4*)&g_k[(size_t)(kj0 + r) * NHD + hb + d4];
            float4 vv = *(const float4*)&g_v[(size_t)(kj0 + r) * NHD + hb + d4];
            float* kd = &ks[r * KPAD + (d4 & ~7) + ((d4 & 4) ? 1 : 0)];
            kd[0] = f2tf32f(kv.x); kd[2] = f2tf32f(kv.y);
            kd[4] = f2tf32f(kv.z); kd[6] = f2tf32f(kv.w);
            float* vd = &vs[r * VPAD + d4];
            vd[0] = f2tf32f(vv.x); vd[1] = f2tf32f(vv.y);
            vd[2] = f2tf32f(vv.z); vd[3] = f2tf32f(vv.w);
        }
        // RSL (perm), 128 rows (row 127 clamped; never gathered)
        for (int idx = t; idx < 128 * 16; idx += 128) {
            const int mm = idx >> 4;
            const int d4 = (idx & 15) << 2;
            int mg = base + mm;
            if (mg > S - 1) mg = S - 1;
            float4 rv = *(const float4*)&g_r[(size_t)mg * NHD + hb + d4];
            float* rd = &rsl[mm * KPAD + (d4 & ~7) + ((d4 & 4) ? 1 : 0)];
            rd[0] = f2tf32f(rv.x); rd[2] = f2tf32f(rv.y);
            rd[4] = f2tf32f(rv.z); rd[6] = f2tf32f(rv.w);
        }
        if (t < 64) cks_s[t] = g_ck[h * S + kj0 + t];
        {
            int mg = base + t;
            if (mg > S - 1) mg = S - 1;
            crs_s[t] = (t < 127) ? g_cr[h * S + mg] : 0.f;
        }
        __syncthreads();

        // ---- windowed G = Q @ RSL^T (+cr): tiles tile0 .. tile0+9 ----
        {
            float gc[10][4];
#pragma unroll
            for (int ni = 0; ni < 10; ni++) {
                const int col = (tile0 + ni) * 8 + 2 * tg;
                gc[ni][0] = crs_s[col];
                gc[ni][1] = crs_s[col + 1];
                gc[ni][2] = gc[ni][0];
                gc[ni][3] = gc[ni][1];
            }
#pragma unroll
            for (int k0 = 0; k0 < 8; k0++) {
#pragma unroll
                for (int ni = 0; ni < 10; ni++) {
                    const int row = (tile0 + ni) * 8 + g;
                    uint2 bb = *(const uint2*)&rsl[row * KPAD + k0 * 8 + 2 * tg];
                    mma_tf32(gc[ni], qa[k0], bb.x, bb.y);
                }
            }
#pragma unroll
            for (int ni = 0; ni < 10; ni++) {
                const int col = (tile0 + ni) * 8 + 2 * tg;
                *(float2*)&G[i0 * GPAD + col]       = make_float2(gc[ni][0], gc[ni][1]);
                *(float2*)&G[(i0 + 8) * GPAD + col] = make_float2(gc[ni][2], gc[ni][3]);
            }
        }
        __syncwarp();  // G rows are warp-private

        // ---- AC = Q @ K^T (+ck) ----
        float sc[8][4];
#pragma unroll
        for (int nt = 0; nt < 8; nt++) {
            const int col = nt * 8 + 2 * tg;
            sc[nt][0] = cks_s[col];
            sc[nt][1] = cks_s[col + 1];
            sc[nt][2] = sc[nt][0];
            sc[nt][3] = sc[nt][1];
        }
#pragma unroll
        for (int k0 = 0; k0 < 8; k0++) {
#pragma unroll
            for (int nt = 0; nt < 8; nt++) {
                uint2 bb = *(const uint2*)&ks[(nt * 8 + g) * KPAD + k0 * 8 + 2 * tg];
                mma_tf32(sc[nt], qa[k0], bb.x, bb.y);
            }
        }
        __syncthreads();  // all warps done reading ks before P overwrites it

        // ---- BD gather + online softmax ----
        const bool diag = (kt == nkt - 1);
        float rmax0 = -1e30f, rmax1 = -1e30f;
#pragma unroll
        for (int nt = 0; nt < 8; nt++) {
            const int j = nt * 8 + 2 * tg;
            float s00 = (sc[nt][0] + G[i0 * GPAD + 63 + j - i0]) * 0.125f;
            float s01 = (sc[nt][1] + G[i0 * GPAD + 64 + j - i0]) * 0.125f;
            float s10 = (sc[nt][2] + G[(i0 + 8) * GPAD + 55 + j - i0]) * 0.125f;
            float s11 = (sc[nt][3] + G[(i0 + 8) * GPAD + 56 + j - i0]) * 0.125f;
            if (diag) {
                if (kj0 + j     > qi0 + i0)     s00 = -1e30f;
                if (kj0 + j + 1 > qi0 + i0)     s01 = -1e30f;
                if (kj0 + j     > qi0 + i0 + 8) s10 = -1e30f;
                if (kj0 + j + 1 > qi0 + i0 + 8) s11 = -1e30f;
            }
            sc[nt][0] = s00; sc[nt][1] = s01; sc[nt][2] = s10; sc[nt][3] = s11;
            rmax0 = fmaxf(rmax0, fmaxf(s00, s01));
            rmax1 = fmaxf(rmax1, fmaxf(s10, s11));
        }
        rmax0 = fmaxf(rmax0, __shfl_xor_sync(0xffffffffu, rmax0, 1));
        rmax0 = fmaxf(rmax0, __shfl_xor_sync(0xffffffffu, rmax0, 2));
        rmax1 = fmaxf(rmax1, __shfl_xor_sync(0xffffffffu, rmax1, 1));
        rmax1 = fmaxf(rmax1, __shfl_xor_sync(0xffffffffu, rmax1, 2));

        const float newm0 = fmaxf(m0, rmax0);
        const float newm1 = fmaxf(m1, rmax1);
        const float a0 = __expf(m0 - newm0);
        const float a1 = __expf(m1 - newm1);
        m0 = newm0; m1 = newm1;

        float psum0 = 0.f, psum1 = 0.f;
#pragma unroll
        for (int nt = 0; nt < 8; nt++) {
            sc[nt][0] = __expf(sc[nt][0] - m0);
            sc[nt][1] = __expf(sc[nt][1] - m0);
            sc[nt][2] = __expf(sc[nt][2] - m1);
            sc[nt][3] = __expf(sc[nt][3] - m1);
            psum0 += sc[nt][0] + sc[nt][1];
            psum1 += sc[nt][2] + sc[nt][3];
        }
        psum0 += __shfl_xor_sync(0xffffffffu, psum0, 1);
        psum0 += __shfl_xor_sync(0xffffffffu, psum0, 2);
        psum1 += __shfl_xor_sync(0xffffffffu, psum1, 1);
        psum1 += __shfl_xor_sync(0xffffffffu, psum1, 2);
        l0 = l0 * a0 + psum0;
        l1 = l1 * a1 + psum1;
#pragma unroll
        for (int nt = 0; nt < 8; nt++) {
            O[nt][0] *= a0; O[nt][1] *= a0;
            O[nt][2] *= a1; O[nt][3] *= a1;
        }

        // ---- store P (tf32, natural cols) into ks buffer ----
        float* psb = ks;
#pragma unroll
        for (int nt = 0; nt < 8; nt++) {
            const int j = nt * 8 + 2 * tg;
            *(float2*)&psb[i0 * KPAD + j] =
                make_float2(f2tf32f(sc[nt][0]), f2tf32f(sc[nt][1]));
            *(float2*)&psb[(i0 + 8) * KPAD + j] =
                make_float2(f2tf32f(sc[nt][2]), f2tf32f(sc[nt][3]));
        }
        __syncwarp();  // P rows are warp-private

        // ---- PV: O += P @ V ----
#pragma unroll
        for (int k0 = 0; k0 < 8; k0++) {
            u32 pa[4];
            pa[0] = __float_as_uint(psb[i0 * KPAD + k0 * 8 + tg]);
            pa[1] = __float_as_uint(psb[(i0 + 8) * KPAD + k0 * 8 + tg]);
            pa[2] = __float_as_uint(psb[i0 * KPAD + k0 * 8 + tg + 4]);
            pa[3] = __float_as_uint(psb[(i0 + 8) * KPAD + k0 * 8 + tg + 4]);
#pragma unroll
            for (int nt = 0; nt < 8; nt++) {
                u32 b0 = __float_as_uint(vs[(k0 * 8 + tg) * VPAD + nt * 8 + g]);
                u32 b1 = __float_as_uint(vs[(k0 * 8 + tg + 4) * VPAD + nt * 8 + g]);
                mma_tf32(O[nt], pa, b0, b1);
            }
        }
    }

    // ---- epilogue: normalize + bf16 hi/lo split for the output GEMM ----
    const float inv0 = 1.f / l0;
    const float inv1 = 1.f / l1;
#pragma unroll
    for (int nt = 0; nt < 8; nt++) {
        const int col = nt * 8 + 2 * tg;
        const size_t idx0 = (size_t)(qi0 + i0) * NHD + hb + col;
        const size_t idx1 = (size_t)(qi0 + i0 + 8) * NHD + hb + col;
        float o00 = O[nt][0] * inv0, o01 = O[nt][1] * inv0;
        float o10 = O[nt][2] * inv1, o11 = O[nt][3] * inv1;
        __nv_bfloat162 h0 = __floats2bfloat162_rn(o00, o01);
        __nv_bfloat162 h1 = __floats2bfloat162_rn(o10, o11);
        __nv_bfloat162 L0 = __floats2bfloat162_rn(o00 - __bfloat162float(h0.x),
                                                  o01 - __bfloat162float(h0.y));
        __nv_bfloat162 L1 = __floats2bfloat162_rn(o10 - __bfloat162float(h1.x),
                                                  o11 - __bfloat162float(h1.y));
        *(__nv_bfloat162*)&g_at_h[idx0] = h0;
        *(__nv_bfloat162*)&g_at_l[idx0] = L0;
        *(__nv_bfloat162*)&g_at_h[idx1] = h1;
        *(__nv_bfloat162*)&g_at_l[idx1] = L1;
    }
}

// ---------------------------------------------------------------------------
extern "C" void kernel_launch(void* const* d_in, const int* in_sizes, int n_in,
                              void* d_out, int out_size)
{
    const float* inputs_q = (const float*)d_in[0];
    const float* pos_emb  = (const float*)d_in[1];
    const float* r_w_bias = (const float*)d_in[2];
    const float* r_r_bias = (const float*)d_in[3];
    const float* Wq = (const float*)d_in[4];
    const float* bq = (const float*)d_in[5];
    const float* Wk = (const float*)d_in[6];
    const float* bk = (const float*)d_in[7];
    const float* Wv = (const float*)d_in[8];
    const float* bv = (const float*)d_in[9];
    const float* Wr = (const float*)d_in[10];
    const float* br = (const float*)d_in[11];
    const float* Wo = (const float*)d_in[12];
    const float* bo = (const float*)d_in[13];
    float* out = (float*)d_out;

    cudaFuncSetAttribute(attn_kernel,
                         cudaFuncAttributeMaxDynamicSharedMemorySize, SMEM_ATTN);
    cudaFuncSetAttribute(proj_bf_kernel,
                         cudaFuncAttributeMaxDynamicSharedMemorySize, GEMM_SMEM_BYTES);
    cudaFuncSetAttribute(out_bf_kernel,
                         cudaFuncAttributeMaxDynamicSharedMemorySize, GEMM_SMEM_BYTES);

    split_kernel<<<(2 * 524288 + 5 * 262144) / 256, 256>>>(
        inputs_q, pos_emb, Wq, Wk, Wv, Wr, Wo);

    proj_bf_kernel<<<dim3(NHD / 128, S / 128, 4), 256, GEMM_SMEM_BYTES>>>(
        bq, bk, bv, br);

    bias_dots_kernel<<<(2 * H * S * 32) / 256, 256>>>(r_w_bias, r_r_bias);

    attn_kernel<<<dim3(S / 64, H), 128, SMEM_ATTN>>>();

    out_bf_kernel<<<dim3(F / 128, S / 128), 256, GEMM_SMEM_BYTES>>>(bo, out);
}

// round 7
// speedup vs baseline: 5.2889x; 1.0688x over previous
#include <cuda_runtime.h>
#include <cuda_bf16.h>

#define S 2048
#define F 1024
#define H 16
#define DH 64
#define NHD 1024  // H*DH

typedef unsigned long long u64;
typedef unsigned int u32;

// ---- tf32 helpers (attention) ----
__device__ __forceinline__ u32 f2tf32(float x) {
    u32 r;
    asm("cvt.rna.tf32.f32 %0, %1;" : "=r"(r) : "f"(x));
    return r;
}
__device__ __forceinline__ float f2tf32f(float x) {
    return __uint_as_float(f2tf32(x));
}
__device__ __forceinline__ void mma_tf32(float c[4], const u32 a[4], u32 b0, u32 b1) {
    asm volatile(
        "mma.sync.aligned.m16n8k8.row.col.f32.tf32.tf32.f32 "
        "{%0,%1,%2,%3}, {%4,%5,%6,%7}, {%8,%9}, {%0,%1,%2,%3};\n"
        : "+f"(c[0]), "+f"(c[1]), "+f"(c[2]), "+f"(c[3])
        : "r"(a[0]), "r"(a[1]), "r"(a[2]), "r"(a[3]), "r"(b0), "r"(b1));
}

// ---- bf16 helpers (GEMMs) ----
__device__ __forceinline__ void mma_bf16(float c[4], const u32 a[4], u32 b0, u32 b1) {
    asm volatile(
        "mma.sync.aligned.m16n8k16.row.col.f32.bf16.bf16.f32 "
        "{%0,%1,%2,%3}, {%4,%5,%6,%7}, {%8,%9}, {%0,%1,%2,%3};\n"
        : "+f"(c[0]), "+f"(c[1]), "+f"(c[2]), "+f"(c[3])
        : "r"(a[0]), "r"(a[1]), "r"(a[2]), "r"(a[3]), "r"(b0), "r"(b1));
}
__device__ __forceinline__ void ldm2t(u32& d0, u32& d1, u32 saddr) {
    asm volatile("ldmatrix.sync.aligned.m8n8.x2.trans.shared.b16 {%0,%1}, [%2];"
                 : "=r"(d0), "=r"(d1) : "r"(saddr));
}
__device__ __forceinline__ u32 sptr(const void* p) {
    return (u32)__cvta_generic_to_shared(p);
}

// Scratch (device globals: allocation-free per harness rules)
__device__ float g_q[S * NHD];
__device__ float g_k[S * NHD];
__device__ float g_v[S * NHD];
__device__ float g_r[S * NHD];
__device__ float g_ck[H * S];
__device__ float g_cr[H * S];
// bf16 hi/lo split panels
__device__ __nv_bfloat16 g_xq_h[S * F],   g_xq_l[S * F];
__device__ __nv_bfloat16 g_xr_h[S * F],   g_xr_l[S * F];
__device__ __nv_bfloat16 g_wh[5 * F * NHD], g_wl[5 * F * NHD];  // Wq,Wk,Wv,Wr,Wo
__device__ __nv_bfloat16 g_at_h[S * NHD], g_at_l[S * NHD];

// ---------------------------------------------------------------------------
// Split fp32 -> (bf16 hi, bf16 lo) for all GEMM operands in ONE launch.
// ---------------------------------------------------------------------------
__global__ __launch_bounds__(256) void split_kernel(
    const float* __restrict__ xq, const float* __restrict__ xr,
    const float* __restrict__ w0, const float* __restrict__ w1,
    const float* __restrict__ w2, const float* __restrict__ w3,
    const float* __restrict__ w4)
{
    const int i = blockIdx.x * 256 + threadIdx.x;
    const float* src;
    __nv_bfloat16 *h, *l;
    int off;
    if (i < 524288)        { src = xq; h = g_xq_h; l = g_xq_l; off = i; }
    else if (i < 1048576)  { src = xr; h = g_xr_h; l = g_xr_l; off = i - 524288; }
    else {
        const int j = i - 1048576;
        const int w = j >> 18;
        off = j & 262143;
        const float* ws[5] = {w0, w1, w2, w3, w4};
        src = ws[w];
        h = g_wh + (size_t)w * (F * NHD);
        l = g_wl + (size_t)w * (F * NHD);
    }
    float4 v = ((const float4*)src)[off];
    __nv_bfloat162 h0 = __floats2bfloat162_rn(v.x, v.y);
    __nv_bfloat162 h1 = __floats2bfloat162_rn(v.z, v.w);
    __nv_bfloat162 l0 = __floats2bfloat162_rn(v.x - __bfloat162float(h0.x),
                                              v.y - __bfloat162float(h0.y));
    __nv_bfloat162 l1 = __floats2bfloat162_rn(v.z - __bfloat162float(h1.x),
                                              v.w - __bfloat162float(h1.y));
    ((__nv_bfloat162*)h)[off * 2]     = h0;
    ((__nv_bfloat162*)h)[off * 2 + 1] = h1;
    ((__nv_bfloat162*)l)[off * 2]     = l0;
    ((__nv_bfloat162*)l)[off * 2 + 1] = l1;
}

// ---------------------------------------------------------------------------
// bf16 split-GEMM (unchanged — known good)
// ---------------------------------------------------------------------------
#define GEMM_SMEM_BYTES 75776

__device__ __forceinline__ void gemm_bf16_body(
    const __nv_bfloat16* __restrict__ Ah, const __nv_bfloat16* __restrict__ Al,
    const __nv_bfloat16* __restrict__ Bh, const __nv_bfloat16* __restrict__ Bl,
    const float* __restrict__ bias, float* __restrict__ C,
    int M, int N, int K)
{
    extern __shared__ __nv_bfloat16 sb[];
    __nv_bfloat16* As_h = sb;
    __nv_bfloat16* As_l = sb + 10240;
    __nv_bfloat16* Bs_h = sb + 20480;
    __nv_bfloat16* Bs_l = sb + 29184;

    const int t    = threadIdx.x;
    const int lane = t & 31;
    const int w    = t >> 5;
    const int wm   = (w & 3) * 32;
    const int wn   = (w >> 2) * 64;
    const int g    = lane >> 2;
    const int tg   = lane & 3;
    const int m0   = blockIdx.y * 128;
    const int n0   = blockIdx.x * 128;

    float Cr[2][8][4];
#pragma unroll
    for (int mt = 0; mt < 2; mt++)
#pragma unroll
        for (int nt = 0; nt < 8; nt++) {
            Cr[mt][nt][0] = 0.f; Cr[mt][nt][1] = 0.f;
            Cr[mt][nt][2] = 0.f; Cr[mt][nt][3] = 0.f;
        }

    const int fm = t >> 1, fh = (t & 1) * 16;
    const int fk = t >> 3, fv = (t & 7) * 16;

    const __nv_bfloat16* gAh = Ah + (size_t)(m0 + fm) * K + fh;
    const __nv_bfloat16* gAl = Al + (size_t)(m0 + fm) * K + fh;
    const __nv_bfloat16* gBh = Bh + (size_t)fk * N + n0 + fv;
    const __nv_bfloat16* gBl = Bl + (size_t)fk * N + n0 + fv;

    {
        uint4 r0 = *(const uint4*)gAh;
        uint4 r1 = *(const uint4*)(gAh + 8);
        uint4 r2 = *(const uint4*)gAl;
        uint4 r3 = *(const uint4*)(gAl + 8);
        uint4 r4 = *(const uint4*)gBh;
        uint4 r5 = *(const uint4*)(gBh + 8);
        uint4 r6 = *(const uint4*)gBl;
        uint4 r7 = *(const uint4*)(gBl + 8);
        __nv_bfloat16* sa = As_h + fm * 40 + fh;
        *(uint4*)sa = r0; *(uint4*)(sa + 8) = r1;
        sa = As_l + fm * 40 + fh;
        *(uint4*)sa = r2; *(uint4*)(sa + 8) = r3;
        __nv_bfloat16* sbp = Bs_h + fk * 136 + fv;
        *(uint4*)sbp = r4; *(uint4*)(sbp + 8) = r5;
        sbp = Bs_l + fk * 136 + fv;
        *(uint4*)sbp = r6; *(uint4*)(sbp + 8) = r7;
    }
    __syncthreads();

    int buf = 0;
    const int nkc = K / 32;
    for (int kc = 0; kc < nkc; kc++) {
        uint4 ra[8];
        const bool has = (kc + 1) < nkc;
        if (has) {
            const __nv_bfloat16* pAh = gAh + (kc + 1) * 32;
            const __nv_bfloat16* pAl = gAl + (kc + 1) * 32;
            const __nv_bfloat16* pBh = gBh + (size_t)(kc + 1) * 32 * N;
            const __nv_bfloat16* pBl = gBl + (size_t)(kc + 1) * 32 * N;
            ra[0] = *(const uint4*)pAh; ra[1] = *(const uint4*)(pAh + 8);
            ra[2] = *(const uint4*)pAl; ra[3] = *(const uint4*)(pAl + 8);
            ra[4] = *(const uint4*)pBh; ra[5] = *(const uint4*)(pBh + 8);
            ra[6] = *(const uint4*)pBl; ra[7] = *(const uint4*)(pBl + 8);
        }
        const __nv_bfloat16* Ab_h = As_h + buf * 5120;
        const __nv_bfloat16* Ab_l = As_l + buf * 5120;
        const __nv_bfloat16* Bb_h = Bs_h + buf * 4352;
        const __nv_bfloat16* Bb_l = Bs_l + buf * 4352;

#pragma unroll
        for (int ks2 = 0; ks2 < 2; ks2++) {
            const int ks = ks2 * 16;
            u32 ah[2][4], al[2][4];
#pragma unroll
            for (int mt = 0; mt < 2; mt++) {
                const __nv_bfloat16* r0 = Ab_h + (wm + mt * 16 + g) * 40 + ks + 2 * tg;
                ah[mt][0] = *(const u32*)r0;
                ah[mt][1] = *(const u32*)(r0 + 8 * 40);
                ah[mt][2] = *(const u32*)(r0 + 8);
                ah[mt][3] = *(const u32*)(r0 + 8 * 40 + 8);
                const __nv_bfloat16* r1 = Ab_l + (wm + mt * 16 + g) * 40 + ks + 2 * tg;
                al[mt][0] = *(const u32*)r1;
                al[mt][1] = *(const u32*)(r1 + 8 * 40);
                al[mt][2] = *(const u32*)(r1 + 8);
                al[mt][3] = *(const u32*)(r1 + 8 * 40 + 8);
            }
            const u32 bbh = sptr(Bb_h + (ks + (lane & 15)) * 136 + wn);
            const u32 bbl = sptr(Bb_l + (ks + (lane & 15)) * 136 + wn);
#pragma unroll
            for (int nt = 0; nt < 8; nt++) {
                u32 bh0, bh1, bl0, bl1;
                ldm2t(bh0, bh1, bbh + nt * 16);
                ldm2t(bl0, bl1, bbl + nt * 16);
#pragma unroll
                for (int mt = 0; mt < 2; mt++) {
                    mma_bf16(Cr[mt][nt], ah[mt], bh0, bh1);
                    mma_bf16(Cr[mt][nt], ah[mt], bl0, bl1);
                    mma_bf16(Cr[mt][nt], al[mt], bh0, bh1);
                }
            }
        }

        if (has) {
            __nv_bfloat16* sa = As_h + (buf ^ 1) * 5120 + fm * 40 + fh;
            *(uint4*)sa = ra[0]; *(uint4*)(sa + 8) = ra[1];
            sa = As_l + (buf ^ 1) * 5120 + fm * 40 + fh;
            *(uint4*)sa = ra[2]; *(uint4*)(sa + 8) = ra[3];
            __nv_bfloat16* sbp = Bs_h + (buf ^ 1) * 4352 + fk * 136 + fv;
            *(uint4*)sbp = ra[4]; *(uint4*)(sbp + 8) = ra[5];
            sbp = Bs_l + (buf ^ 1) * 4352 + fk * 136 + fv;
            *(uint4*)sbp = ra[6]; *(uint4*)(sbp + 8) = ra[7];
            __syncthreads();
            buf ^= 1;
        }
    }

#pragma unroll
    for (int mt = 0; mt < 2; mt++) {
        const int row = m0 + wm + mt * 16 + g;
#pragma unroll
        for (int nt = 0; nt < 8; nt++) {
            const int col = n0 + wn + nt * 8 + 2 * tg;
            float2 b01 = *(const float2*)&bias[col];
            float2 o;
            o.x = Cr[mt][nt][0] + b01.x;
            o.y = Cr[mt][nt][1] + b01.y;
            *(float2*)(C + (size_t)row * N + col) = o;
            o.x = Cr[mt][nt][2] + b01.x;
            o.y = Cr[mt][nt][3] + b01.y;
            *(float2*)(C + (size_t)(row + 8) * N + col) = o;
        }
    }
}

__global__ __launch_bounds__(256) void proj_bf_kernel(
    const float* __restrict__ bq, const float* __restrict__ bk,
    const float* __restrict__ bv, const float* __restrict__ br)
{
    const int z = blockIdx.z;
    const __nv_bfloat16* Ah = (z < 3) ? g_xq_h : g_xr_h;
    const __nv_bfloat16* Al = (z < 3) ? g_xq_l : g_xr_l;
    const __nv_bfloat16* Bh = g_wh + (size_t)z * (F * NHD);
    const __nv_bfloat16* Bl = g_wl + (size_t)z * (F * NHD);
    const float* bias;
    float* C;
    switch (z) {
        case 0:  bias = bq; C = g_q; break;
        case 1:  bias = bk; C = g_k; break;
        case 2:  bias = bv; C = g_v; break;
        default: bias = br; C = g_r; break;
    }
    gemm_bf16_body(Ah, Al, Bh, Bl, bias, C, S, NHD, F);
}

__global__ __launch_bounds__(256) void out_bf_kernel(
    const float* __restrict__ bo, float* __restrict__ out)
{
    gemm_bf16_body(g_at_h, g_at_l,
                   g_wh + (size_t)4 * (F * NHD), g_wl + (size_t)4 * (F * NHD),
                   bo, out, S, F, NHD);
}

// ---------------------------------------------------------------------------
// ck[h][j] = rw[h].k[j,h,:],  cr[h][m] = rr[h].r[m,h,:]
// ---------------------------------------------------------------------------
__global__ __launch_bounds__(256) void bias_dots_kernel(
    const float* __restrict__ rwb, const float* __restrict__ rrb)
{
    const int gw   = (blockIdx.x * blockDim.x + threadIdx.x) >> 5;
    const int lane = threadIdx.x & 31;
    const int which = gw >= H * S;
    const int idx   = which ? gw - H * S : gw;
    const int hh = idx >> 11;
    const int j  = idx & (S - 1);
    const float* bias = which ? rrb : rwb;
    const float* mat  = which ? g_r : g_k;
    const float b0 = bias[hh * DH + lane];
    const float b1 = bias[hh * DH + 32 + lane];
    const float* row = mat + (size_t)j * NHD + hh * DH;
    float s = fmaf(b0, row[lane], b1 * row[32 + lane]);
#pragma unroll
    for (int off = 16; off > 0; off >>= 1)
        s += __shfl_xor_sync(0xffffffffu, s, off);
    if (lane == 0) {
        float* dst = which ? g_cr : g_ck;
        dst[hh * S + j] = s;
    }
}

// ---------------------------------------------------------------------------
// Causal flash attention, tf32 tensor cores.
// R7: circular incremental RSL (64 new rows/ktile), 8-block fills (halved
// fill instructions), P tile hosted in G region (no second barrier).
// perm(d): pos 8m+2t <- d=8m+t ; pos 8m+2t+1 <- d=8m+t+4
// ---------------------------------------------------------------------------
#define KPAD 72
#define VPAD 72
#define GPAD 132
#define SMEM_ATTN ((64*KPAD + 64*VPAD + 128*KPAD + 64*GPAD + 128 + 64) * 4)

__global__ __launch_bounds__(128) void attn_kernel()
{
    const int h   = blockIdx.y;
    const int qi0 = (gridDim.x - 1 - blockIdx.x) * 64;

    extern __shared__ float sm[];
    float* ks    = sm;                 // 64 x KPAD (perm d)
    float* vs    = ks + 64 * KPAD;     // 64 x VPAD (natural)
    float* rsl   = vs + 64 * VPAD;     // 128 x KPAD (perm d, circular rows)
    float* G     = rsl + 128 * KPAD;   // 64 x GPAD (fp32); P reuses same rows
    float* crs_s = G + 64 * GPAD;      // 128
    float* cks_s = crs_s + 128;        // 64

    const int t    = threadIdx.x;
    const int lane = t & 31;
    const int w    = t >> 5;
    const int g    = lane >> 2;
    const int tg   = lane & 3;
    const int i0   = w * 16 + g;
    const int hb   = h * DH;
    const int tile0 = 6 - 2 * w;       // first G n-tile this warp needs

    u32 qa[8][4];
    {
        const float* q0 = &g_q[(size_t)(qi0 + i0) * NHD + hb];
        const float* q1 = q0 + 8 * NHD;
#pragma unroll
        for (int k0 = 0; k0 < 8; k0++) {
            qa[k0][0] = f2tf32(q0[k0 * 8 + tg]);
            qa[k0][1] = f2tf32(q1[k0 * 8 + tg]);
            qa[k0][2] = f2tf32(q0[k0 * 8 + tg + 4]);
            qa[k0][3] = f2tf32(q1[k0 * 8 + tg + 4]);
        }
    }

    float O[8][4];
#pragma unroll
    for (int nt = 0; nt < 8; nt++) {
        O[nt][0] = 0.f; O[nt][1] = 0.f; O[nt][2] = 0.f; O[nt][3] = 0.f;
    }
    float m0 = -1e30f, m1 = -1e30f, l0 = 0.f, l1 = 0.f;

    const int nkt = qi0 / 64 + 1;
    for (int kt = 0; kt < nkt; kt++) {
        const int kj0   = kt * 64;
        const int base  = (S - 1) + kj0 - qi0 - 63;
        const int rbase = base & 127;
        __syncthreads();  // previous consumers done before refill

        // ---- K (perm) + V (natural) fills: 8-wide d-blocks ----
#pragma unroll
        for (int it = 0; it < 4; it++) {
            const int idx = t + it * 128;      // < 512
            const int r = idx >> 3, m8 = (idx & 7) << 3;
            const float* kp = &g_k[(size_t)(kj0 + r) * NHD + hb + m8];
            const float* vp = &g_v[(size_t)(kj0 + r) * NHD + hb + m8];
            float4 ka = *(const float4*)kp;
            float4 kb = *(const float4*)(kp + 4);
            float4 va = *(const float4*)vp;
            float4 vb = *(const float4*)(vp + 4);
            float2* kd = (float2*)&ks[r * KPAD + m8];
            kd[0] = make_float2(f2tf32f(ka.x), f2tf32f(kb.x));
            kd[1] = make_float2(f2tf32f(ka.y), f2tf32f(kb.y));
            kd[2] = make_float2(f2tf32f(ka.z), f2tf32f(kb.z));
            kd[3] = make_float2(f2tf32f(ka.w), f2tf32f(kb.w));
            va.x = f2tf32f(va.x); va.y = f2tf32f(va.y);
            va.z = f2tf32f(va.z); va.w = f2tf32f(va.w);
            vb.x = f2tf32f(vb.x); vb.y = f2tf32f(vb.y);
            vb.z = f2tf32f(vb.z); vb.w = f2tf32f(vb.w);
            float* vd = &vs[r * VPAD + m8];
            *(float4*)vd = va;
            *(float4*)(vd + 4) = vb;
        }
        // ---- RSL (perm, circular): only new rows (all 128 on first tile) ----
        {
            const int rl0 = (kt == 0) ? 0 : 64;
            const int nit = (kt == 0) ? 8 : 4;
            for (int it = 0; it < nit; it++) {
                const int idx = t + it * 128;
                const int row = rl0 + (idx >> 3);
                const int m8  = (idx & 7) << 3;
                int mg = base + row;
                if (mg > S - 1) mg = S - 1;
                const float* rp = &g_r[(size_t)mg * NHD + hb + m8];
                float4 a = *(const float4*)rp;
                float4 b = *(const float4*)(rp + 4);
                float2* rd = (float2*)&rsl[((rbase + row) & 127) * KPAD + m8];
                rd[0] = make_float2(f2tf32f(a.x), f2tf32f(b.x));
                rd[1] = make_float2(f2tf32f(a.y), f2tf32f(b.y));
                rd[2] = make_float2(f2tf32f(a.z), f2tf32f(b.z));
                rd[3] = make_float2(f2tf32f(a.w), f2tf32f(b.w));
            }
        }
        if (t < 64) cks_s[t] = g_ck[h * S + kj0 + t];
        {
            int mg = base + t;
            if (mg > S - 1) mg = S - 1;
            crs_s[t] = (t < 127) ? g_cr[h * S + mg] : 0.f;
        }
        __syncthreads();

        // ---- windowed G = Q @ RSL^T (+cr): tiles tile0 .. tile0+9 ----
        {
            int prow[10];
#pragma unroll
            for (int ni = 0; ni < 10; ni++)
                prow[ni] = ((rbase + (tile0 + ni) * 8 + g) & 127) * KPAD;
            float gc[10][4];
#pragma unroll
            for (int ni = 0; ni < 10; ni++) {
                const int col = (tile0 + ni) * 8 + 2 * tg;
                gc[ni][0] = crs_s[col];
                gc[ni][1] = crs_s[col + 1];
                gc[ni][2] = gc[ni][0];
                gc[ni][3] = gc[ni][1];
            }
#pragma unroll
            for (int k0 = 0; k0 < 8; k0++) {
#pragma unroll
                for (int ni = 0; ni < 10; ni++) {
                    uint2 bb = *(const uint2*)&rsl[prow[ni] + k0 * 8 + 2 * tg];
                    mma_tf32(gc[ni], qa[k0], bb.x, bb.y);
                }
            }
#pragma unroll
            for (int ni = 0; ni < 10; ni++) {
                const int col = (tile0 + ni) * 8 + 2 * tg;
                *(float2*)&G[i0 * GPAD + col]       = make_float2(gc[ni][0], gc[ni][1]);
                *(float2*)&G[(i0 + 8) * GPAD + col] = make_float2(gc[ni][2], gc[ni][3]);
            }
        }
        __syncwarp();  // G rows are warp-private

        // ---- AC = Q @ K^T (+ck) ----
        float sc[8][4];
#pragma unroll
        for (int nt = 0; nt < 8; nt++) {
            const int col = nt * 8 + 2 * tg;
            sc[nt][0] = cks_s[col];
            sc[nt][1] = cks_s[col + 1];
            sc[nt][2] = sc[nt][0];
            sc[nt][3] = sc[nt][1];
        }
#pragma unroll
        for (int k0 = 0; k0 < 8; k0++) {
#pragma unroll
            for (int nt = 0; nt < 8; nt++) {
                uint2 bb = *(const uint2*)&ks[(nt * 8 + g) * KPAD + k0 * 8 + 2 * tg];
                mma_tf32(sc[nt], qa[k0], bb.x, bb.y);
            }
        }

        // ---- BD gather + online softmax (reads own G rows only) ----
        const bool diag = (kt == nkt - 1);
        float rmax0 = -1e30f, rmax1 = -1e30f;
#pragma unroll
        for (int nt = 0; nt < 8; nt++) {
            const int j = nt * 8 + 2 * tg;
            float s00 = (sc[nt][0] + G[i0 * GPAD + 63 + j - i0]) * 0.125f;
            float s01 = (sc[nt][1] + G[i0 * GPAD + 64 + j - i0]) * 0.125f;
            float s10 = (sc[nt][2] + G[(i0 + 8) * GPAD + 55 + j - i0]) * 0.125f;
            float s11 = (sc[nt][3] + G[(i0 + 8) * GPAD + 56 + j - i0]) * 0.125f;
            if (diag) {
                if (kj0 + j     > qi0 + i0)     s00 = -1e30f;
                if (kj0 + j + 1 > qi0 + i0)     s01 = -1e30f;
                if (kj0 + j     > qi0 + i0 + 8) s10 = -1e30f;
                if (kj0 + j + 1 > qi0 + i0 + 8) s11 = -1e30f;
            }
            sc[nt][0] = s00; sc[nt][1] = s01; sc[nt][2] = s10; sc[nt][3] = s11;
            rmax0 = fmaxf(rmax0, fmaxf(s00, s01));
            rmax1 = fmaxf(rmax1, fmaxf(s10, s11));
        }
        rmax0 = fmaxf(rmax0, __shfl_xor_sync(0xffffffffu, rmax0, 1));
        rmax0 = fmaxf(rmax0, __shfl_xor_sync(0xffffffffu, rmax0, 2));
        rmax1 = fmaxf(rmax1, __shfl_xor_sync(0xffffffffu, rmax1, 1));
        rmax1 = fmaxf(rmax1, __shfl_xor_sync(0xffffffffu, rmax1, 2));

        const float newm0 = fmaxf(m0, rmax0);
        const float newm1 = fmaxf(m1, rmax1);
        const float a0 = __expf(m0 - newm0);
        const float a1 = __expf(m1 - newm1);
        m0 = newm0; m1 = newm1;

        float psum0 = 0.f, psum1 = 0.f;
#pragma unroll
        for (int nt = 0; nt < 8; nt++) {
            sc[nt][0] = __expf(sc[nt][0] - m0);
            sc[nt][1] = __expf(sc[nt][1] - m0);
            sc[nt][2] = __expf(sc[nt][2] - m1);
            sc[nt][3] = __expf(sc[nt][3] - m1);
            psum0 += sc[nt][0] + sc[nt][1];
            psum1 += sc[nt][2] + sc[nt][3];
        }
        psum0 += __shfl_xor_sync(0xffffffffu, psum0, 1);
        psum0 += __shfl_xor_sync(0xffffffffu, psum0, 2);
        psum1 += __shfl_xor_sync(0xffffffffu, psum1, 1);
        psum1 += __shfl_xor_sync(0xffffffffu, psum1, 2);
        l0 = l0 * a0 + psum0;
        l1 = l1 * a1 + psum1;
#pragma unroll
        for (int nt = 0; nt < 8; nt++) {
            O[nt][0] *= a0; O[nt][1] *= a0;
            O[nt][2] *= a1; O[nt][3] *= a1;
        }

        // ---- store P (tf32) into this warp's own G rows (cols 0..63) ----
        float* psb = G;
#pragma unroll
        for (int nt = 0; nt < 8; nt++) {
            const int j = nt * 8 + 2 * tg;
            *(float2*)&psb[i0 * GPAD + j] =
                make_float2(f2tf32f(sc[nt][0]), f2tf32f(sc[nt][1]));
            *(float2*)&psb[(i0 + 8) * GPAD + j] =
                make_float2(f2tf32f(sc[nt][2]), f2tf32f(sc[nt][3]));
        }
        __syncwarp();  // P rows are warp-private

        // ---- PV: O += P @ V ----
#pragma unroll
        for (int k0 = 0; k0 < 8; k0++) {
            u32 pa[4];
            pa[0] = __float_as_uint(psb[i0 * GPAD + k0 * 8 + tg]);
            pa[1] = __float_as_uint(psb[(i0 + 8) * GPAD + k0 * 8 + tg]);
            pa[2] = __float_as_uint(psb[i0 * GPAD + k0 * 8 + tg + 4]);
            pa[3] = __float_as_uint(psb[(i0 + 8) * GPAD + k0 * 8 + tg + 4]);
#pragma unroll
            for (int nt = 0; nt < 8; nt++) {
                u32 b0 = __float_as_uint(vs[(k0 * 8 + tg) * VPAD + nt * 8 + g]);
                u32 b1 = __float_as_uint(vs[(k0 * 8 + tg + 4) * VPAD + nt * 8 + g]);
                mma_tf32(O[nt], pa, b0, b1);
            }
        }
    }

    // ---- epilogue: normalize + bf16 hi/lo split for the output GEMM ----
    const float inv0 = 1.f / l0;
    const float inv1 = 1.f / l1;
#pragma unroll
    for (int nt = 0; nt < 8; nt++) {
        const int col = nt * 8 + 2 * tg;
        const size_t idx0 = (size_t)(qi0 + i0) * NHD + hb + col;
        const size_t idx1 = (size_t)(qi0 + i0 + 8) * NHD + hb + col;
        float o00 = O[nt][0] * inv0, o01 = O[nt][1] * inv0;
        float o10 = O[nt][2] * inv1, o11 = O[nt][3] * inv1;
        __nv_bfloat162 h0 = __floats2bfloat162_rn(o00, o01);
        __nv_bfloat162 h1 = __floats2bfloat162_rn(o10, o11);
        __nv_bfloat162 L0 = __floats2bfloat162_rn(o00 - __bfloat162float(h0.x),
                                                  o01 - __bfloat162float(h0.y));
        __nv_bfloat162 L1 = __floats2bfloat162_rn(o10 - __bfloat162float(h1.x),
                                                  o11 - __bfloat162float(h1.y));
        *(__nv_bfloat162*)&g_at_h[idx0] = h0;
        *(__nv_bfloat162*)&g_at_l[idx0] = L0;
        *(__nv_bfloat162*)&g_at_h[idx1] = h1;
        *(__nv_bfloat162*)&g_at_l[idx1] = L1;
    }
}

// ---------------------------------------------------------------------------
extern "C" void kernel_launch(void* const* d_in, const int* in_sizes, int n_in,
                              void* d_out, int out_size)
{
    const float* inputs_q = (const float*)d_in[0];
    const float* pos_emb  = (const float*)d_in[1];
    const float* r_w_bias = (const float*)d_in[2];
    const float* r_r_bias = (const float*)d_in[3];
    const float* Wq = (const float*)d_in[4];
    const float* bq = (const float*)d_in[5];
    const float* Wk = (const float*)d_in[6];
    const float* bk = (const float*)d_in[7];
    const float* Wv = (const float*)d_in[8];
    const float* bv = (const float*)d_in[9];
    const float* Wr = (const float*)d_in[10];
    const float* br = (const float*)d_in[11];
    const float* Wo = (const float*)d_in[12];
    const float* bo = (const float*)d_in[13];
    float* out = (float*)d_out;

    cudaFuncSetAttribute(attn_kernel,
                         cudaFuncAttributeMaxDynamicSharedMemorySize, SMEM_ATTN);
    cudaFuncSetAttribute(proj_bf_kernel,
                         cudaFuncAttributeMaxDynamicSharedMemorySize, GEMM_SMEM_BYTES);
    cudaFuncSetAttribute(out_bf_kernel,
                         cudaFuncAttributeMaxDynamicSharedMemorySize, GEMM_SMEM_BYTES);

    split_kernel<<<(2 * 524288 + 5 * 262144) / 256, 256>>>(
        inputs_q, pos_emb, Wq, Wk, Wv, Wr, Wo);

    proj_bf_kernel<<<dim3(NHD / 128, S / 128, 4), 256, GEMM_SMEM_BYTES>>>(
        bq, bk, bv, br);

    bias_dots_kernel<<<(2 * H * S * 32) / 256, 256>>>(r_w_bias, r_r_bias);

    attn_kernel<<<dim3(S / 64, H), 128, SMEM_ATTN>>>();

    out_bf_kernel<<<dim3(F / 128, S / 128), 256, GEMM_SMEM_BYTES>>>(bo, out);
}

// round 8
// speedup vs baseline: 5.3464x; 1.0109x over previous
#include <cuda_runtime.h>
#include <cuda_bf16.h>

#define S 2048
#define F 1024
#define H 16
#define DH 64
#define NHD 1024  // H*DH

typedef unsigned long long u64;
typedef unsigned int u32;

// ---- tf32 helpers (attention) ----
__device__ __forceinline__ u32 f2tf32(float x) {
    u32 r;
    asm("cvt.rna.tf32.f32 %0, %1;" : "=r"(r) : "f"(x));
    return r;
}
__device__ __forceinline__ float f2tf32f(float x) {
    return __uint_as_float(f2tf32(x));
}
__device__ __forceinline__ void mma_tf32(float c[4], const u32 a[4], u32 b0, u32 b1) {
    asm volatile(
        "mma.sync.aligned.m16n8k8.row.col.f32.tf32.tf32.f32 "
        "{%0,%1,%2,%3}, {%4,%5,%6,%7}, {%8,%9}, {%0,%1,%2,%3};\n"
        : "+f"(c[0]), "+f"(c[1]), "+f"(c[2]), "+f"(c[3])
        : "r"(a[0]), "r"(a[1]), "r"(a[2]), "r"(a[3]), "r"(b0), "r"(b1));
}

// ---- bf16 helpers (GEMMs) ----
__device__ __forceinline__ void mma_bf16(float c[4], const u32 a[4], u32 b0, u32 b1) {
    asm volatile(
        "mma.sync.aligned.m16n8k16.row.col.f32.bf16.bf16.f32 "
        "{%0,%1,%2,%3}, {%4,%5,%6,%7}, {%8,%9}, {%0,%1,%2,%3};\n"
        : "+f"(c[0]), "+f"(c[1]), "+f"(c[2]), "+f"(c[3])
        : "r"(a[0]), "r"(a[1]), "r"(a[2]), "r"(a[3]), "r"(b0), "r"(b1));
}
__device__ __forceinline__ void ldm2t(u32& d0, u32& d1, u32 saddr) {
    asm volatile("ldmatrix.sync.aligned.m8n8.x2.trans.shared.b16 {%0,%1}, [%2];"
                 : "=r"(d0), "=r"(d1) : "r"(saddr));
}
__device__ __forceinline__ u32 sptr(const void* p) {
    return (u32)__cvta_generic_to_shared(p);
}
__device__ __forceinline__ void pair_bar(int wp) {
    asm volatile("bar.sync %0, 64;" :: "r"(1 + wp) : "memory");
}

// Scratch (device globals: allocation-free per harness rules)
__device__ float g_q[S * NHD];
__device__ float g_k[S * NHD];
__device__ float g_v[S * NHD];
__device__ float g_r[S * NHD];
__device__ float g_ck[H * S];
__device__ float g_cr[H * S];
// bf16 hi/lo split panels
__device__ __nv_bfloat16 g_xq_h[S * F],   g_xq_l[S * F];
__device__ __nv_bfloat16 g_xr_h[S * F],   g_xr_l[S * F];
__device__ __nv_bfloat16 g_wh[5 * F * NHD], g_wl[5 * F * NHD];  // Wq,Wk,Wv,Wr,Wo
__device__ __nv_bfloat16 g_at_h[S * NHD], g_at_l[S * NHD];

// ---------------------------------------------------------------------------
// Split fp32 -> (bf16 hi, bf16 lo) for all GEMM operands in ONE launch.
// ---------------------------------------------------------------------------
__global__ __launch_bounds__(256) void split_kernel(
    const float* __restrict__ xq, const float* __restrict__ xr,
    const float* __restrict__ w0, const float* __restrict__ w1,
    const float* __restrict__ w2, const float* __restrict__ w3,
    const float* __restrict__ w4)
{
    const int i = blockIdx.x * 256 + threadIdx.x;
    const float* src;
    __nv_bfloat16 *h, *l;
    int off;
    if (i < 524288)        { src = xq; h = g_xq_h; l = g_xq_l; off = i; }
    else if (i < 1048576)  { src = xr; h = g_xr_h; l = g_xr_l; off = i - 524288; }
    else {
        const int j = i - 1048576;
        const int w = j >> 18;
        off = j & 262143;
        const float* ws[5] = {w0, w1, w2, w3, w4};
        src = ws[w];
        h = g_wh + (size_t)w * (F * NHD);
        l = g_wl + (size_t)w * (F * NHD);
    }
    float4 v = ((const float4*)src)[off];
    __nv_bfloat162 h0 = __floats2bfloat162_rn(v.x, v.y);
    __nv_bfloat162 h1 = __floats2bfloat162_rn(v.z, v.w);
    __nv_bfloat162 l0 = __floats2bfloat162_rn(v.x - __bfloat162float(h0.x),
                                              v.y - __bfloat162float(h0.y));
    __nv_bfloat162 l1 = __floats2bfloat162_rn(v.z - __bfloat162float(h1.x),
                                              v.w - __bfloat162float(h1.y));
    ((__nv_bfloat162*)h)[off * 2]     = h0;
    ((__nv_bfloat162*)h)[off * 2 + 1] = h1;
    ((__nv_bfloat162*)l)[off * 2]     = l0;
    ((__nv_bfloat162*)l)[off * 2 + 1] = l1;
}

// ---------------------------------------------------------------------------
// bf16 split-GEMM (unchanged — known good)
// ---------------------------------------------------------------------------
#define GEMM_SMEM_BYTES 75776

__device__ __forceinline__ void gemm_bf16_body(
    const __nv_bfloat16* __restrict__ Ah, const __nv_bfloat16* __restrict__ Al,
    const __nv_bfloat16* __restrict__ Bh, const __nv_bfloat16* __restrict__ Bl,
    const float* __restrict__ bias, float* __restrict__ C,
    int M, int N, int K)
{
    extern __shared__ __nv_bfloat16 sb[];
    __nv_bfloat16* As_h = sb;
    __nv_bfloat16* As_l = sb + 10240;
    __nv_bfloat16* Bs_h = sb + 20480;
    __nv_bfloat16* Bs_l = sb + 29184;

    const int t    = threadIdx.x;
    const int lane = t & 31;
    const int w    = t >> 5;
    const int wm   = (w & 3) * 32;
    const int wn   = (w >> 2) * 64;
    const int g    = lane >> 2;
    const int tg   = lane & 3;
    const int m0   = blockIdx.y * 128;
    const int n0   = blockIdx.x * 128;

    float Cr[2][8][4];
#pragma unroll
    for (int mt = 0; mt < 2; mt++)
#pragma unroll
        for (int nt = 0; nt < 8; nt++) {
            Cr[mt][nt][0] = 0.f; Cr[mt][nt][1] = 0.f;
            Cr[mt][nt][2] = 0.f; Cr[mt][nt][3] = 0.f;
        }

    const int fm = t >> 1, fh = (t & 1) * 16;
    const int fk = t >> 3, fv = (t & 7) * 16;

    const __nv_bfloat16* gAh = Ah + (size_t)(m0 + fm) * K + fh;
    const __nv_bfloat16* gAl = Al + (size_t)(m0 + fm) * K + fh;
    const __nv_bfloat16* gBh = Bh + (size_t)fk * N + n0 + fv;
    const __nv_bfloat16* gBl = Bl + (size_t)fk * N + n0 + fv;

    {
        uint4 r0 = *(const uint4*)gAh;
        uint4 r1 = *(const uint4*)(gAh + 8);
        uint4 r2 = *(const uint4*)gAl;
        uint4 r3 = *(const uint4*)(gAl + 8);
        uint4 r4 = *(const uint4*)gBh;
        uint4 r5 = *(const uint4*)(gBh + 8);
        uint4 r6 = *(const uint4*)gBl;
        uint4 r7 = *(const uint4*)(gBl + 8);
        __nv_bfloat16* sa = As_h + fm * 40 + fh;
        *(uint4*)sa = r0; *(uint4*)(sa + 8) = r1;
        sa = As_l + fm * 40 + fh;
        *(uint4*)sa = r2; *(uint4*)(sa + 8) = r3;
        __nv_bfloat16* sbp = Bs_h + fk * 136 + fv;
        *(uint4*)sbp = r4; *(uint4*)(sbp + 8) = r5;
        sbp = Bs_l + fk * 136 + fv;
        *(uint4*)sbp = r6; *(uint4*)(sbp + 8) = r7;
    }
    __syncthreads();

    int buf = 0;
    const int nkc = K / 32;
    for (int kc = 0; kc < nkc; kc++) {
        uint4 ra[8];
        const bool has = (kc + 1) < nkc;
        if (has) {
            const __nv_bfloat16* pAh = gAh + (kc + 1) * 32;
            const __nv_bfloat16* pAl = gAl + (kc + 1) * 32;
            const __nv_bfloat16* pBh = gBh + (size_t)(kc + 1) * 32 * N;
            const __nv_bfloat16* pBl = gBl + (size_t)(kc + 1) * 32 * N;
            ra[0] = *(const uint4*)pAh; ra[1] = *(const uint4*)(pAh + 8);
            ra[2] = *(const uint4*)pAl; ra[3] = *(const uint4*)(pAl + 8);
            ra[4] = *(const uint4*)pBh; ra[5] = *(const uint4*)(pBh + 8);
            ra[6] = *(const uint4*)pBl; ra[7] = *(const uint4*)(pBl + 8);
        }
        const __nv_bfloat16* Ab_h = As_h + buf * 5120;
        const __nv_bfloat16* Ab_l = As_l + buf * 5120;
        const __nv_bfloat16* Bb_h = Bs_h + buf * 4352;
        const __nv_bfloat16* Bb_l = Bs_l + buf * 4352;

#pragma unroll
        for (int ks2 = 0; ks2 < 2; ks2++) {
            const int ks = ks2 * 16;
            u32 ah[2][4], al[2][4];
#pragma unroll
            for (int mt = 0; mt < 2; mt++) {
                const __nv_bfloat16* r0 = Ab_h + (wm + mt * 16 + g) * 40 + ks + 2 * tg;
                ah[mt][0] = *(const u32*)r0;
                ah[mt][1] = *(const u32*)(r0 + 8 * 40);
                ah[mt][2] = *(const u32*)(r0 + 8);
                ah[mt][3] = *(const u32*)(r0 + 8 * 40 + 8);
                const __nv_bfloat16* r1 = Ab_l + (wm + mt * 16 + g) * 40 + ks + 2 * tg;
                al[mt][0] = *(const u32*)r1;
                al[mt][1] = *(const u32*)(r1 + 8 * 40);
                al[mt][2] = *(const u32*)(r1 + 8);
                al[mt][3] = *(const u32*)(r1 + 8 * 40 + 8);
            }
            const u32 bbh = sptr(Bb_h + (ks + (lane & 15)) * 136 + wn);
            const u32 bbl = sptr(Bb_l + (ks + (lane & 15)) * 136 + wn);
#pragma unroll
            for (int nt = 0; nt < 8; nt++) {
                u32 bh0, bh1, bl0, bl1;
                ldm2t(bh0, bh1, bbh + nt * 16);
                ldm2t(bl0, bl1, bbl + nt * 16);
#pragma unroll
                for (int mt = 0; mt < 2; mt++) {
                    mma_bf16(Cr[mt][nt], ah[mt], bh0, bh1);
                    mma_bf16(Cr[mt][nt], ah[mt], bl0, bl1);
                    mma_bf16(Cr[mt][nt], al[mt], bh0, bh1);
                }
            }
        }

        if (has) {
            __nv_bfloat16* sa = As_h + (buf ^ 1) * 5120 + fm * 40 + fh;
            *(uint4*)sa = ra[0]; *(uint4*)(sa + 8) = ra[1];
            sa = As_l + (buf ^ 1) * 5120 + fm * 40 + fh;
            *(uint4*)sa = ra[2]; *(uint4*)(sa + 8) = ra[3];
            __nv_bfloat16* sbp = Bs_h + (buf ^ 1) * 4352 + fk * 136 + fv;
            *(uint4*)sbp = ra[4]; *(uint4*)(sbp + 8) = ra[5];
            sbp = Bs_l + (buf ^ 1) * 4352 + fk * 136 + fv;
            *(uint4*)sbp = ra[6]; *(uint4*)(sbp + 8) = ra[7];
            __syncthreads();
            buf ^= 1;
        }
    }

#pragma unroll
    for (int mt = 0; mt < 2; mt++) {
        const int row = m0 + wm + mt * 16 + g;
#pragma unroll
        for (int nt = 0; nt < 8; nt++) {
            const int col = n0 + wn + nt * 8 + 2 * tg;
            float2 b01 = *(const float2*)&bias[col];
            float2 o;
            o.x = Cr[mt][nt][0] + b01.x;
            o.y = Cr[mt][nt][1] + b01.y;
            *(float2*)(C + (size_t)row * N + col) = o;
            o.x = Cr[mt][nt][2] + b01.x;
            o.y = Cr[mt][nt][3] + b01.y;
            *(float2*)(C + (size_t)(row + 8) * N + col) = o;
        }
    }
}

__global__ __launch_bounds__(256) void proj_bf_kernel(
    const float* __restrict__ bq, const float* __restrict__ bk,
    const float* __restrict__ bv, const float* __restrict__ br)
{
    const int z = blockIdx.z;
    const __nv_bfloat16* Ah = (z < 3) ? g_xq_h : g_xr_h;
    const __nv_bfloat16* Al = (z < 3) ? g_xq_l : g_xr_l;
    const __nv_bfloat16* Bh = g_wh + (size_t)z * (F * NHD);
    const __nv_bfloat16* Bl = g_wl + (size_t)z * (F * NHD);
    const float* bias;
    float* C;
    switch (z) {
        case 0:  bias = bq; C = g_q; break;
        case 1:  bias = bk; C = g_k; break;
        case 2:  bias = bv; C = g_v; break;
        default: bias = br; C = g_r; break;
    }
    gemm_bf16_body(Ah, Al, Bh, Bl, bias, C, S, NHD, F);
}

__global__ __launch_bounds__(256) void out_bf_kernel(
    const float* __restrict__ bo, float* __restrict__ out)
{
    gemm_bf16_body(g_at_h, g_at_l,
                   g_wh + (size_t)4 * (F * NHD), g_wl + (size_t)4 * (F * NHD),
                   bo, out, S, F, NHD);
}

// ---------------------------------------------------------------------------
// ck[h][j] = rw[h].k[j,h,:],  cr[h][m] = rr[h].r[m,h,:]
// ---------------------------------------------------------------------------
__global__ __launch_bounds__(256) void bias_dots_kernel(
    const float* __restrict__ rwb, const float* __restrict__ rrb)
{
    const int gw   = (blockIdx.x * blockDim.x + threadIdx.x) >> 5;
    const int lane = threadIdx.x & 31;
    const int which = gw >= H * S;
    const int idx   = which ? gw - H * S : gw;
    const int hh = idx >> 11;
    const int j  = idx & (S - 1);
    const float* bias = which ? rrb : rwb;
    const float* mat  = which ? g_r : g_k;
    const float b0 = bias[hh * DH + lane];
    const float b1 = bias[hh * DH + 32 + lane];
    const float* row = mat + (size_t)j * NHD + hh * DH;
    float s = fmaf(b0, row[lane], b1 * row[32 + lane]);
#pragma unroll
    for (int off = 16; off > 0; off >>= 1)
        s += __shfl_xor_sync(0xffffffffu, s, off);
    if (lane == 0) {
        float* dst = which ? g_cr : g_ck;
        dst[hh * S + j] = s;
    }
}

// ---------------------------------------------------------------------------
// Causal flash attention, tf32 tensor cores.
// R8: 256 threads / CTA. Warp (wp, half): wp=w&3 owns 16 q-rows, half=w>>2
// owns 32 key-cols. Pair shares the row max via a tiny smem exchange +
// named pair barrier; partial l/O merged once at the end.
// perm(d): pos 8m+2t <- d=8m+t ; pos 8m+2t+1 <- d=8m+t+4
// ---------------------------------------------------------------------------
#define KPAD 72
#define VPAD 72
#define GPAD 132
#define SMEM_ATTN ((64*KPAD + 64*VPAD + 128*KPAD + 64*GPAD + 128 + 64 + 128) * 4)

__global__ __launch_bounds__(256, 2) void attn_kernel()
{
    const int h   = blockIdx.y;
    const int qi0 = (gridDim.x - 1 - blockIdx.x) * 64;

    extern __shared__ float sm[];
    float* ks    = sm;                 // 64 x KPAD (perm d)
    float* vs    = ks + 64 * KPAD;     // 64 x VPAD (natural)
    float* rsl   = vs + 64 * VPAD;     // 128 x KPAD (perm d, circular rows)
    float* G     = rsl + 128 * KPAD;   // 64 x GPAD (fp32); P reuses same rows
    float* crs_s = G + 64 * GPAD;      // 128
    float* cks_s = crs_s + 128;        // 64
    float* mx    = cks_s + 64;         // 128: per-row, per-half max exchange

    const int t    = threadIdx.x;
    const int lane = t & 31;
    const int w    = t >> 5;
    const int wp   = w & 3;            // q-row group
    const int half = w >> 2;           // key-column half
    const int g    = lane >> 2;
    const int tg   = lane & 3;
    const int i0   = wp * 16 + g;
    const int hb   = h * DH;
    const int jbase = half * 32;
    // G n-tiles: half0 -> 6-2wp .. 10-2wp ; half1 -> 11-2wp .. 15-2wp
    const int tile0 = (half == 0) ? (6 - 2 * wp) : (11 - 2 * wp);

    u32 qa[8][4];
    {
        const float* q0 = &g_q[(size_t)(qi0 + i0) * NHD + hb];
        const float* q1 = q0 + 8 * NHD;
#pragma unroll
        for (int k0 = 0; k0 < 8; k0++) {
            qa[k0][0] = f2tf32(q0[k0 * 8 + tg]);
            qa[k0][1] = f2tf32(q1[k0 * 8 + tg]);
            qa[k0][2] = f2tf32(q0[k0 * 8 + tg + 4]);
            qa[k0][3] = f2tf32(q1[k0 * 8 + tg + 4]);
        }
    }

    float O[8][4];
#pragma unroll
    for (int nt = 0; nt < 8; nt++) {
        O[nt][0] = 0.f; O[nt][1] = 0.f; O[nt][2] = 0.f; O[nt][3] = 0.f;
    }
    float m0 = -1e30f, m1 = -1e30f, l0 = 0.f, l1 = 0.f;

    const int nkt = qi0 / 64 + 1;
    for (int kt = 0; kt < nkt; kt++) {
        const int kj0   = kt * 64;
        const int base  = (S - 1) + kj0 - qi0 - 63;
        const int rbase = base & 127;
        __syncthreads();  // all consumers done before refill

        // ---- K (perm) + V (natural) fills: 512 items, 2 iterations ----
#pragma unroll
        for (int it = 0; it < 2; it++) {
            const int idx = t + it * 256;
            const int r = idx >> 3, m8 = (idx & 7) << 3;
            const float* kp = &g_k[(size_t)(kj0 + r) * NHD + hb + m8];
            const float* vp = &g_v[(size_t)(kj0 + r) * NHD + hb + m8];
            float4 ka = *(const float4*)kp;
            float4 kb = *(const float4*)(kp + 4);
            float4 va = *(const float4*)vp;
            float4 vb = *(const float4*)(vp + 4);
            float2* kd = (float2*)&ks[r * KPAD + m8];
            kd[0] = make_float2(f2tf32f(ka.x), f2tf32f(kb.x));
            kd[1] = make_float2(f2tf32f(ka.y), f2tf32f(kb.y));
            kd[2] = make_float2(f2tf32f(ka.z), f2tf32f(kb.z));
            kd[3] = make_float2(f2tf32f(ka.w), f2tf32f(kb.w));
            va.x = f2tf32f(va.x); va.y = f2tf32f(va.y);
            va.z = f2tf32f(va.z); va.w = f2tf32f(va.w);
            vb.x = f2tf32f(vb.x); vb.y = f2tf32f(vb.y);
            vb.z = f2tf32f(vb.z); vb.w = f2tf32f(vb.w);
            float* vd = &vs[r * VPAD + m8];
            *(float4*)vd = va;
            *(float4*)(vd + 4) = vb;
        }
        // ---- RSL (perm, circular): only new rows ----
        {
            const int rl0 = (kt == 0) ? 0 : 64;
            const int nit = (kt == 0) ? 4 : 2;
            for (int it = 0; it < nit; it++) {
                const int idx = t + it * 256;
                const int row = rl0 + (idx >> 3);
                const int m8  = (idx & 7) << 3;
                int mg = base + row;
                if (mg > S - 1) mg = S - 1;
                const float* rp = &g_r[(size_t)mg * NHD + hb + m8];
                float4 a = *(const float4*)rp;
                float4 b = *(const float4*)(rp + 4);
                float2* rd = (float2*)&rsl[((rbase + row) & 127) * KPAD + m8];
                rd[0] = make_float2(f2tf32f(a.x), f2tf32f(b.x));
                rd[1] = make_float2(f2tf32f(a.y), f2tf32f(b.y));
                rd[2] = make_float2(f2tf32f(a.z), f2tf32f(b.z));
                rd[3] = make_float2(f2tf32f(a.w), f2tf32f(b.w));
            }
        }
        if (t < 64) cks_s[t] = g_ck[h * S + kj0 + t];
        else if (t < 192) {
            const int mm = t - 64;
            int mg = base + mm;
            if (mg > S - 1) mg = S - 1;
            crs_s[mm] = (mm < 127) ? g_cr[h * S + mg] : 0.f;
        }
        __syncthreads();

        // ---- windowed G = Q @ RSL^T (+cr): 5 tiles per warp ----
        {
            int prow[5];
#pragma unroll
            for (int ni = 0; ni < 5; ni++)
                prow[ni] = ((rbase + (tile0 + ni) * 8 + g) & 127) * KPAD;
            float gc[5][4];
#pragma unroll
            for (int ni = 0; ni < 5; ni++) {
                const int col = (tile0 + ni) * 8 + 2 * tg;
                gc[ni][0] = crs_s[col];
                gc[ni][1] = crs_s[col + 1];
                gc[ni][2] = gc[ni][0];
                gc[ni][3] = gc[ni][1];
            }
#pragma unroll
            for (int k0 = 0; k0 < 8; k0++) {
#pragma unroll
                for (int ni = 0; ni < 5; ni++) {
                    uint2 bb = *(const uint2*)&rsl[prow[ni] + k0 * 8 + 2 * tg];
                    mma_tf32(gc[ni], qa[k0], bb.x, bb.y);
                }
            }
#pragma unroll
            for (int ni = 0; ni < 5; ni++) {
                const int col = (tile0 + ni) * 8 + 2 * tg;
                *(float2*)&G[i0 * GPAD + col]       = make_float2(gc[ni][0], gc[ni][1]);
                *(float2*)&G[(i0 + 8) * GPAD + col] = make_float2(gc[ni][2], gc[ni][3]);
            }
        }
        pair_bar(wp);  // pair's G halves visible before gather

        // ---- AC = Q @ K^T (+ck), own 32-key half ----
        float sc[4][4];
#pragma unroll
        for (int nt = 0; nt < 4; nt++) {
            const int col = jbase + nt * 8 + 2 * tg;
            sc[nt][0] = cks_s[col];
            sc[nt][1] = cks_s[col + 1];
            sc[nt][2] = sc[nt][0];
            sc[nt][3] = sc[nt][1];
        }
#pragma unroll
        for (int k0 = 0; k0 < 8; k0++) {
#pragma unroll
            for (int nt = 0; nt < 4; nt++) {
                uint2 bb = *(const uint2*)&ks[(jbase + nt * 8 + g) * KPAD + k0 * 8 + 2 * tg];
                mma_tf32(sc[nt], qa[k0], bb.x, bb.y);
            }
        }

        // ---- BD gather + mask + own-half row max ----
        const bool diag = (kt == nkt - 1);
        float rmax0 = -1e30f, rmax1 = -1e30f;
#pragma unroll
        for (int nt = 0; nt < 4; nt++) {
            const int j = jbase + nt * 8 + 2 * tg;
            float s00 = (sc[nt][0] + G[i0 * GPAD + 63 + j - i0]) * 0.125f;
            float s01 = (sc[nt][1] + G[i0 * GPAD + 64 + j - i0]) * 0.125f;
            float s10 = (sc[nt][2] + G[(i0 + 8) * GPAD + 55 + j - i0]) * 0.125f;
            float s11 = (sc[nt][3] + G[(i0 + 8) * GPAD + 56 + j - i0]) * 0.125f;
            if (diag) {
                if (kj0 + j     > qi0 + i0)     s00 = -1e30f;
                if (kj0 + j + 1 > qi0 + i0)     s01 = -1e30f;
                if (kj0 + j     > qi0 + i0 + 8) s10 = -1e30f;
                if (kj0 + j + 1 > qi0 + i0 + 8) s11 = -1e30f;
            }
            sc[nt][0] = s00; sc[nt][1] = s01; sc[nt][2] = s10; sc[nt][3] = s11;
            rmax0 = fmaxf(rmax0, fmaxf(s00, s01));
            rmax1 = fmaxf(rmax1, fmaxf(s10, s11));
        }
        rmax0 = fmaxf(rmax0, __shfl_xor_sync(0xffffffffu, rmax0, 1));
        rmax0 = fmaxf(rmax0, __shfl_xor_sync(0xffffffffu, rmax0, 2));
        rmax1 = fmaxf(rmax1, __shfl_xor_sync(0xffffffffu, rmax1, 1));
        rmax1 = fmaxf(rmax1, __shfl_xor_sync(0xffffffffu, rmax1, 2));

        // exchange with partner half (both warps finished gathering at this bar)
        mx[2 * i0 + half]       = rmax0;
        mx[2 * (i0 + 8) + half] = rmax1;
        pair_bar(wp);
        rmax0 = fmaxf(rmax0, mx[2 * i0 + (half ^ 1)]);
        rmax1 = fmaxf(rmax1, mx[2 * (i0 + 8) + (half ^ 1)]);

        const float newm0 = fmaxf(m0, rmax0);
        const float newm1 = fmaxf(m1, rmax1);
        const float a0 = __expf(m0 - newm0);
        const float a1 = __expf(m1 - newm1);
        m0 = newm0; m1 = newm1;

        float psum0 = 0.f, psum1 = 0.f;
#pragma unroll
        for (int nt = 0; nt < 4; nt++) {
            sc[nt][0] = __expf(sc[nt][0] - m0);
            sc[nt][1] = __expf(sc[nt][1] - m0);
            sc[nt][2] = __expf(sc[nt][2] - m1);
            sc[nt][3] = __expf(sc[nt][3] - m1);
            psum0 += sc[nt][0] + sc[nt][1];
            psum1 += sc[nt][2] + sc[nt][3];
        }
        psum0 += __shfl_xor_sync(0xffffffffu, psum0, 1);
        psum0 += __shfl_xor_sync(0xffffffffu, psum0, 2);
        psum1 += __shfl_xor_sync(0xffffffffu, psum1, 1);
        psum1 += __shfl_xor_sync(0xffffffffu, psum1, 2);
        l0 = l0 * a0 + psum0;   // own-half partial sums; merged at the end
        l1 = l1 * a1 + psum1;
#pragma unroll
        for (int nt = 0; nt < 8; nt++) {
            O[nt][0] *= a0; O[nt][1] *= a0;
            O[nt][2] *= a1; O[nt][3] *= a1;
        }

        // ---- store P (tf32) into own rows/cols of G region ----
        float* psb = G;
#pragma unroll
        for (int nt = 0; nt < 4; nt++) {
            const int j = jbase + nt * 8 + 2 * tg;
            *(float2*)&psb[i0 * GPAD + j] =
                make_float2(f2tf32f(sc[nt][0]), f2tf32f(sc[nt][1]));
            *(float2*)&psb[(i0 + 8) * GPAD + j] =
                make_float2(f2tf32f(sc[nt][2]), f2tf32f(sc[nt][3]));
        }
        __syncwarp();  // P rows/cols are warp-private

        // ---- PV (partial over own 32 keys): O += P_half @ V_half ----
#pragma unroll
        for (int kk = 0; kk < 4; kk++) {
            const int k0 = 4 * half + kk;
            u32 pa[4];
            pa[0] = __float_as_uint(psb[i0 * GPAD + k0 * 8 + tg]);
            pa[1] = __float_as_uint(psb[(i0 + 8) * GPAD + k0 * 8 + tg]);
            pa[2] = __float_as_uint(psb[i0 * GPAD + k0 * 8 + tg + 4]);
            pa[3] = __float_as_uint(psb[(i0 + 8) * GPAD + k0 * 8 + tg + 4]);
#pragma unroll
            for (int nt = 0; nt < 8; nt++) {
                u32 b0 = __float_as_uint(vs[(k0 * 8 + tg) * VPAD + nt * 8 + g]);
                u32 b1 = __float_as_uint(vs[(k0 * 8 + tg + 4) * VPAD + nt * 8 + g]);
                mma_tf32(O[nt], pa, b0, b1);
            }
        }
    }

    // ---- merge the two key-halves (same m-sequence -> plain sums) ----
    __syncthreads();
    if (half == 1) {
#pragma unroll
        for (int nt = 0; nt < 8; nt++) {
            const int col = nt * 8 + 2 * tg;
            *(float2*)&G[i0 * GPAD + col]       = make_float2(O[nt][0], O[nt][1]);
            *(float2*)&G[(i0 + 8) * GPAD + col] = make_float2(O[nt][2], O[nt][3]);
        }
        if (tg == 0) {
            cks_s[i0]     = l0;
            cks_s[i0 + 8] = l1;
        }
    }
    __syncthreads();
    if (half == 0) {
        l0 += cks_s[i0];
        l1 += cks_s[i0 + 8];
        const float inv0 = 1.f / l0;
        const float inv1 = 1.f / l1;
#pragma unroll
        for (int nt = 0; nt < 8; nt++) {
            const int col = nt * 8 + 2 * tg;
            float2 p0 = *(const float2*)&G[i0 * GPAD + col];
            float2 p1 = *(const float2*)&G[(i0 + 8) * GPAD + col];
            float o00 = (O[nt][0] + p0.x) * inv0, o01 = (O[nt][1] + p0.y) * inv0;
            float o10 = (O[nt][2] + p1.x) * inv1, o11 = (O[nt][3] + p1.y) * inv1;
            const size_t idx0 = (size_t)(qi0 + i0) * NHD + hb + col;
            const size_t idx1 = (size_t)(qi0 + i0 + 8) * NHD + hb + col;
            __nv_bfloat162 h0 = __floats2bfloat162_rn(o00, o01);
            __nv_bfloat162 h1 = __floats2bfloat162_rn(o10, o11);
            __nv_bfloat162 L0 = __floats2bfloat162_rn(o00 - __bfloat162float(h0.x),
                                                      o01 - __bfloat162float(h0.y));
            __nv_bfloat162 L1 = __floats2bfloat162_rn(o10 - __bfloat162float(h1.x),
                                                      o11 - __bfloat162float(h1.y));
            *(__nv_bfloat162*)&g_at_h[idx0] = h0;
            *(__nv_bfloat162*)&g_at_l[idx0] = L0;
            *(__nv_bfloat162*)&g_at_h[idx1] = h1;
            *(__nv_bfloat162*)&g_at_l[idx1] = L1;
        }
    }
}

// ---------------------------------------------------------------------------
extern "C" void kernel_launch(void* const* d_in, const int* in_sizes, int n_in,
                              void* d_out, int out_size)
{
    const float* inputs_q = (const float*)d_in[0];
    const float* pos_emb  = (const float*)d_in[1];
    const float* r_w_bias = (const float*)d_in[2];
    const float* r_r_bias = (const float*)d_in[3];
    const float* Wq = (const float*)d_in[4];
    const float* bq = (const float*)d_in[5];
    const float* Wk = (const float*)d_in[6];
    const float* bk = (const float*)d_in[7];
    const float* Wv = (const float*)d_in[8];
    const float* bv = (const float*)d_in[9];
    const float* Wr = (const float*)d_in[10];
    const float* br = (const float*)d_in[11];
    const float* Wo = (const float*)d_in[12];
    const float* bo = (const float*)d_in[13];
    float* out = (float*)d_out;

    cudaFuncSetAttribute(attn_kernel,
                         cudaFuncAttributeMaxDynamicSharedMemorySize, SMEM_ATTN);
    cudaFuncSetAttribute(proj_bf_kernel,
                         cudaFuncAttributeMaxDynamicSharedMemorySize, GEMM_SMEM_BYTES);
    cudaFuncSetAttribute(out_bf_kernel,
                         cudaFuncAttributeMaxDynamicSharedMemorySize, GEMM_SMEM_BYTES);

    split_kernel<<<(2 * 524288 + 5 * 262144) / 256, 256>>>(
        inputs_q, pos_emb, Wq, Wk, Wv, Wr, Wo);

    proj_bf_kernel<<<dim3(NHD / 128, S / 128, 4), 256, GEMM_SMEM_BYTES>>>(
        bq, bk, bv, br);

    bias_dots_kernel<<<(2 * H * S * 32) / 256, 256>>>(r_w_bias, r_r_bias);

    attn_kernel<<<dim3(S / 64, H), 256, SMEM_ATTN>>>();

    out_bf_kernel<<<dim3(F / 128, S / 128), 256, GEMM_SMEM_BYTES>>>(bo, out);
}

// round 9
// speedup vs baseline: 5.6382x; 1.0546x over previous
#include <cuda_runtime.h>
#include <cuda_bf16.h>
#include <cuda_fp16.h>

#define S 2048
#define F 1024
#define H 16
#define DH 64
#define NHD 1024  // H*DH

typedef unsigned long long u64;
typedef unsigned int u32;

#define LOG2E 1.4426950408889634f

// ---- tf32 helpers (attention AC/G) ----
__device__ __forceinline__ u32 f2tf32(float x) {
    u32 r;
    asm("cvt.rna.tf32.f32 %0, %1;" : "=r"(r) : "f"(x));
    return r;
}
__device__ __forceinline__ float f2tf32f(float x) {
    return __uint_as_float(f2tf32(x));
}
__device__ __forceinline__ void mma_tf32(float c[4], const u32 a[4], u32 b0, u32 b1) {
    asm volatile(
        "mma.sync.aligned.m16n8k8.row.col.f32.tf32.tf32.f32 "
        "{%0,%1,%2,%3}, {%4,%5,%6,%7}, {%8,%9}, {%0,%1,%2,%3};\n"
        : "+f"(c[0]), "+f"(c[1]), "+f"(c[2]), "+f"(c[3])
        : "r"(a[0]), "r"(a[1]), "r"(a[2]), "r"(a[3]), "r"(b0), "r"(b1));
}

// ---- f16 mma (attention PV) ----
__device__ __forceinline__ void mma_f16(float c[4], const u32 a[4], u32 b0, u32 b1) {
    asm volatile(
        "mma.sync.aligned.m16n8k16.row.col.f32.f16.f16.f32 "
        "{%0,%1,%2,%3}, {%4,%5,%6,%7}, {%8,%9}, {%0,%1,%2,%3};\n"
        : "+f"(c[0]), "+f"(c[1]), "+f"(c[2]), "+f"(c[3])
        : "r"(a[0]), "r"(a[1]), "r"(a[2]), "r"(a[3]), "r"(b0), "r"(b1));
}

// 2^ylo, 2^yhi packed as f16x2 via one MUFU
__device__ __forceinline__ u32 exp2_f16x2(float ylo, float yhi) {
    __half2 h = __floats2half2_rn(ylo, yhi);
    __half2 r = h2exp2(h);
    return *(u32*)&r;
}

// ---- bf16 helpers (GEMMs) ----
__device__ __forceinline__ void mma_bf16(float c[4], const u32 a[4], u32 b0, u32 b1) {
    asm volatile(
        "mma.sync.aligned.m16n8k16.row.col.f32.bf16.bf16.f32 "
        "{%0,%1,%2,%3}, {%4,%5,%6,%7}, {%8,%9}, {%0,%1,%2,%3};\n"
        : "+f"(c[0]), "+f"(c[1]), "+f"(c[2]), "+f"(c[3])
        : "r"(a[0]), "r"(a[1]), "r"(a[2]), "r"(a[3]), "r"(b0), "r"(b1));
}
__device__ __forceinline__ void ldm2t(u32& d0, u32& d1, u32 saddr) {
    asm volatile("ldmatrix.sync.aligned.m8n8.x2.trans.shared.b16 {%0,%1}, [%2];"
                 : "=r"(d0), "=r"(d1) : "r"(saddr));
}
__device__ __forceinline__ u32 sptr(const void* p) {
    return (u32)__cvta_generic_to_shared(p);
}
__device__ __forceinline__ void pair_bar(int wp) {
    asm volatile("bar.sync %0, 64;" :: "r"(1 + wp) : "memory");
}

// Scratch (device globals: allocation-free per harness rules)
__device__ float g_q[S * NHD];
__device__ float g_k[S * NHD];
__device__ float g_v[S * NHD];
__device__ float g_r[S * NHD];
__device__ float g_ck[H * S];
__device__ float g_cr[H * S];
// bf16 hi/lo split panels
__device__ __nv_bfloat16 g_xq_h[S * F],   g_xq_l[S * F];
__device__ __nv_bfloat16 g_xr_h[S * F],   g_xr_l[S * F];
__device__ __nv_bfloat16 g_wh[5 * F * NHD], g_wl[5 * F * NHD];  // Wq,Wk,Wv,Wr,Wo
__device__ __nv_bfloat16 g_at_h[S * NHD], g_at_l[S * NHD];

// ---------------------------------------------------------------------------
// Split fp32 -> (bf16 hi, bf16 lo) for all GEMM operands in ONE launch.
// ---------------------------------------------------------------------------
__global__ __launch_bounds__(256) void split_kernel(
    const float* __restrict__ xq, const float* __restrict__ xr,
    const float* __restrict__ w0, const float* __restrict__ w1,
    const float* __restrict__ w2, const float* __restrict__ w3,
    const float* __restrict__ w4)
{
    const int i = blockIdx.x * 256 + threadIdx.x;
    const float* src;
    __nv_bfloat16 *h, *l;
    int off;
    if (i < 524288)        { src = xq; h = g_xq_h; l = g_xq_l; off = i; }
    else if (i < 1048576)  { src = xr; h = g_xr_h; l = g_xr_l; off = i - 524288; }
    else {
        const int j = i - 1048576;
        const int w = j >> 18;
        off = j & 262143;
        const float* ws[5] = {w0, w1, w2, w3, w4};
        src = ws[w];
        h = g_wh + (size_t)w * (F * NHD);
        l = g_wl + (size_t)w * (F * NHD);
    }
    float4 v = ((const float4*)src)[off];
    __nv_bfloat162 h0 = __floats2bfloat162_rn(v.x, v.y);
    __nv_bfloat162 h1 = __floats2bfloat162_rn(v.z, v.w);
    __nv_bfloat162 l0 = __floats2bfloat162_rn(v.x - __bfloat162float(h0.x),
                                              v.y - __bfloat162float(h0.y));
    __nv_bfloat162 l1 = __floats2bfloat162_rn(v.z - __bfloat162float(h1.x),
                                              v.w - __bfloat162float(h1.y));
    ((__nv_bfloat162*)h)[off * 2]     = h0;
    ((__nv_bfloat162*)h)[off * 2 + 1] = h1;
    ((__nv_bfloat162*)l)[off * 2]     = l0;
    ((__nv_bfloat162*)l)[off * 2 + 1] = l1;
}

// ---------------------------------------------------------------------------
// bf16 split-GEMM (unchanged — known good)
// ---------------------------------------------------------------------------
#define GEMM_SMEM_BYTES 75776

__device__ __forceinline__ void gemm_bf16_body(
    const __nv_bfloat16* __restrict__ Ah, const __nv_bfloat16* __restrict__ Al,
    const __nv_bfloat16* __restrict__ Bh, const __nv_bfloat16* __restrict__ Bl,
    const float* __restrict__ bias, float* __restrict__ C,
    int M, int N, int K)
{
    extern __shared__ __nv_bfloat16 sb[];
    __nv_bfloat16* As_h = sb;
    __nv_bfloat16* As_l = sb + 10240;
    __nv_bfloat16* Bs_h = sb + 20480;
    __nv_bfloat16* Bs_l = sb + 29184;

    const int t    = threadIdx.x;
    const int lane = t & 31;
    const int w    = t >> 5;
    const int wm   = (w & 3) * 32;
    const int wn   = (w >> 2) * 64;
    const int g    = lane >> 2;
    const int tg   = lane & 3;
    const int m0   = blockIdx.y * 128;
    const int n0   = blockIdx.x * 128;

    float Cr[2][8][4];
#pragma unroll
    for (int mt = 0; mt < 2; mt++)
#pragma unroll
        for (int nt = 0; nt < 8; nt++) {
            Cr[mt][nt][0] = 0.f; Cr[mt][nt][1] = 0.f;
            Cr[mt][nt][2] = 0.f; Cr[mt][nt][3] = 0.f;
        }

    const int fm = t >> 1, fh = (t & 1) * 16;
    const int fk = t >> 3, fv = (t & 7) * 16;

    const __nv_bfloat16* gAh = Ah + (size_t)(m0 + fm) * K + fh;
    const __nv_bfloat16* gAl = Al + (size_t)(m0 + fm) * K + fh;
    const __nv_bfloat16* gBh = Bh + (size_t)fk * N + n0 + fv;
    const __nv_bfloat16* gBl = Bl + (size_t)fk * N + n0 + fv;

    {
        uint4 r0 = *(const uint4*)gAh;
        uint4 r1 = *(const uint4*)(gAh + 8);
        uint4 r2 = *(const uint4*)gAl;
        uint4 r3 = *(const uint4*)(gAl + 8);
        uint4 r4 = *(const uint4*)gBh;
        uint4 r5 = *(const uint4*)(gBh + 8);
        uint4 r6 = *(const uint4*)gBl;
        uint4 r7 = *(const uint4*)(gBl + 8);
        __nv_bfloat16* sa = As_h + fm * 40 + fh;
        *(uint4*)sa = r0; *(uint4*)(sa + 8) = r1;
        sa = As_l + fm * 40 + fh;
        *(uint4*)sa = r2; *(uint4*)(sa + 8) = r3;
        __nv_bfloat16* sbp = Bs_h + fk * 136 + fv;
        *(uint4*)sbp = r4; *(uint4*)(sbp + 8) = r5;
        sbp = Bs_l + fk * 136 + fv;
        *(uint4*)sbp = r6; *(uint4*)(sbp + 8) = r7;
    }
    __syncthreads();

    int buf = 0;
    const int nkc = K / 32;
    for (int kc = 0; kc < nkc; kc++) {
        uint4 ra[8];
        const bool has = (kc + 1) < nkc;
        if (has) {
            const __nv_bfloat16* pAh = gAh + (kc + 1) * 32;
            const __nv_bfloat16* pAl = gAl + (kc + 1) * 32;
            const __nv_bfloat16* pBh = gBh + (size_t)(kc + 1) * 32 * N;
            const __nv_bfloat16* pBl = gBl + (size_t)(kc + 1) * 32 * N;
            ra[0] = *(const uint4*)pAh; ra[1] = *(const uint4*)(pAh + 8);
            ra[2] = *(const uint4*)pAl; ra[3] = *(const uint4*)(pAl + 8);
            ra[4] = *(const uint4*)pBh; ra[5] = *(const uint4*)(pBh + 8);
            ra[6] = *(const uint4*)pBl; ra[7] = *(const uint4*)(pBl + 8);
        }
        const __nv_bfloat16* Ab_h = As_h + buf * 5120;
        const __nv_bfloat16* Ab_l = As_l + buf * 5120;
        const __nv_bfloat16* Bb_h = Bs_h + buf * 4352;
        const __nv_bfloat16* Bb_l = Bs_l + buf * 4352;

#pragma unroll
        for (int ks2 = 0; ks2 < 2; ks2++) {
            const int ks = ks2 * 16;
            u32 ah[2][4], al[2][4];
#pragma unroll
            for (int mt = 0; mt < 2; mt++) {
                const __nv_bfloat16* r0 = Ab_h + (wm + mt * 16 + g) * 40 + ks + 2 * tg;
                ah[mt][0] = *(const u32*)r0;
                ah[mt][1] = *(const u32*)(r0 + 8 * 40);
                ah[mt][2] = *(const u32*)(r0 + 8);
                ah[mt][3] = *(const u32*)(r0 + 8 * 40 + 8);
                const __nv_bfloat16* r1 = Ab_l + (wm + mt * 16 + g) * 40 + ks + 2 * tg;
                al[mt][0] = *(const u32*)r1;
                al[mt][1] = *(const u32*)(r1 + 8 * 40);
                al[mt][2] = *(const u32*)(r1 + 8);
                al[mt][3] = *(const u32*)(r1 + 8 * 40 + 8);
            }
            const u32 bbh = sptr(Bb_h + (ks + (lane & 15)) * 136 + wn);
            const u32 bbl = sptr(Bb_l + (ks + (lane & 15)) * 136 + wn);
#pragma unroll
            for (int nt = 0; nt < 8; nt++) {
                u32 bh0, bh1, bl0, bl1;
                ldm2t(bh0, bh1, bbh + nt * 16);
                ldm2t(bl0, bl1, bbl + nt * 16);
#pragma unroll
                for (int mt = 0; mt < 2; mt++) {
                    mma_bf16(Cr[mt][nt], ah[mt], bh0, bh1);
                    mma_bf16(Cr[mt][nt], ah[mt], bl0, bl1);
                    mma_bf16(Cr[mt][nt], al[mt], bh0, bh1);
                }
            }
        }

        if (has) {
            __nv_bfloat16* sa = As_h + (buf ^ 1) * 5120 + fm * 40 + fh;
            *(uint4*)sa = ra[0]; *(uint4*)(sa + 8) = ra[1];
            sa = As_l + (buf ^ 1) * 5120 + fm * 40 + fh;
            *(uint4*)sa = ra[2]; *(uint4*)(sa + 8) = ra[3];
            __nv_bfloat16* sbp = Bs_h + (buf ^ 1) * 4352 + fk * 136 + fv;
            *(uint4*)sbp = ra[4]; *(uint4*)(sbp + 8) = ra[5];
            sbp = Bs_l + (buf ^ 1) * 4352 + fk * 136 + fv;
            *(uint4*)sbp = ra[6]; *(uint4*)(sbp + 8) = ra[7];
            __syncthreads();
            buf ^= 1;
        }
    }

#pragma unroll
    for (int mt = 0; mt < 2; mt++) {
        const int row = m0 + wm + mt * 16 + g;
#pragma unroll
        for (int nt = 0; nt < 8; nt++) {
            const int col = n0 + wn + nt * 8 + 2 * tg;
            float2 b01 = *(const float2*)&bias[col];
            float2 o;
            o.x = Cr[mt][nt][0] + b01.x;
            o.y = Cr[mt][nt][1] + b01.y;
            *(float2*)(C + (size_t)row * N + col) = o;
            o.x = Cr[mt][nt][2] + b01.x;
            o.y = Cr[mt][nt][3] + b01.y;
            *(float2*)(C + (size_t)(row + 8) * N + col) = o;
        }
    }
}

__global__ __launch_bounds__(256) void proj_bf_kernel(
    const float* __restrict__ bq, const float* __restrict__ bk,
    const float* __restrict__ bv, const float* __restrict__ br)
{
    const int z = blockIdx.z;
    const __nv_bfloat16* Ah = (z < 3) ? g_xq_h : g_xr_h;
    const __nv_bfloat16* Al = (z < 3) ? g_xq_l : g_xr_l;
    const __nv_bfloat16* Bh = g_wh + (size_t)z * (F * NHD);
    const __nv_bfloat16* Bl = g_wl + (size_t)z * (F * NHD);
    const float* bias;
    float* C;
    switch (z) {
        case 0:  bias = bq; C = g_q; break;
        case 1:  bias = bk; C = g_k; break;
        case 2:  bias = bv; C = g_v; break;
        default: bias = br; C = g_r; break;
    }
    gemm_bf16_body(Ah, Al, Bh, Bl, bias, C, S, NHD, F);
}

__global__ __launch_bounds__(256) void out_bf_kernel(
    const float* __restrict__ bo, float* __restrict__ out)
{
    gemm_bf16_body(g_at_h, g_at_l,
                   g_wh + (size_t)4 * (F * NHD), g_wl + (size_t)4 * (F * NHD),
                   bo, out, S, F, NHD);
}

// ---------------------------------------------------------------------------
// ck[h][j] = rw[h].k[j,h,:],  cr[h][m] = rr[h].r[m,h,:]
// ---------------------------------------------------------------------------
__global__ __launch_bounds__(256) void bias_dots_kernel(
    const float* __restrict__ rwb, const float* __restrict__ rrb)
{
    const int gw   = (blockIdx.x * blockDim.x + threadIdx.x) >> 5;
    const int lane = threadIdx.x & 31;
    const int which = gw >= H * S;
    const int idx   = which ? gw - H * S : gw;
    const int hh = idx >> 11;
    const int j  = idx & (S - 1);
    const float* bias = which ? rrb : rwb;
    const float* mat  = which ? g_r : g_k;
    const float b0 = bias[hh * DH + lane];
    const float b1 = bias[hh * DH + 32 + lane];
    const float* row = mat + (size_t)j * NHD + hh * DH;
    float s = fmaf(b0, row[lane], b1 * row[32 + lane]);
#pragma unroll
    for (int off = 16; off > 0; off >>= 1)
        s += __shfl_xor_sync(0xffffffffu, s, off);
    if (lane == 0) {
        float* dst = which ? g_cr : g_ck;
        dst[hh * S + j] = s;
    }
}

// ---------------------------------------------------------------------------
// Causal flash attention. AC/G on tf32 mma (unchanged). R9:
//  - score exps via ex2.approx.f16x2 (MUFU halved); P stays packed fp16
//  - PV on f16 m16n8k16 (half the MMAs), V tile fp16 + ones column
//  - l = row-sum(P) computed by the PV MMA (9th n-tile), psum/shfl deleted
// P lives in the first 128B of each G row (f32 cols 0..31); cross-half
// gather of those columns is ordered by the mx pair_bar before P stores.
// ---------------------------------------------------------------------------
#define KPAD 72
#define VP16 72   // f16 pitch for V tile (64 d + ones col + pad)
#define GPAD 132
#define PP16 (GPAD * 2)  // P f16 pitch inside G rows
#define SMEM_ATTN ((64*KPAD)*4 + 64*VP16*2 + (128*KPAD)*4 + (64*GPAD)*4 + (128+64+128)*4)

__global__ __launch_bounds__(256, 2) void attn_kernel()
{
    const int h   = blockIdx.y;
    const int qi0 = (gridDim.x - 1 - blockIdx.x) * 64;

    extern __shared__ float sm[];
    float*  ks    = sm;                               // 64 x KPAD f32 (perm d)
    __half* vs16  = (__half*)(ks + 64 * KPAD);        // 64 x VP16 f16
    float*  rsl   = (float*)(vs16 + 64 * VP16);       // 128 x KPAD f32 (perm, circular)
    float*  G     = rsl + 128 * KPAD;                 // 64 x GPAD f32; P (f16) reuses rows
    float*  crs_s = G + 64 * GPAD;                    // 128
    float*  cks_s = crs_s + 128;                      // 64
    float*  mx    = cks_s + 64;                       // 128

    const int t    = threadIdx.x;
    const int lane = t & 31;
    const int w    = t >> 5;
    const int wp   = w & 3;            // q-row group
    const int half = w >> 2;           // key-column half
    const int g    = lane >> 2;
    const int tg   = lane & 3;
    const int i0   = wp * 16 + g;
    const int hb   = h * DH;
    const int jbase = half * 32;
    const int tile0 = (half == 0) ? (6 - 2 * wp) : (11 - 2 * wp);

    u32 qa[8][4];
    {
        const float* q0 = &g_q[(size_t)(qi0 + i0) * NHD + hb];
        const float* q1 = q0 + 8 * NHD;
#pragma unroll
        for (int k0 = 0; k0 < 8; k0++) {
            qa[k0][0] = f2tf32(q0[k0 * 8 + tg]);
            qa[k0][1] = f2tf32(q1[k0 * 8 + tg]);
            qa[k0][2] = f2tf32(q0[k0 * 8 + tg + 4]);
            qa[k0][3] = f2tf32(q1[k0 * 8 + tg + 4]);
        }
    }

    float O[9][4];   // [8] = l column (V ones col)
#pragma unroll
    for (int nt = 0; nt < 9; nt++) {
        O[nt][0] = 0.f; O[nt][1] = 0.f; O[nt][2] = 0.f; O[nt][3] = 0.f;
    }
    float m0 = -1e30f, m1 = -1e30f;

    const int nkt = qi0 / 64 + 1;
    for (int kt = 0; kt < nkt; kt++) {
        const int kj0   = kt * 64;
        const int base  = (S - 1) + kj0 - qi0 - 63;
        const int rbase = base & 127;
        __syncthreads();  // all consumers done before refill

        // ---- K (perm f32/tf32) + V (f16 + ones col) fills ----
#pragma unroll
        for (int it = 0; it < 2; it++) {
            const int idx = t + it * 256;
            const int r = idx >> 3, m8 = (idx & 7) << 3;
            const float* kp = &g_k[(size_t)(kj0 + r) * NHD + hb + m8];
            const float* vp = &g_v[(size_t)(kj0 + r) * NHD + hb + m8];
            float4 ka = *(const float4*)kp;
            float4 kb = *(const float4*)(kp + 4);
            float4 va = *(const float4*)vp;
            float4 vb = *(const float4*)(vp + 4);
            float2* kd = (float2*)&ks[r * KPAD + m8];
            kd[0] = make_float2(f2tf32f(ka.x), f2tf32f(kb.x));
            kd[1] = make_float2(f2tf32f(ka.y), f2tf32f(kb.y));
            kd[2] = make_float2(f2tf32f(ka.z), f2tf32f(kb.z));
            kd[3] = make_float2(f2tf32f(ka.w), f2tf32f(kb.w));
            __half2 h0 = __floats2half2_rn(va.x, va.y);
            __half2 h1 = __floats2half2_rn(va.z, va.w);
            __half2 h2 = __floats2half2_rn(vb.x, vb.y);
            __half2 h3 = __floats2half2_rn(vb.z, vb.w);
            uint4 pk;
            pk.x = *(u32*)&h0; pk.y = *(u32*)&h1;
            pk.z = *(u32*)&h2; pk.w = *(u32*)&h3;
            *(uint4*)&vs16[r * VP16 + m8] = pk;
        }
        if (t < 64) {
            __half2 one0 = __floats2half2_rn(1.f, 0.f);
            __half2 zz   = __floats2half2_rn(0.f, 0.f);
            uint4 pk;
            pk.x = *(u32*)&one0;
            pk.y = pk.z = pk.w = *(u32*)&zz;
            *(uint4*)&vs16[t * VP16 + 64] = pk;
        }
        // ---- RSL (perm, circular): only new rows ----
        {
            const int rl0 = (kt == 0) ? 0 : 64;
            const int nit = (kt == 0) ? 4 : 2;
            for (int it = 0; it < nit; it++) {
                const int idx = t + it * 256;
                const int row = rl0 + (idx >> 3);
                const int m8  = (idx & 7) << 3;
                int mg = base + row;
                if (mg > S - 1) mg = S - 1;
                const float* rp = &g_r[(size_t)mg * NHD + hb + m8];
                float4 a = *(const float4*)rp;
                float4 b = *(const float4*)(rp + 4);
                float2* rd = (float2*)&rsl[((rbase + row) & 127) * KPAD + m8];
                rd[0] = make_float2(f2tf32f(a.x), f2tf32f(b.x));
                rd[1] = make_float2(f2tf32f(a.y), f2tf32f(b.y));
                rd[2] = make_float2(f2tf32f(a.z), f2tf32f(b.z));
                rd[3] = make_float2(f2tf32f(a.w), f2tf32f(b.w));
            }
        }
        if (t < 64) cks_s[t] = g_ck[h * S + kj0 + t];
        else if (t < 192) {
            const int mm = t - 64;
            int mg = base + mm;
            if (mg > S - 1) mg = S - 1;
            crs_s[mm] = (mm < 127) ? g_cr[h * S + mg] : 0.f;
        }
        __syncthreads();

        // ---- windowed G = Q @ RSL^T (+cr): 5 tiles per warp ----
        {
            int prow[5];
#pragma unroll
            for (int ni = 0; ni < 5; ni++)
                prow[ni] = ((rbase + (tile0 + ni) * 8 + g) & 127) * KPAD;
            float gc[5][4];
#pragma unroll
            for (int ni = 0; ni < 5; ni++) {
                const int col = (tile0 + ni) * 8 + 2 * tg;
                gc[ni][0] = crs_s[col];
                gc[ni][1] = crs_s[col + 1];
                gc[ni][2] = gc[ni][0];
                gc[ni][3] = gc[ni][1];
            }
#pragma unroll
            for (int k0 = 0; k0 < 8; k0++) {
#pragma unroll
                for (int ni = 0; ni < 5; ni++) {
                    uint2 bb = *(const uint2*)&rsl[prow[ni] + k0 * 8 + 2 * tg];
                    mma_tf32(gc[ni], qa[k0], bb.x, bb.y);
                }
            }
#pragma unroll
            for (int ni = 0; ni < 5; ni++) {
                const int col = (tile0 + ni) * 8 + 2 * tg;
                *(float2*)&G[i0 * GPAD + col]       = make_float2(gc[ni][0], gc[ni][1]);
                *(float2*)&G[(i0 + 8) * GPAD + col] = make_float2(gc[ni][2], gc[ni][3]);
            }
        }
        pair_bar(wp);  // pair's G halves visible before gather

        // ---- AC = Q @ K^T (+ck), own 32-key half ----
        float sc[4][4];
#pragma unroll
        for (int nt = 0; nt < 4; nt++) {
            const int col = jbase + nt * 8 + 2 * tg;
            sc[nt][0] = cks_s[col];
            sc[nt][1] = cks_s[col + 1];
            sc[nt][2] = sc[nt][0];
            sc[nt][3] = sc[nt][1];
        }
#pragma unroll
        for (int k0 = 0; k0 < 8; k0++) {
#pragma unroll
            for (int nt = 0; nt < 4; nt++) {
                uint2 bb = *(const uint2*)&ks[(jbase + nt * 8 + g) * KPAD + k0 * 8 + 2 * tg];
                mma_tf32(sc[nt], qa[k0], bb.x, bb.y);
            }
        }

        // ---- BD gather + mask + own-half row max ----
        const bool diag = (kt == nkt - 1);
        float rmax0 = -1e30f, rmax1 = -1e30f;
#pragma unroll
        for (int nt = 0; nt < 4; nt++) {
            const int j = jbase + nt * 8 + 2 * tg;
            float s00 = (sc[nt][0] + G[i0 * GPAD + 63 + j - i0]) * 0.125f;
            float s01 = (sc[nt][1] + G[i0 * GPAD + 64 + j - i0]) * 0.125f;
            float s10 = (sc[nt][2] + G[(i0 + 8) * GPAD + 55 + j - i0]) * 0.125f;
            float s11 = (sc[nt][3] + G[(i0 + 8) * GPAD + 56 + j - i0]) * 0.125f;
            if (diag) {
                if (kj0 + j     > qi0 + i0)     s00 = -1e30f;
                if (kj0 + j + 1 > qi0 + i0)     s01 = -1e30f;
                if (kj0 + j     > qi0 + i0 + 8) s10 = -1e30f;
                if (kj0 + j + 1 > qi0 + i0 + 8) s11 = -1e30f;
            }
            sc[nt][0] = s00; sc[nt][1] = s01; sc[nt][2] = s10; sc[nt][3] = s11;
            rmax0 = fmaxf(rmax0, fmaxf(s00, s01));
            rmax1 = fmaxf(rmax1, fmaxf(s10, s11));
        }
        rmax0 = fmaxf(rmax0, __shfl_xor_sync(0xffffffffu, rmax0, 1));
        rmax0 = fmaxf(rmax0, __shfl_xor_sync(0xffffffffu, rmax0, 2));
        rmax1 = fmaxf(rmax1, __shfl_xor_sync(0xffffffffu, rmax1, 1));
        rmax1 = fmaxf(rmax1, __shfl_xor_sync(0xffffffffu, rmax1, 2));

        // exchange with partner half (also orders partner gather before P stores)
        mx[2 * i0 + half]       = rmax0;
        mx[2 * (i0 + 8) + half] = rmax1;
        pair_bar(wp);
        rmax0 = fmaxf(rmax0, mx[2 * i0 + (half ^ 1)]);
        rmax1 = fmaxf(rmax1, mx[2 * (i0 + 8) + (half ^ 1)]);

        const float newm0 = fmaxf(m0, rmax0);
        const float newm1 = fmaxf(m1, rmax1);
        const float a0 = __expf(m0 - newm0);
        const float a1 = __expf(m1 - newm1);
        m0 = newm0; m1 = newm1;
#pragma unroll
        for (int nt = 0; nt < 9; nt++) {
            O[nt][0] *= a0; O[nt][1] *= a0;
            O[nt][2] *= a1; O[nt][3] *= a1;
        }

        // ---- exp (f16x2 MUFU) + store packed-f16 P into own G-row bytes ----
        __half* psb16 = (__half*)G;
        const float negm0 = -m0 * LOG2E;
        const float negm1 = -m1 * LOG2E;
#pragma unroll
        for (int nt = 0; nt < 4; nt++) {
            const int col = jbase + nt * 8 + 2 * tg;
            u32 p01 = exp2_f16x2(fmaf(sc[nt][0], LOG2E, negm0),
                                 fmaf(sc[nt][1], LOG2E, negm0));
            u32 p23 = exp2_f16x2(fmaf(sc[nt][2], LOG2E, negm1),
                                 fmaf(sc[nt][3], LOG2E, negm1));
            *(u32*)&psb16[i0 * PP16 + col]       = p01;
            *(u32*)&psb16[(i0 + 8) * PP16 + col] = p23;
        }
        __syncwarp();  // P rows/cols are warp-private

        // ---- PV (f16 k16): O += P_half @ [V | 1], l rides in n-tile 8 ----
#pragma unroll
        for (int ki = 0; ki < 2; ki++) {
            const int kb = jbase + ki * 16;
            u32 pa[4];
            pa[0] = *(const u32*)&psb16[i0 * PP16 + kb + 2 * tg];
            pa[1] = *(const u32*)&psb16[(i0 + 8) * PP16 + kb + 2 * tg];
            pa[2] = *(const u32*)&psb16[i0 * PP16 + kb + 8 + 2 * tg];
            pa[3] = *(const u32*)&psb16[(i0 + 8) * PP16 + kb + 8 + 2 * tg];
            const u32 vb = sptr(vs16 + (size_t)(kb + (lane & 15)) * VP16);
#pragma unroll
            for (int nt = 0; nt < 9; nt++) {
                u32 b0, b1;
                ldm2t(b0, b1, vb + nt * 16);
                mma_f16(O[nt], pa, b0, b1);
            }
        }
    }

    // ---- extract l (ones-column accumulator, tg==0 lanes own it) ----
    float l0 = __shfl_sync(0xffffffffu, O[8][0], lane & 28);
    float l1 = __shfl_sync(0xffffffffu, O[8][2], lane & 28);

    // ---- merge the two key-halves (same m-sequence -> plain sums) ----
    __syncthreads();
    if (half == 1) {
#pragma unroll
        for (int nt = 0; nt < 8; nt++) {
            const int col = nt * 8 + 2 * tg;
            *(float2*)&G[i0 * GPAD + col]       = make_float2(O[nt][0], O[nt][1]);
            *(float2*)&G[(i0 + 8) * GPAD + col] = make_float2(O[nt][2], O[nt][3]);
        }
        if (tg == 0) {
            cks_s[i0]     = l0;
            cks_s[i0 + 8] = l1;
        }
    }
    __syncthreads();
    if (half == 0) {
        l0 += cks_s[i0];
        l1 += cks_s[i0 + 8];
        const float inv0 = 1.f / l0;
        const float inv1 = 1.f / l1;
#pragma unroll
        for (int nt = 0; nt < 8; nt++) {
            const int col = nt * 8 + 2 * tg;
            float2 p0 = *(const float2*)&G[i0 * GPAD + col];
            float2 p1 = *(const float2*)&G[(i0 + 8) * GPAD + col];
            float o00 = (O[nt][0] + p0.x) * inv0, o01 = (O[nt][1] + p0.y) * inv0;
            float o10 = (O[nt][2] + p1.x) * inv1, o11 = (O[nt][3] + p1.y) * inv1;
            const size_t idx0 = (size_t)(qi0 + i0) * NHD + hb + col;
            const size_t idx1 = (size_t)(qi0 + i0 + 8) * NHD + hb + col;
            __nv_bfloat162 h0 = __floats2bfloat162_rn(o00, o01);
            __nv_bfloat162 h1 = __floats2bfloat162_rn(o10, o11);
            __nv_bfloat162 L0 = __floats2bfloat162_rn(o00 - __bfloat162float(h0.x),
                                                      o01 - __bfloat162float(h0.y));
            __nv_bfloat162 L1 = __floats2bfloat162_rn(o10 - __bfloat162float(h1.x),
                                                      o11 - __bfloat162float(h1.y));
            *(__nv_bfloat162*)&g_at_h[idx0] = h0;
            *(__nv_bfloat162*)&g_at_l[idx0] = L0;
            *(__nv_bfloat162*)&g_at_h[idx1] = h1;
            *(__nv_bfloat162*)&g_at_l[idx1] = L1;
        }
    }
}

// ---------------------------------------------------------------------------
extern "C" void kernel_launch(void* const* d_in, const int* in_sizes, int n_in,
                              void* d_out, int out_size)
{
    const float* inputs_q = (const float*)d_in[0];
    const float* pos_emb  = (const float*)d_in[1];
    const float* r_w_bias = (const float*)d_in[2];
    const float* r_r_bias = (const float*)d_in[3];
    const float* Wq = (const float*)d_in[4];
    const float* bq = (const float*)d_in[5];
    const float* Wk = (const float*)d_in[6];
    const float* bk = (const float*)d_in[7];
    const float* Wv = (const float*)d_in[8];
    const float* bv = (const float*)d_in[9];
    const float* Wr = (const float*)d_in[10];
    const float* br = (const float*)d_in[11];
    const float* Wo = (const float*)d_in[12];
    const float* bo = (const float*)d_in[13];
    float* out = (float*)d_out;

    cudaFuncSetAttribute(attn_kernel,
                         cudaFuncAttributeMaxDynamicSharedMemorySize, SMEM_ATTN);
    cudaFuncSetAttribute(proj_bf_kernel,
                         cudaFuncAttributeMaxDynamicSharedMemorySize, GEMM_SMEM_BYTES);
    cudaFuncSetAttribute(out_bf_kernel,
                         cudaFuncAttributeMaxDynamicSharedMemorySize, GEMM_SMEM_BYTES);

    split_kernel<<<(2 * 524288 + 5 * 262144) / 256, 256>>>(
        inputs_q, pos_emb, Wq, Wk, Wv, Wr, Wo);

    proj_bf_kernel<<<dim3(NHD / 128, S / 128, 4), 256, GEMM_SMEM_BYTES>>>(
        bq, bk, bv, br);

    bias_dots_kernel<<<(2 * H * S * 32) / 256, 256>>>(r_w_bias, r_r_bias);

    attn_kernel<<<dim3(S / 64, H), 256, SMEM_ATTN>>>();

    out_bf_kernel<<<dim3(F / 128, S / 128), 256, GEMM_SMEM_BYTES>>>(bo, out);
}

// round 10
// speedup vs baseline: 6.2254x; 1.1041x over previous
#include <cuda_runtime.h>
#include <cuda_bf16.h>
#include <cuda_fp16.h>

#define S 2048
#define F 1024
#define H 16
#define DH 64
#define NHD 1024  // H*DH

typedef unsigned long long u64;
typedef unsigned int u32;

#define LOG2E 1.4426950408889634f

// ---- tf32 helpers (attention AC/G) ----
__device__ __forceinline__ u32 f2tf32(float x) {
    u32 r;
    asm("cvt.rna.tf32.f32 %0, %1;" : "=r"(r) : "f"(x));
    return r;
}
__device__ __forceinline__ void mma_tf32(float c[4], const u32 a[4], u32 b0, u32 b1) {
    asm volatile(
        "mma.sync.aligned.m16n8k8.row.col.f32.tf32.tf32.f32 "
        "{%0,%1,%2,%3}, {%4,%5,%6,%7}, {%8,%9}, {%0,%1,%2,%3};\n"
        : "+f"(c[0]), "+f"(c[1]), "+f"(c[2]), "+f"(c[3])
        : "r"(a[0]), "r"(a[1]), "r"(a[2]), "r"(a[3]), "r"(b0), "r"(b1));
}

// ---- f16 mma (attention PV) ----
__device__ __forceinline__ void mma_f16(float c[4], const u32 a[4], u32 b0, u32 b1) {
    asm volatile(
        "mma.sync.aligned.m16n8k16.row.col.f32.f16.f16.f32 "
        "{%0,%1,%2,%3}, {%4,%5,%6,%7}, {%8,%9}, {%0,%1,%2,%3};\n"
        : "+f"(c[0]), "+f"(c[1]), "+f"(c[2]), "+f"(c[3])
        : "r"(a[0]), "r"(a[1]), "r"(a[2]), "r"(a[3]), "r"(b0), "r"(b1));
}

__device__ __forceinline__ u32 exp2_f16x2(float ylo, float yhi) {
    __half2 h = __floats2half2_rn(ylo, yhi);
    __half2 r = h2exp2(h);
    return *(u32*)&r;
}

// ---- bf16 helpers (GEMMs) ----
__device__ __forceinline__ void mma_bf16(float c[4], const u32 a[4], u32 b0, u32 b1) {
    asm volatile(
        "mma.sync.aligned.m16n8k16.row.col.f32.bf16.bf16.f32 "
        "{%0,%1,%2,%3}, {%4,%5,%6,%7}, {%8,%9}, {%0,%1,%2,%3};\n"
        : "+f"(c[0]), "+f"(c[1]), "+f"(c[2]), "+f"(c[3])
        : "r"(a[0]), "r"(a[1]), "r"(a[2]), "r"(a[3]), "r"(b0), "r"(b1));
}
__device__ __forceinline__ void ldm2t(u32& d0, u32& d1, u32 saddr) {
    asm volatile("ldmatrix.sync.aligned.m8n8.x2.trans.shared.b16 {%0,%1}, [%2];"
                 : "=r"(d0), "=r"(d1) : "r"(saddr));
}
__device__ __forceinline__ u32 sptr(const void* p) {
    return (u32)__cvta_generic_to_shared(p);
}
__device__ __forceinline__ void pair_bar(int wp) {
    asm volatile("bar.sync %0, 64;" :: "r"(1 + wp) : "memory");
}
// ---- cp.async (global -> shared, 16B) ----
__device__ __forceinline__ void cpa16(u32 dst, const void* src) {
    asm volatile("cp.async.ca.shared.global [%0], [%1], 16;"
                 :: "r"(dst), "l"(src) : "memory");
}
#define CP_COMMIT() asm volatile("cp.async.commit_group;" ::: "memory")
#define CP_WAIT0()  asm volatile("cp.async.wait_group 0;" ::: "memory")

// Scratch (device globals: allocation-free per harness rules)
__device__ float g_q[S * NHD];
__device__ float g_k[S * NHD];
__device__ float g_v[S * NHD];
__device__ float g_r[S * NHD];
__device__ float g_ck[H * S];
__device__ float g_cr[H * S];
// bf16 hi/lo split panels
__device__ __nv_bfloat16 g_xq_h[S * F],   g_xq_l[S * F];
__device__ __nv_bfloat16 g_xr_h[S * F],   g_xr_l[S * F];
__device__ __nv_bfloat16 g_wh[5 * F * NHD], g_wl[5 * F * NHD];  // Wq,Wk,Wv,Wr,Wo
__device__ __nv_bfloat16 g_at_h[S * NHD], g_at_l[S * NHD];

// ---------------------------------------------------------------------------
// Split fp32 -> (bf16 hi, bf16 lo) for all GEMM operands in ONE launch.
// ---------------------------------------------------------------------------
__global__ __launch_bounds__(256) void split_kernel(
    const float* __restrict__ xq, const float* __restrict__ xr,
    const float* __restrict__ w0, const float* __restrict__ w1,
    const float* __restrict__ w2, const float* __restrict__ w3,
    const float* __restrict__ w4)
{
    const int i = blockIdx.x * 256 + threadIdx.x;
    const float* src;
    __nv_bfloat16 *h, *l;
    int off;
    if (i < 524288)        { src = xq; h = g_xq_h; l = g_xq_l; off = i; }
    else if (i < 1048576)  { src = xr; h = g_xr_h; l = g_xr_l; off = i - 524288; }
    else {
        const int j = i - 1048576;
        const int w = j >> 18;
        off = j & 262143;
        const float* ws[5] = {w0, w1, w2, w3, w4};
        src = ws[w];
        h = g_wh + (size_t)w * (F * NHD);
        l = g_wl + (size_t)w * (F * NHD);
    }
    float4 v = ((const float4*)src)[off];
    __nv_bfloat162 h0 = __floats2bfloat162_rn(v.x, v.y);
    __nv_bfloat162 h1 = __floats2bfloat162_rn(v.z, v.w);
    __nv_bfloat162 l0 = __floats2bfloat162_rn(v.x - __bfloat162float(h0.x),
                                              v.y - __bfloat162float(h0.y));
    __nv_bfloat162 l1 = __floats2bfloat162_rn(v.z - __bfloat162float(h1.x),
                                              v.w - __bfloat162float(h1.y));
    ((__nv_bfloat162*)h)[off * 2]     = h0;
    ((__nv_bfloat162*)h)[off * 2 + 1] = h1;
    ((__nv_bfloat162*)l)[off * 2]     = l0;
    ((__nv_bfloat162*)l)[off * 2 + 1] = l1;
}

// ---------------------------------------------------------------------------
// bf16 split-GEMM, R10: cp.async fills (no register staging) -> occ 2
// ---------------------------------------------------------------------------
#define GEMM_SMEM_BYTES 75776

__device__ __forceinline__ void gemm_bf16_body(
    const __nv_bfloat16* __restrict__ Ah, const __nv_bfloat16* __restrict__ Al,
    const __nv_bfloat16* __restrict__ Bh, const __nv_bfloat16* __restrict__ Bl,
    const float* __restrict__ bias, float* __restrict__ C,
    int M, int N, int K)
{
    extern __shared__ __nv_bfloat16 sb[];
    __nv_bfloat16* As_h = sb;
    __nv_bfloat16* As_l = sb + 10240;
    __nv_bfloat16* Bs_h = sb + 20480;
    __nv_bfloat16* Bs_l = sb + 29184;

    const int t    = threadIdx.x;
    const int lane = t & 31;
    const int w    = t >> 5;
    const int wm   = (w & 3) * 32;
    const int wn   = (w >> 2) * 64;
    const int g    = lane >> 2;
    const int tg   = lane & 3;
    const int m0   = blockIdx.y * 128;
    const int n0   = blockIdx.x * 128;

    float Cr[2][8][4];
#pragma unroll
    for (int mt = 0; mt < 2; mt++)
#pragma unroll
        for (int nt = 0; nt < 8; nt++) {
            Cr[mt][nt][0] = 0.f; Cr[mt][nt][1] = 0.f;
            Cr[mt][nt][2] = 0.f; Cr[mt][nt][3] = 0.f;
        }

    const int fm = t >> 1, fh = (t & 1) * 16;
    const int fk = t >> 3, fv = (t & 7) * 16;

    const __nv_bfloat16* gAh = Ah + (size_t)(m0 + fm) * K + fh;
    const __nv_bfloat16* gAl = Al + (size_t)(m0 + fm) * K + fh;
    const __nv_bfloat16* gBh = Bh + (size_t)fk * N + n0 + fv;
    const __nv_bfloat16* gBl = Bl + (size_t)fk * N + n0 + fv;

    // per-thread smem fill bases (bf16 offsets)
    const int sa_off = fm * 40 + fh;
    const int sb_off = fk * 136 + fv;

    // preload chunk 0 into buf 0 (async)
    {
        u32 d;
        d = sptr(As_h + sa_off); cpa16(d, gAh); cpa16(d + 16, gAh + 8);
        d = sptr(As_l + sa_off); cpa16(d, gAl); cpa16(d + 16, gAl + 8);
        d = sptr(Bs_h + sb_off); cpa16(d, gBh); cpa16(d + 16, gBh + 8);
        d = sptr(Bs_l + sb_off); cpa16(d, gBl); cpa16(d + 16, gBl + 8);
        CP_COMMIT();
        CP_WAIT0();
    }
    __syncthreads();

    int buf = 0;
    const int nkc = K / 32;
    for (int kc = 0; kc < nkc; kc++) {
        const bool has = (kc + 1) < nkc;
        if (has) {
            const __nv_bfloat16* pAh = gAh + (kc + 1) * 32;
            const __nv_bfloat16* pAl = gAl + (kc + 1) * 32;
            const __nv_bfloat16* pBh = gBh + (size_t)(kc + 1) * 32 * N;
            const __nv_bfloat16* pBl = gBl + (size_t)(kc + 1) * 32 * N;
            const int nb = buf ^ 1;
            u32 d;
            d = sptr(As_h + nb * 5120 + sa_off); cpa16(d, pAh); cpa16(d + 16, pAh + 8);
            d = sptr(As_l + nb * 5120 + sa_off); cpa16(d, pAl); cpa16(d + 16, pAl + 8);
            d = sptr(Bs_h + nb * 4352 + sb_off); cpa16(d, pBh); cpa16(d + 16, pBh + 8);
            d = sptr(Bs_l + nb * 4352 + sb_off); cpa16(d, pBl); cpa16(d + 16, pBl + 8);
            CP_COMMIT();
        }
        const __nv_bfloat16* Ab_h = As_h + buf * 5120;
        const __nv_bfloat16* Ab_l = As_l + buf * 5120;
        const __nv_bfloat16* Bb_h = Bs_h + buf * 4352;
        const __nv_bfloat16* Bb_l = Bs_l + buf * 4352;

#pragma unroll
        for (int ks2 = 0; ks2 < 2; ks2++) {
            const int ks = ks2 * 16;
            u32 ah[2][4], al[2][4];
#pragma unroll
            for (int mt = 0; mt < 2; mt++) {
                const __nv_bfloat16* r0 = Ab_h + (wm + mt * 16 + g) * 40 + ks + 2 * tg;
                ah[mt][0] = *(const u32*)r0;
                ah[mt][1] = *(const u32*)(r0 + 8 * 40);
                ah[mt][2] = *(const u32*)(r0 + 8);
                ah[mt][3] = *(const u32*)(r0 + 8 * 40 + 8);
                const __nv_bfloat16* r1 = Ab_l + (wm + mt * 16 + g) * 40 + ks + 2 * tg;
                al[mt][0] = *(const u32*)r1;
                al[mt][1] = *(const u32*)(r1 + 8 * 40);
                al[mt][2] = *(const u32*)(r1 + 8);
                al[mt][3] = *(const u32*)(r1 + 8 * 40 + 8);
            }
            const u32 bbh = sptr(Bb_h + (ks + (lane & 15)) * 136 + wn);
            const u32 bbl = sptr(Bb_l + (ks + (lane & 15)) * 136 + wn);
#pragma unroll
            for (int nt = 0; nt < 8; nt++) {
                u32 bh0, bh1, bl0, bl1;
                ldm2t(bh0, bh1, bbh + nt * 16);
                ldm2t(bl0, bl1, bbl + nt * 16);
#pragma unroll
                for (int mt = 0; mt < 2; mt++) {
                    mma_bf16(Cr[mt][nt], ah[mt], bh0, bh1);
                    mma_bf16(Cr[mt][nt], ah[mt], bl0, bl1);
                    mma_bf16(Cr[mt][nt], al[mt], bh0, bh1);
                }
            }
        }

        if (has) {
            CP_WAIT0();
            __syncthreads();
            buf ^= 1;
        }
    }

#pragma unroll
    for (int mt = 0; mt < 2; mt++) {
        const int row = m0 + wm + mt * 16 + g;
#pragma unroll
        for (int nt = 0; nt < 8; nt++) {
            const int col = n0 + wn + nt * 8 + 2 * tg;
            float2 b01 = *(const float2*)&bias[col];
            float2 o;
            o.x = Cr[mt][nt][0] + b01.x;
            o.y = Cr[mt][nt][1] + b01.y;
            *(float2*)(C + (size_t)row * N + col) = o;
            o.x = Cr[mt][nt][2] + b01.x;
            o.y = Cr[mt][nt][3] + b01.y;
            *(float2*)(C + (size_t)(row + 8) * N + col) = o;
        }
    }
}

__global__ __launch_bounds__(256, 2) void proj_bf_kernel(
    const float* __restrict__ bq, const float* __restrict__ bk,
    const float* __restrict__ bv, const float* __restrict__ br)
{
    const int z = blockIdx.z;
    const __nv_bfloat16* Ah = (z < 3) ? g_xq_h : g_xr_h;
    const __nv_bfloat16* Al = (z < 3) ? g_xq_l : g_xr_l;
    const __nv_bfloat16* Bh = g_wh + (size_t)z * (F * NHD);
    const __nv_bfloat16* Bl = g_wl + (size_t)z * (F * NHD);
    const float* bias;
    float* C;
    switch (z) {
        case 0:  bias = bq; C = g_q; break;
        case 1:  bias = bk; C = g_k; break;
        case 2:  bias = bv; C = g_v; break;
        default: bias = br; C = g_r; break;
    }
    gemm_bf16_body(Ah, Al, Bh, Bl, bias, C, S, NHD, F);
}

__global__ __launch_bounds__(256, 2) void out_bf_kernel(
    const float* __restrict__ bo, float* __restrict__ out)
{
    gemm_bf16_body(g_at_h, g_at_l,
                   g_wh + (size_t)4 * (F * NHD), g_wl + (size_t)4 * (F * NHD),
                   bo, out, S, F, NHD);
}

// ---------------------------------------------------------------------------
// ck[h][j] = rw[h].k[j,h,:],  cr[h][m] = rr[h].r[m,h,:]
// ---------------------------------------------------------------------------
__global__ __launch_bounds__(256) void bias_dots_kernel(
    const float* __restrict__ rwb, const float* __restrict__ rrb)
{
    const int gw   = (blockIdx.x * blockDim.x + threadIdx.x) >> 5;
    const int lane = threadIdx.x & 31;
    const int which = gw >= H * S;
    const int idx   = which ? gw - H * S : gw;
    const int hh = idx >> 11;
    const int j  = idx & (S - 1);
    const float* bias = which ? rrb : rwb;
    const float* mat  = which ? g_r : g_k;
    const float b0 = bias[hh * DH + lane];
    const float b1 = bias[hh * DH + 32 + lane];
    const float* row = mat + (size_t)j * NHD + hh * DH;
    float s = fmaf(b0, row[lane], b1 * row[32 + lane]);
#pragma unroll
    for (int off = 16; off > 0; off >>= 1)
        s += __shfl_xor_sync(0xffffffffu, s, off);
    if (lane == 0) {
        float* dst = which ? g_cr : g_ck;
        dst[hh * S + j] = s;
    }
}

// ---------------------------------------------------------------------------
// Causal flash attention. R10: K and RSL filled by cp.async as RAW fp32
// (natural layout, pad 68 — conflict-free scalar b-frags; tf32 MMA
// truncates the extra mantissa bits). V manual (needs f16 cvt).
// ---------------------------------------------------------------------------
#define KPAD 68
#define VP16 72   // f16 pitch for V tile (64 d + ones col + pad)
#define GPAD 132
#define PP16 (GPAD * 2)  // P f16 pitch inside G rows
#define SMEM_ATTN ((64*KPAD)*4 + 64*VP16*2 + (128*KPAD)*4 + (64*GPAD)*4 + (128+64+128)*4)

__global__ __launch_bounds__(256, 2) void attn_kernel()
{
    const int h   = blockIdx.y;
    const int qi0 = (gridDim.x - 1 - blockIdx.x) * 64;

    extern __shared__ float sm[];
    float*  ks    = sm;                               // 64 x KPAD f32 (raw)
    __half* vs16  = (__half*)(ks + 64 * KPAD);        // 64 x VP16 f16
    float*  rsl   = (float*)(vs16 + 64 * VP16);       // 128 x KPAD f32 (raw, circular)
    float*  G     = rsl + 128 * KPAD;                 // 64 x GPAD f32; P (f16) reuses rows
    float*  crs_s = G + 64 * GPAD;                    // 128
    float*  cks_s = crs_s + 128;                      // 64
    float*  mx    = cks_s + 64;                       // 128

    const int t    = threadIdx.x;
    const int lane = t & 31;
    const int w    = t >> 5;
    const int wp   = w & 3;            // q-row group
    const int half = w >> 2;           // key-column half
    const int g    = lane >> 2;
    const int tg   = lane & 3;
    const int i0   = wp * 16 + g;
    const int hb   = h * DH;
    const int jbase = half * 32;
    const int tile0 = (half == 0) ? (6 - 2 * wp) : (11 - 2 * wp);

    u32 qa[8][4];
    {
        const float* q0 = &g_q[(size_t)(qi0 + i0) * NHD + hb];
        const float* q1 = q0 + 8 * NHD;
#pragma unroll
        for (int k0 = 0; k0 < 8; k0++) {
            qa[k0][0] = f2tf32(q0[k0 * 8 + tg]);
            qa[k0][1] = f2tf32(q1[k0 * 8 + tg]);
            qa[k0][2] = f2tf32(q0[k0 * 8 + tg + 4]);
            qa[k0][3] = f2tf32(q1[k0 * 8 + tg + 4]);
        }
    }

    float O[9][4];   // [8] = l column (V ones col)
#pragma unroll
    for (int nt = 0; nt < 9; nt++) {
        O[nt][0] = 0.f; O[nt][1] = 0.f; O[nt][2] = 0.f; O[nt][3] = 0.f;
    }
    float m0 = -1e30f, m1 = -1e30f;

    const int nkt = qi0 / 64 + 1;
    for (int kt = 0; kt < nkt; kt++) {
        const int kj0   = kt * 64;
        const int base  = (S - 1) + kj0 - qi0 - 63;
        const int rbase = base & 127;
        __syncthreads();  // all consumers done before refill

        // ---- K (cp.async raw f32) + V (manual f16) fills ----
#pragma unroll
        for (int it = 0; it < 2; it++) {
            const int idx = t + it * 256;
            const int r = idx >> 3, m8 = (idx & 7) << 3;
            const float* kp = &g_k[(size_t)(kj0 + r) * NHD + hb + m8];
            u32 kd = sptr(&ks[r * KPAD + m8]);
            cpa16(kd, kp);
            cpa16(kd + 16, kp + 4);
            const float* vp = &g_v[(size_t)(kj0 + r) * NHD + hb + m8];
            float4 va = *(const float4*)vp;
            float4 vb = *(const float4*)(vp + 4);
            __half2 h0 = __floats2half2_rn(va.x, va.y);
            __half2 h1 = __floats2half2_rn(va.z, va.w);
            __half2 h2 = __floats2half2_rn(vb.x, vb.y);
            __half2 h3 = __floats2half2_rn(vb.z, vb.w);
            uint4 pk;
            pk.x = *(u32*)&h0; pk.y = *(u32*)&h1;
            pk.z = *(u32*)&h2; pk.w = *(u32*)&h3;
            *(uint4*)&vs16[r * VP16 + m8] = pk;
        }
        if (t < 64) {
            __half2 one0 = __floats2half2_rn(1.f, 0.f);
            __half2 zz   = __floats2half2_rn(0.f, 0.f);
            uint4 pk;
            pk.x = *(u32*)&one0;
            pk.y = pk.z = pk.w = *(u32*)&zz;
            *(uint4*)&vs16[t * VP16 + 64] = pk;
        }
        // ---- RSL (cp.async raw f32, circular): only new rows ----
        {
            const int rl0 = (kt == 0) ? 0 : 64;
            const int nit = (kt == 0) ? 4 : 2;
            for (int it = 0; it < nit; it++) {
                const int idx = t + it * 256;
                const int row = rl0 + (idx >> 3);
                const int m8  = (idx & 7) << 3;
                int mg = base + row;
                if (mg > S - 1) mg = S - 1;
                const float* rp = &g_r[(size_t)mg * NHD + hb + m8];
                u32 rd = sptr(&rsl[((rbase + row) & 127) * KPAD + m8]);
                cpa16(rd, rp);
                cpa16(rd + 16, rp + 4);
            }
        }
        if (t < 64) cks_s[t] = g_ck[h * S + kj0 + t];
        else if (t < 192) {
            const int mm = t - 64;
            int mg = base + mm;
            if (mg > S - 1) mg = S - 1;
            crs_s[mm] = (mm < 127) ? g_cr[h * S + mg] : 0.f;
        }
        CP_COMMIT();
        CP_WAIT0();
        __syncthreads();

        // ---- windowed G = Q @ RSL^T (+cr): 5 tiles per warp ----
        {
            int prow[5];
#pragma unroll
            for (int ni = 0; ni < 5; ni++)
                prow[ni] = ((rbase + (tile0 + ni) * 8 + g) & 127) * KPAD;
            float gc[5][4];
#pragma unroll
            for (int ni = 0; ni < 5; ni++) {
                const int col = (tile0 + ni) * 8 + 2 * tg;
                gc[ni][0] = crs_s[col];
                gc[ni][1] = crs_s[col + 1];
                gc[ni][2] = gc[ni][0];
                gc[ni][3] = gc[ni][1];
            }
#pragma unroll
            for (int k0 = 0; k0 < 8; k0++) {
#pragma unroll
                for (int ni = 0; ni < 5; ni++) {
                    u32 b0 = __float_as_uint(rsl[prow[ni] + k0 * 8 + tg]);
                    u32 b1 = __float_as_uint(rsl[prow[ni] + k0 * 8 + tg + 4]);
                    mma_tf32(gc[ni], qa[k0], b0, b1);
                }
            }
#pragma unroll
            for (int ni = 0; ni < 5; ni++) {
                const int col = (tile0 + ni) * 8 + 2 * tg;
                *(float2*)&G[i0 * GPAD + col]       = make_float2(gc[ni][0], gc[ni][1]);
                *(float2*)&G[(i0 + 8) * GPAD + col] = make_float2(gc[ni][2], gc[ni][3]);
            }
        }
        pair_bar(wp);  // pair's G halves visible before gather

        // ---- AC = Q @ K^T (+ck), own 32-key half ----
        float sc[4][4];
#pragma unroll
        for (int nt = 0; nt < 4; nt++) {
            const int col = jbase + nt * 8 + 2 * tg;
            sc[nt][0] = cks_s[col];
            sc[nt][1] = cks_s[col + 1];
            sc[nt][2] = sc[nt][0];
            sc[nt][3] = sc[nt][1];
        }
#pragma unroll
        for (int k0 = 0; k0 < 8; k0++) {
#pragma unroll
            for (int nt = 0; nt < 4; nt++) {
                const int krow = (jbase + nt * 8 + g) * KPAD + k0 * 8 + tg;
                u32 b0 = __float_as_uint(ks[krow]);
                u32 b1 = __float_as_uint(ks[krow + 4]);
                mma_tf32(sc[nt], qa[k0], b0, b1);
            }
        }

        // ---- BD gather + mask + own-half row max ----
        const bool diag = (kt == nkt - 1);
        float rmax0 = -1e30f, rmax1 = -1e30f;
#pragma unroll
        for (int nt = 0; nt < 4; nt++) {
            const int j = jbase + nt * 8 + 2 * tg;
            float s00 = (sc[nt][0] + G[i0 * GPAD + 63 + j - i0]) * 0.125f;
            float s01 = (sc[nt][1] + G[i0 * GPAD + 64 + j - i0]) * 0.125f;
            float s10 = (sc[nt][2] + G[(i0 + 8) * GPAD + 55 + j - i0]) * 0.125f;
            float s11 = (sc[nt][3] + G[(i0 + 8) * GPAD + 56 + j - i0]) * 0.125f;
            if (diag) {
                if (kj0 + j     > qi0 + i0)     s00 = -1e30f;
                if (kj0 + j + 1 > qi0 + i0)     s01 = -1e30f;
                if (kj0 + j     > qi0 + i0 + 8) s10 = -1e30f;
                if (kj0 + j + 1 > qi0 + i0 + 8) s11 = -1e30f;
            }
            sc[nt][0] = s00; sc[nt][1] = s01; sc[nt][2] = s10; sc[nt][3] = s11;
            rmax0 = fmaxf(rmax0, fmaxf(s00, s01));
            rmax1 = fmaxf(rmax1, fmaxf(s10, s11));
        }
        rmax0 = fmaxf(rmax0, __shfl_xor_sync(0xffffffffu, rmax0, 1));
        rmax0 = fmaxf(rmax0, __shfl_xor_sync(0xffffffffu, rmax0, 2));
        rmax1 = fmaxf(rmax1, __shfl_xor_sync(0xffffffffu, rmax1, 1));
        rmax1 = fmaxf(rmax1, __shfl_xor_sync(0xffffffffu, rmax1, 2));

        // exchange with partner half (also orders partner gather before P stores)
        mx[2 * i0 + half]       = rmax0;
        mx[2 * (i0 + 8) + half] = rmax1;
        pair_bar(wp);
        rmax0 = fmaxf(rmax0, mx[2 * i0 + (half ^ 1)]);
        rmax1 = fmaxf(rmax1, mx[2 * (i0 + 8) + (half ^ 1)]);

        const float newm0 = fmaxf(m0, rmax0);
        const float newm1 = fmaxf(m1, rmax1);
        const float a0 = __expf(m0 - newm0);
        const float a1 = __expf(m1 - newm1);
        m0 = newm0; m1 = newm1;
#pragma unroll
        for (int nt = 0; nt < 9; nt++) {
            O[nt][0] *= a0; O[nt][1] *= a0;
            O[nt][2] *= a1; O[nt][3] *= a1;
        }

        // ---- exp (f16x2 MUFU) + store packed-f16 P into own G-row bytes ----
        __half* psb16 = (__half*)G;
        const float negm0 = -m0 * LOG2E;
        const float negm1 = -m1 * LOG2E;
#pragma unroll
        for (int nt = 0; nt < 4; nt++) {
            const int col = jbase + nt * 8 + 2 * tg;
            u32 p01 = exp2_f16x2(fmaf(sc[nt][0], LOG2E, negm0),
                                 fmaf(sc[nt][1], LOG2E, negm0));
            u32 p23 = exp2_f16x2(fmaf(sc[nt][2], LOG2E, negm1),
                                 fmaf(sc[nt][3], LOG2E, negm1));
            *(u32*)&psb16[i0 * PP16 + col]       = p01;
            *(u32*)&psb16[(i0 + 8) * PP16 + col] = p23;
        }
        __syncwarp();  // P rows/cols are warp-private

        // ---- PV (f16 k16): O += P_half @ [V | 1], l rides in n-tile 8 ----
#pragma unroll
        for (int ki = 0; ki < 2; ki++) {
            const int kb = jbase + ki * 16;
            u32 pa[4];
            pa[0] = *(const u32*)&psb16[i0 * PP16 + kb + 2 * tg];
            pa[1] = *(const u32*)&psb16[(i0 + 8) * PP16 + kb + 2 * tg];
            pa[2] = *(const u32*)&psb16[i0 * PP16 + kb + 8 + 2 * tg];
            pa[3] = *(const u32*)&psb16[(i0 + 8) * PP16 + kb + 8 + 2 * tg];
            const u32 vb = sptr(vs16 + (size_t)(kb + (lane & 15)) * VP16);
#pragma unroll
            for (int nt = 0; nt < 9; nt++) {
                u32 b0, b1;
                ldm2t(b0, b1, vb + nt * 16);
                mma_f16(O[nt], pa, b0, b1);
            }
        }
    }

    // ---- extract l (ones-column accumulator, tg==0 lanes own it) ----
    float l0 = __shfl_sync(0xffffffffu, O[8][0], lane & 28);
    float l1 = __shfl_sync(0xffffffffu, O[8][2], lane & 28);

    // ---- merge the two key-halves (same m-sequence -> plain sums) ----
    __syncthreads();
    if (half == 1) {
#pragma unroll
        for (int nt = 0; nt < 8; nt++) {
            const int col = nt * 8 + 2 * tg;
            *(float2*)&G[i0 * GPAD + col]       = make_float2(O[nt][0], O[nt][1]);
            *(float2*)&G[(i0 + 8) * GPAD + col] = make_float2(O[nt][2], O[nt][3]);
        }
        if (tg == 0) {
            cks_s[i0]     = l0;
            cks_s[i0 + 8] = l1;
        }
    }
    __syncthreads();
    if (half == 0) {
        l0 += cks_s[i0];
        l1 += cks_s[i0 + 8];
        const float inv0 = 1.f / l0;
        const float inv1 = 1.f / l1;
#pragma unroll
        for (int nt = 0; nt < 8; nt++) {
            const int col = nt * 8 + 2 * tg;
            float2 p0 = *(const float2*)&G[i0 * GPAD + col];
            float2 p1 = *(const float2*)&G[(i0 + 8) * GPAD + col];
            float o00 = (O[nt][0] + p0.x) * inv0, o01 = (O[nt][1] + p0.y) * inv0;
            float o10 = (O[nt][2] + p1.x) * inv1, o11 = (O[nt][3] + p1.y) * inv1;
            const size_t idx0 = (size_t)(qi0 + i0) * NHD + hb + col;
            const size_t idx1 = (size_t)(qi0 + i0 + 8) * NHD + hb + col;
            __nv_bfloat162 h0 = __floats2bfloat162_rn(o00, o01);
            __nv_bfloat162 h1 = __floats2bfloat162_rn(o10, o11);
            __nv_bfloat162 L0 = __floats2bfloat162_rn(o00 - __bfloat162float(h0.x),
                                                      o01 - __bfloat162float(h0.y));
            __nv_bfloat162 L1 = __floats2bfloat162_rn(o10 - __bfloat162float(h1.x),
                                                      o11 - __bfloat162float(h1.y));
            *(__nv_bfloat162*)&g_at_h[idx0] = h0;
            *(__nv_bfloat162*)&g_at_l[idx0] = L0;
            *(__nv_bfloat162*)&g_at_h[idx1] = h1;
            *(__nv_bfloat162*)&g_at_l[idx1] = L1;
        }
    }
}

// ---------------------------------------------------------------------------
extern "C" void kernel_launch(void* const* d_in, const int* in_sizes, int n_in,
                              void* d_out, int out_size)
{
    const float* inputs_q = (const float*)d_in[0];
    const float* pos_emb  = (const float*)d_in[1];
    const float* r_w_bias = (const float*)d_in[2];
    const float* r_r_bias = (const float*)d_in[3];
    const float* Wq = (const float*)d_in[4];
    const float* bq = (const float*)d_in[5];
    const float* Wk = (const float*)d_in[6];
    const float* bk = (const float*)d_in[7];
    const float* Wv = (const float*)d_in[8];
    const float* bv = (const float*)d_in[9];
    const float* Wr = (const float*)d_in[10];
    const float* br = (const float*)d_in[11];
    const float* Wo = (const float*)d_in[12];
    const float* bo = (const float*)d_in[13];
    float* out = (float*)d_out;

    cudaFuncSetAttribute(attn_kernel,
                         cudaFuncAttributeMaxDynamicSharedMemorySize, SMEM_ATTN);
    cudaFuncSetAttribute(proj_bf_kernel,
                         cudaFuncAttributeMaxDynamicSharedMemorySize, GEMM_SMEM_BYTES);
    cudaFuncSetAttribute(out_bf_kernel,
                         cudaFuncAttributeMaxDynamicSharedMemorySize, GEMM_SMEM_BYTES);

    split_kernel<<<(2 * 524288 + 5 * 262144) / 256, 256>>>(
        inputs_q, pos_emb, Wq, Wk, Wv, Wr, Wo);

    proj_bf_kernel<<<dim3(NHD / 128, S / 128, 4), 256, GEMM_SMEM_BYTES>>>(
        bq, bk, bv, br);

    bias_dots_kernel<<<(2 * H * S * 32) / 256, 256>>>(r_w_bias, r_r_bias);

    attn_kernel<<<dim3(S / 64, H), 256, SMEM_ATTN>>>();

    out_bf_kernel<<<dim3(F / 128, S / 128), 256, GEMM_SMEM_BYTES>>>(bo, out);
}

// round 11
// speedup vs baseline: 7.3344x; 1.1781x over previous
#include <cuda_runtime.h>
#include <cuda_bf16.h>
#include <cuda_fp16.h>

#define S 2048
#define F 1024
#define H 16
#define DH 64
#define NHD 1024  // H*DH

typedef unsigned long long u64;
typedef unsigned int u32;

#define LOG2E 1.4426950408889634f
#define SCQ (0.125f * LOG2E)   // folded softmax scale + log2 conversion

// ---- f16 mma (attention AC/G/PV) ----
__device__ __forceinline__ void mma_f16(float c[4], const u32 a[4], u32 b0, u32 b1) {
    asm volatile(
        "mma.sync.aligned.m16n8k16.row.col.f32.f16.f16.f32 "
        "{%0,%1,%2,%3}, {%4,%5,%6,%7}, {%8,%9}, {%0,%1,%2,%3};\n"
        : "+f"(c[0]), "+f"(c[1]), "+f"(c[2]), "+f"(c[3])
        : "r"(a[0]), "r"(a[1]), "r"(a[2]), "r"(a[3]), "r"(b0), "r"(b1));
}

__device__ __forceinline__ u32 exp2_f16x2(float ylo, float yhi) {
    __half2 h = __floats2half2_rn(ylo, yhi);
    __half2 r = h2exp2(h);
    return *(u32*)&r;
}

// ---- bf16 helpers (GEMMs) ----
__device__ __forceinline__ void mma_bf16(float c[4], const u32 a[4], u32 b0, u32 b1) {
    asm volatile(
        "mma.sync.aligned.m16n8k16.row.col.f32.bf16.bf16.f32 "
        "{%0,%1,%2,%3}, {%4,%5,%6,%7}, {%8,%9}, {%0,%1,%2,%3};\n"
        : "+f"(c[0]), "+f"(c[1]), "+f"(c[2]), "+f"(c[3])
        : "r"(a[0]), "r"(a[1]), "r"(a[2]), "r"(a[3]), "r"(b0), "r"(b1));
}
__device__ __forceinline__ void ldm2t(u32& d0, u32& d1, u32 saddr) {
    asm volatile("ldmatrix.sync.aligned.m8n8.x2.trans.shared.b16 {%0,%1}, [%2];"
                 : "=r"(d0), "=r"(d1) : "r"(saddr));
}
__device__ __forceinline__ void ldm2(u32& d0, u32& d1, u32 saddr) {
    asm volatile("ldmatrix.sync.aligned.m8n8.x2.shared.b16 {%0,%1}, [%2];"
                 : "=r"(d0), "=r"(d1) : "r"(saddr));
}
__device__ __forceinline__ u32 sptr(const void* p) {
    return (u32)__cvta_generic_to_shared(p);
}
__device__ __forceinline__ void pair_bar(int wp) {
    asm volatile("bar.sync %0, 64;" :: "r"(1 + wp) : "memory");
}
// ---- cp.async (global -> shared, 16B) ----
__device__ __forceinline__ void cpa16(u32 dst, const void* src) {
    asm volatile("cp.async.ca.shared.global [%0], [%1], 16;"
                 :: "r"(dst), "l"(src) : "memory");
}
#define CP_COMMIT() asm volatile("cp.async.commit_group;" ::: "memory")
#define CP_WAIT0()  asm volatile("cp.async.wait_group 0;" ::: "memory")

// Scratch (device globals: allocation-free per harness rules)
__device__ float g_k[S * NHD];   // fp32 for bias_dots
__device__ float g_r[S * NHD];   // fp32 for bias_dots
__device__ float g_ck[H * S];
__device__ float g_cr[H * S];
// f16 attention operands (emitted by proj epilogue)
__device__ __half g_q16[S * NHD];   // pre-scaled by SCQ
__device__ __half g_k16[S * NHD];
__device__ __half g_v16[S * NHD];
__device__ __half g_r16[S * NHD];
// bf16 hi/lo split panels
__device__ __nv_bfloat16 g_xq_h[S * F],   g_xq_l[S * F];
__device__ __nv_bfloat16 g_xr_h[S * F],   g_xr_l[S * F];
__device__ __nv_bfloat16 g_wh[5 * F * NHD], g_wl[5 * F * NHD];  // Wq,Wk,Wv,Wr,Wo
__device__ __nv_bfloat16 g_at_h[S * NHD], g_at_l[S * NHD];

// ---------------------------------------------------------------------------
// Split fp32 -> (bf16 hi, bf16 lo) for all GEMM operands in ONE launch.
// ---------------------------------------------------------------------------
__global__ __launch_bounds__(256) void split_kernel(
    const float* __restrict__ xq, const float* __restrict__ xr,
    const float* __restrict__ w0, const float* __restrict__ w1,
    const float* __restrict__ w2, const float* __restrict__ w3,
    const float* __restrict__ w4)
{
    const int i = blockIdx.x * 256 + threadIdx.x;
    const float* src;
    __nv_bfloat16 *h, *l;
    int off;
    if (i < 524288)        { src = xq; h = g_xq_h; l = g_xq_l; off = i; }
    else if (i < 1048576)  { src = xr; h = g_xr_h; l = g_xr_l; off = i - 524288; }
    else {
        const int j = i - 1048576;
        const int w = j >> 18;
        off = j & 262143;
        const float* ws[5] = {w0, w1, w2, w3, w4};
        src = ws[w];
        h = g_wh + (size_t)w * (F * NHD);
        l = g_wl + (size_t)w * (F * NHD);
    }
    float4 v = ((const float4*)src)[off];
    __nv_bfloat162 h0 = __floats2bfloat162_rn(v.x, v.y);
    __nv_bfloat162 h1 = __floats2bfloat162_rn(v.z, v.w);
    __nv_bfloat162 l0 = __floats2bfloat162_rn(v.x - __bfloat162float(h0.x),
                                              v.y - __bfloat162float(h0.y));
    __nv_bfloat162 l1 = __floats2bfloat162_rn(v.z - __bfloat162float(h1.x),
                                              v.w - __bfloat162float(h1.y));
    ((__nv_bfloat162*)h)[off * 2]     = h0;
    ((__nv_bfloat162*)h)[off * 2 + 1] = h1;
    ((__nv_bfloat162*)l)[off * 2]     = l0;
    ((__nv_bfloat162*)l)[off * 2 + 1] = l1;
}

// ---------------------------------------------------------------------------
// bf16 split-GEMM with cp.async fills. Epilogue can emit fp32 (C) and/or
// scaled f16 (C16) outputs.
// ---------------------------------------------------------------------------
#define GEMM_SMEM_BYTES 75776

__device__ __forceinline__ void gemm_bf16_body(
    const __nv_bfloat16* __restrict__ Ah, const __nv_bfloat16* __restrict__ Al,
    const __nv_bfloat16* __restrict__ Bh, const __nv_bfloat16* __restrict__ Bl,
    const float* __restrict__ bias, float* __restrict__ C,
    __half* __restrict__ C16, float scale,
    int M, int N, int K)
{
    extern __shared__ __nv_bfloat16 sb[];
    __nv_bfloat16* As_h = sb;
    __nv_bfloat16* As_l = sb + 10240;
    __nv_bfloat16* Bs_h = sb + 20480;
    __nv_bfloat16* Bs_l = sb + 29184;

    const int t    = threadIdx.x;
    const int lane = t & 31;
    const int w    = t >> 5;
    const int wm   = (w & 3) * 32;
    const int wn   = (w >> 2) * 64;
    const int g    = lane >> 2;
    const int tg   = lane & 3;
    const int m0   = blockIdx.y * 128;
    const int n0   = blockIdx.x * 128;

    float Cr[2][8][4];
#pragma unroll
    for (int mt = 0; mt < 2; mt++)
#pragma unroll
        for (int nt = 0; nt < 8; nt++) {
            Cr[mt][nt][0] = 0.f; Cr[mt][nt][1] = 0.f;
            Cr[mt][nt][2] = 0.f; Cr[mt][nt][3] = 0.f;
        }

    const int fm = t >> 1, fh = (t & 1) * 16;
    const int fk = t >> 3, fv = (t & 7) * 16;

    const __nv_bfloat16* gAh = Ah + (size_t)(m0 + fm) * K + fh;
    const __nv_bfloat16* gAl = Al + (size_t)(m0 + fm) * K + fh;
    const __nv_bfloat16* gBh = Bh + (size_t)fk * N + n0 + fv;
    const __nv_bfloat16* gBl = Bl + (size_t)fk * N + n0 + fv;

    const int sa_off = fm * 40 + fh;
    const int sb_off = fk * 136 + fv;

    {
        u32 d;
        d = sptr(As_h + sa_off); cpa16(d, gAh); cpa16(d + 16, gAh + 8);
        d = sptr(As_l + sa_off); cpa16(d, gAl); cpa16(d + 16, gAl + 8);
        d = sptr(Bs_h + sb_off); cpa16(d, gBh); cpa16(d + 16, gBh + 8);
        d = sptr(Bs_l + sb_off); cpa16(d, gBl); cpa16(d + 16, gBl + 8);
        CP_COMMIT();
        CP_WAIT0();
    }
    __syncthreads();

    int buf = 0;
    const int nkc = K / 32;
    for (int kc = 0; kc < nkc; kc++) {
        const bool has = (kc + 1) < nkc;
        if (has) {
            const __nv_bfloat16* pAh = gAh + (kc + 1) * 32;
            const __nv_bfloat16* pAl = gAl + (kc + 1) * 32;
            const __nv_bfloat16* pBh = gBh + (size_t)(kc + 1) * 32 * N;
            const __nv_bfloat16* pBl = gBl + (size_t)(kc + 1) * 32 * N;
            const int nb = buf ^ 1;
            u32 d;
            d = sptr(As_h + nb * 5120 + sa_off); cpa16(d, pAh); cpa16(d + 16, pAh + 8);
            d = sptr(As_l + nb * 5120 + sa_off); cpa16(d, pAl); cpa16(d + 16, pAl + 8);
            d = sptr(Bs_h + nb * 4352 + sb_off); cpa16(d, pBh); cpa16(d + 16, pBh + 8);
            d = sptr(Bs_l + nb * 4352 + sb_off); cpa16(d, pBl); cpa16(d + 16, pBl + 8);
            CP_COMMIT();
        }
        const __nv_bfloat16* Ab_h = As_h + buf * 5120;
        const __nv_bfloat16* Ab_l = As_l + buf * 5120;
        const __nv_bfloat16* Bb_h = Bs_h + buf * 4352;
        const __nv_bfloat16* Bb_l = Bs_l + buf * 4352;

#pragma unroll
        for (int ks2 = 0; ks2 < 2; ks2++) {
            const int ks = ks2 * 16;
            u32 ah[2][4], al[2][4];
#pragma unroll
            for (int mt = 0; mt < 2; mt++) {
                const __nv_bfloat16* r0 = Ab_h + (wm + mt * 16 + g) * 40 + ks + 2 * tg;
                ah[mt][0] = *(const u32*)r0;
                ah[mt][1] = *(const u32*)(r0 + 8 * 40);
                ah[mt][2] = *(const u32*)(r0 + 8);
                ah[mt][3] = *(const u32*)(r0 + 8 * 40 + 8);
                const __nv_bfloat16* r1 = Ab_l + (wm + mt * 16 + g) * 40 + ks + 2 * tg;
                al[mt][0] = *(const u32*)r1;
                al[mt][1] = *(const u32*)(r1 + 8 * 40);
                al[mt][2] = *(const u32*)(r1 + 8);
                al[mt][3] = *(const u32*)(r1 + 8 * 40 + 8);
            }
            const u32 bbh = sptr(Bb_h + (ks + (lane & 15)) * 136 + wn);
            const u32 bbl = sptr(Bb_l + (ks + (lane & 15)) * 136 + wn);
#pragma unroll
            for (int nt = 0; nt < 8; nt++) {
                u32 bh0, bh1, bl0, bl1;
                ldm2t(bh0, bh1, bbh + nt * 16);
                ldm2t(bl0, bl1, bbl + nt * 16);
#pragma unroll
                for (int mt = 0; mt < 2; mt++) {
                    mma_bf16(Cr[mt][nt], ah[mt], bh0, bh1);
                    mma_bf16(Cr[mt][nt], ah[mt], bl0, bl1);
                    mma_bf16(Cr[mt][nt], al[mt], bh0, bh1);
                }
            }
        }

        if (has) {
            CP_WAIT0();
            __syncthreads();
            buf ^= 1;
        }
    }

#pragma unroll
    for (int mt = 0; mt < 2; mt++) {
        const int row = m0 + wm + mt * 16 + g;
#pragma unroll
        for (int nt = 0; nt < 8; nt++) {
            const int col = n0 + wn + nt * 8 + 2 * tg;
            float2 b01 = *(const float2*)&bias[col];
            const float v00 = Cr[mt][nt][0] + b01.x;
            const float v01 = Cr[mt][nt][1] + b01.y;
            const float v10 = Cr[mt][nt][2] + b01.x;
            const float v11 = Cr[mt][nt][3] + b01.y;
            if (C) {
                *(float2*)(C + (size_t)row * N + col)       = make_float2(v00, v01);
                *(float2*)(C + (size_t)(row + 8) * N + col) = make_float2(v10, v11);
            }
            if (C16) {
                *(__half2*)(C16 + (size_t)row * N + col) =
                    __floats2half2_rn(v00 * scale, v01 * scale);
                *(__half2*)(C16 + (size_t)(row + 8) * N + col) =
                    __floats2half2_rn(v10 * scale, v11 * scale);
            }
        }
    }
}

__global__ __launch_bounds__(256, 2) void proj_bf_kernel(
    const float* __restrict__ bq, const float* __restrict__ bk,
    const float* __restrict__ bv, const float* __restrict__ br)
{
    const int z = blockIdx.z;
    const __nv_bfloat16* Ah = (z < 3) ? g_xq_h : g_xr_h;
    const __nv_bfloat16* Al = (z < 3) ? g_xq_l : g_xr_l;
    const __nv_bfloat16* Bh = g_wh + (size_t)z * (F * NHD);
    const __nv_bfloat16* Bl = g_wl + (size_t)z * (F * NHD);
    const float* bias;
    float* C;
    __half* C16;
    float scale = 1.f;
    switch (z) {
        case 0:  bias = bq; C = nullptr; C16 = g_q16; scale = SCQ; break;
        case 1:  bias = bk; C = g_k;     C16 = g_k16; break;
        case 2:  bias = bv; C = nullptr; C16 = g_v16; break;
        default: bias = br; C = g_r;     C16 = g_r16; break;
    }
    gemm_bf16_body(Ah, Al, Bh, Bl, bias, C, C16, scale, S, NHD, F);
}

__global__ __launch_bounds__(256, 2) void out_bf_kernel(
    const float* __restrict__ bo, float* __restrict__ out)
{
    gemm_bf16_body(g_at_h, g_at_l,
                   g_wh + (size_t)4 * (F * NHD), g_wl + (size_t)4 * (F * NHD),
                   bo, out, nullptr, 1.f, S, F, NHD);
}

// ---------------------------------------------------------------------------
// ck[h][j] = SCQ * rw[h].k[j,h,:],  cr[h][m] = SCQ * rr[h].r[m,h,:]
// ---------------------------------------------------------------------------
__global__ __launch_bounds__(256) void bias_dots_kernel(
    const float* __restrict__ rwb, const float* __restrict__ rrb)
{
    const int gw   = (blockIdx.x * blockDim.x + threadIdx.x) >> 5;
    const int lane = threadIdx.x & 31;
    const int which = gw >= H * S;
    const int idx   = which ? gw - H * S : gw;
    const int hh = idx >> 11;
    const int j  = idx & (S - 1);
    const float* bias = which ? rrb : rwb;
    const float* mat  = which ? g_r : g_k;
    const float b0 = bias[hh * DH + lane];
    const float b1 = bias[hh * DH + 32 + lane];
    const float* row = mat + (size_t)j * NHD + hh * DH;
    float s = fmaf(b0, row[lane], b1 * row[32 + lane]);
#pragma unroll
    for (int off = 16; off > 0; off >>= 1)
        s += __shfl_xor_sync(0xffffffffu, s, off);
    if (lane == 0) {
        float* dst = which ? g_cr : g_ck;
        dst[hh * S + j] = s * SCQ;
    }
}

// ---------------------------------------------------------------------------
// Causal flash attention, all-f16 MMA (k16). Scores already in log2 domain
// (SCQ folded into q and ck/cr): s = AC + gather(G); p = 2^(s - m).
// ---------------------------------------------------------------------------
#define KP16 72
#define GPAD 132
#define PP16 (GPAD * 2)  // P f16 pitch inside G rows
#define SMEM_ATTN ((64*KP16 + 64*KP16 + 128*KP16)*2 + (64*GPAD)*4 + (128+64+128)*4)

__global__ __launch_bounds__(256, 2) void attn_kernel()
{
    const int h   = blockIdx.y;
    const int qi0 = (gridDim.x - 1 - blockIdx.x) * 64;

    extern __shared__ float sm[];
    __half* ks16  = (__half*)sm;                      // 64 x KP16
    __half* vs16  = ks16 + 64 * KP16;                 // 64 x KP16 (+ ones col 64)
    __half* rsl16 = vs16 + 64 * KP16;                 // 128 x KP16 (circular)
    float*  G     = (float*)(rsl16 + 128 * KP16);     // 64 x GPAD; P (f16) reuses rows
    float*  crs_s = G + 64 * GPAD;                    // 128
    float*  cks_s = crs_s + 128;                      // 64
    float*  mx    = cks_s + 64;                       // 128

    const int t    = threadIdx.x;
    const int lane = t & 31;
    const int w    = t >> 5;
    const int wp   = w & 3;            // q-row group
    const int half = w >> 2;           // key-column half
    const int g    = lane >> 2;
    const int tg   = lane & 3;
    const int i0   = wp * 16 + g;
    const int hb   = h * DH;
    const int jbase = half * 32;
    const int tile0 = (half == 0) ? (6 - 2 * wp) : (11 - 2 * wp);

    // ---- persistent Q a-frags (f16, pre-scaled by SCQ) ----
    u32 qa[4][4];
    {
        const __half* q0 = &g_q16[(size_t)(qi0 + i0) * NHD + hb];
        const __half* q1 = q0 + 8 * NHD;
#pragma unroll
        for (int k0 = 0; k0 < 4; k0++) {
            qa[k0][0] = *(const u32*)(q0 + k0 * 16 + 2 * tg);
            qa[k0][1] = *(const u32*)(q1 + k0 * 16 + 2 * tg);
            qa[k0][2] = *(const u32*)(q0 + k0 * 16 + 8 + 2 * tg);
            qa[k0][3] = *(const u32*)(q1 + k0 * 16 + 8 + 2 * tg);
        }
    }

    // ones column for l (cols 64..71 of vs16; never touched by fills)
    if (t < 64) {
        __half* p = &vs16[t * KP16 + 64];
        p[0] = __float2half(1.f);
#pragma unroll
        for (int i = 1; i < 8; i++) p[i] = __float2half(0.f);
    }

    float O[9][4];   // [8] = l column
#pragma unroll
    for (int nt = 0; nt < 9; nt++) {
        O[nt][0] = 0.f; O[nt][1] = 0.f; O[nt][2] = 0.f; O[nt][3] = 0.f;
    }
    float m0 = -1e30f, m1 = -1e30f;

    const int nkt = qi0 / 64 + 1;
    for (int kt = 0; kt < nkt; kt++) {
        const int kj0   = kt * 64;
        const int base  = (S - 1) + kj0 - qi0 - 63;
        const int rbase = base & 127;
        __syncthreads();  // all consumers done before refill

        // ---- K + V fills (cp.async f16, 16B = 8 halves) ----
#pragma unroll
        for (int it = 0; it < 2; it++) {
            const int idx = t + it * 256;      // < 512
            const int r = idx >> 3, c8 = (idx & 7) << 3;
            cpa16(sptr(&ks16[r * KP16 + c8]),
                  &g_k16[(size_t)(kj0 + r) * NHD + hb + c8]);
            cpa16(sptr(&vs16[r * KP16 + c8]),
                  &g_v16[(size_t)(kj0 + r) * NHD + hb + c8]);
        }
        // ---- RSL (cp.async f16, circular): only new rows ----
        {
            const int rl0 = (kt == 0) ? 0 : 64;
            const int nit = (kt == 0) ? 4 : 2;
            for (int it = 0; it < nit; it++) {
                const int idx = t + it * 256;
                const int row = rl0 + (idx >> 3);
                const int c8  = (idx & 7) << 3;
                int mg = base + row;
                if (mg > S - 1) mg = S - 1;
                cpa16(sptr(&rsl16[((rbase + row) & 127) * KP16 + c8]),
                      &g_r16[(size_t)mg * NHD + hb + c8]);
            }
        }
        if (t < 64) cks_s[t] = g_ck[h * S + kj0 + t];
        else if (t < 192) {
            const int mm = t - 64;
            int mg = base + mm;
            if (mg > S - 1) mg = S - 1;
            crs_s[mm] = (mm < 127) ? g_cr[h * S + mg] : 0.f;
        }
        CP_COMMIT();
        CP_WAIT0();
        __syncthreads();

        // ---- windowed G = Q @ RSL^T (+cr): 5 tiles, f16 k16 ----
        {
            u32 rb[5];
#pragma unroll
            for (int ni = 0; ni < 5; ni++) {
                const int lrow = (rbase + (tile0 + ni) * 8 + (lane & 7)) & 127;
                rb[ni] = sptr(&rsl16[lrow * KP16 + ((lane >> 3) & 1) * 8]);
            }
            float gc[5][4];
#pragma unroll
            for (int ni = 0; ni < 5; ni++) {
                const int col = (tile0 + ni) * 8 + 2 * tg;
                gc[ni][0] = crs_s[col];
                gc[ni][1] = crs_s[col + 1];
                gc[ni][2] = gc[ni][0];
                gc[ni][3] = gc[ni][1];
            }
#pragma unroll
            for (int k0 = 0; k0 < 4; k0++) {
#pragma unroll
                for (int ni = 0; ni < 5; ni++) {
                    u32 b0, b1;
                    ldm2(b0, b1, rb[ni] + k0 * 32);
                    mma_f16(gc[ni], qa[k0], b0, b1);
                }
            }
#pragma unroll
            for (int ni = 0; ni < 5; ni++) {
                const int col = (tile0 + ni) * 8 + 2 * tg;
                *(float2*)&G[i0 * GPAD + col]       = make_float2(gc[ni][0], gc[ni][1]);
                *(float2*)&G[(i0 + 8) * GPAD + col] = make_float2(gc[ni][2], gc[ni][3]);
            }
        }
        pair_bar(wp);  // pair's G halves visible before gather

        // ---- AC = Q @ K^T (+ck), own 32-key half, f16 k16 ----
        float sc[4][4];
        u32 kb4[4];
#pragma unroll
        for (int nt = 0; nt < 4; nt++) {
            const int col = jbase + nt * 8 + 2 * tg;
            sc[nt][0] = cks_s[col];
            sc[nt][1] = cks_s[col + 1];
            sc[nt][2] = sc[nt][0];
            sc[nt][3] = sc[nt][1];
            kb4[nt] = sptr(&ks16[(jbase + nt * 8 + (lane & 7)) * KP16 +
                                 ((lane >> 3) & 1) * 8]);
        }
#pragma unroll
        for (int k0 = 0; k0 < 4; k0++) {
#pragma unroll
            for (int nt = 0; nt < 4; nt++) {
                u32 b0, b1;
                ldm2(b0, b1, kb4[nt] + k0 * 32);
                mma_f16(sc[nt], qa[k0], b0, b1);
            }
        }

        // ---- BD gather + mask + own-half row max (log2 domain) ----
        const bool diag = (kt == nkt - 1);
        float rmax0 = -1e30f, rmax1 = -1e30f;
#pragma unroll
        for (int nt = 0; nt < 4; nt++) {
            const int j = jbase + nt * 8 + 2 * tg;
            float s00 = sc[nt][0] + G[i0 * GPAD + 63 + j - i0];
            float s01 = sc[nt][1] + G[i0 * GPAD + 64 + j - i0];
            float s10 = sc[nt][2] + G[(i0 + 8) * GPAD + 55 + j - i0];
            float s11 = sc[nt][3] + G[(i0 + 8) * GPAD + 56 + j - i0];
            if (diag) {
                if (kj0 + j     > qi0 + i0)     s00 = -1e30f;
                if (kj0 + j + 1 > qi0 + i0)     s01 = -1e30f;
                if (kj0 + j     > qi0 + i0 + 8) s10 = -1e30f;
                if (kj0 + j + 1 > qi0 + i0 + 8) s11 = -1e30f;
            }
            sc[nt][0] = s00; sc[nt][1] = s01; sc[nt][2] = s10; sc[nt][3] = s11;
            rmax0 = fmaxf(rmax0, fmaxf(s00, s01));
            rmax1 = fmaxf(rmax1, fmaxf(s10, s11));
        }
        rmax0 = fmaxf(rmax0, __shfl_xor_sync(0xffffffffu, rmax0, 1));
        rmax0 = fmaxf(rmax0, __shfl_xor_sync(0xffffffffu, rmax0, 2));
        rmax1 = fmaxf(rmax1, __shfl_xor_sync(0xffffffffu, rmax1, 1));
        rmax1 = fmaxf(rmax1, __shfl_xor_sync(0xffffffffu, rmax1, 2));

        // exchange with partner half (also orders partner gather before P stores)
        mx[2 * i0 + half]       = rmax0;
        mx[2 * (i0 + 8) + half] = rmax1;
        pair_bar(wp);
        rmax0 = fmaxf(rmax0, mx[2 * i0 + (half ^ 1)]);
        rmax1 = fmaxf(rmax1, mx[2 * (i0 + 8) + (half ^ 1)]);

        const float newm0 = fmaxf(m0, rmax0);
        const float newm1 = fmaxf(m1, rmax1);
        const float a0 = exp2f(m0 - newm0);
        const float a1 = exp2f(m1 - newm1);
        m0 = newm0; m1 = newm1;
#pragma unroll
        for (int nt = 0; nt < 9; nt++) {
            O[nt][0] *= a0; O[nt][1] *= a0;
            O[nt][2] *= a1; O[nt][3] *= a1;
        }

        // ---- p = 2^(s-m) via f16x2 MUFU; store packed-f16 P ----
        __half* psb16 = (__half*)G;
#pragma unroll
        for (int nt = 0; nt < 4; nt++) {
            const int col = jbase + nt * 8 + 2 * tg;
            u32 p01 = exp2_f16x2(sc[nt][0] - m0, sc[nt][1] - m0);
            u32 p23 = exp2_f16x2(sc[nt][2] - m1, sc[nt][3] - m1);
            *(u32*)&psb16[i0 * PP16 + col]       = p01;
            *(u32*)&psb16[(i0 + 8) * PP16 + col] = p23;
        }
        __syncwarp();  // P rows/cols are warp-private

        // ---- PV (f16 k16): O += P_half @ [V | 1], l rides in n-tile 8 ----
#pragma unroll
        for (int ki = 0; ki < 2; ki++) {
            const int kb = jbase + ki * 16;
            u32 pa[4];
            pa[0] = *(const u32*)&psb16[i0 * PP16 + kb + 2 * tg];
            pa[1] = *(const u32*)&psb16[(i0 + 8) * PP16 + kb + 2 * tg];
            pa[2] = *(const u32*)&psb16[i0 * PP16 + kb + 8 + 2 * tg];
            pa[3] = *(const u32*)&psb16[(i0 + 8) * PP16 + kb + 8 + 2 * tg];
            const u32 vb = sptr(vs16 + (size_t)(kb + (lane & 15)) * KP16);
#pragma unroll
            for (int nt = 0; nt < 9; nt++) {
                u32 b0, b1;
                ldm2t(b0, b1, vb + nt * 16);
                mma_f16(O[nt], pa, b0, b1);
            }
        }
    }

    // ---- extract l (ones-column accumulator, tg==0 lanes own it) ----
    float l0 = __shfl_sync(0xffffffffu, O[8][0], lane & 28);
    float l1 = __shfl_sync(0xffffffffu, O[8][2], lane & 28);

    // ---- merge the two key-halves (same m-sequence -> plain sums) ----
    __syncthreads();
    if (half == 1) {
#pragma unroll
        for (int nt = 0; nt < 8; nt++) {
            const int col = nt * 8 + 2 * tg;
            *(float2*)&G[i0 * GPAD + col]       = make_float2(O[nt][0], O[nt][1]);
            *(float2*)&G[(i0 + 8) * GPAD + col] = make_float2(O[nt][2], O[nt][3]);
        }
        if (tg == 0) {
            cks_s[i0]     = l0;
            cks_s[i0 + 8] = l1;
        }
    }
    __syncthreads();
    if (half == 0) {
        l0 += cks_s[i0];
        l1 += cks_s[i0 + 8];
        const float inv0 = 1.f / l0;
        const float inv1 = 1.f / l1;
#pragma unroll
        for (int nt = 0; nt < 8; nt++) {
            const int col = nt * 8 + 2 * tg;
            float2 p0 = *(const float2*)&G[i0 * GPAD + col];
            float2 p1 = *(const float2*)&G[(i0 + 8) * GPAD + col];
            float o00 = (O[nt][0] + p0.x) * inv0, o01 = (O[nt][1] + p0.y) * inv0;
            float o10 = (O[nt][2] + p1.x) * inv1, o11 = (O[nt][3] + p1.y) * inv1;
            const size_t idx0 = (size_t)(qi0 + i0) * NHD + hb + col;
            const size_t idx1 = (size_t)(qi0 + i0 + 8) * NHD + hb + col;
            __nv_bfloat162 h0 = __floats2bfloat162_rn(o00, o01);
            __nv_bfloat162 h1 = __floats2bfloat162_rn(o10, o11);
            __nv_bfloat162 L0 = __floats2bfloat162_rn(o00 - __bfloat162float(h0.x),
                                                      o01 - __bfloat162float(h0.y));
            __nv_bfloat162 L1 = __floats2bfloat162_rn(o10 - __bfloat162float(h1.x),
                                                      o11 - __bfloat162float(h1.y));
            *(__nv_bfloat162*)&g_at_h[idx0] = h0;
            *(__nv_bfloat162*)&g_at_l[idx0] = L0;
            *(__nv_bfloat162*)&g_at_h[idx1] = h1;
            *(__nv_bfloat162*)&g_at_l[idx1] = L1;
        }
    }
}

// ---------------------------------------------------------------------------
extern "C" void kernel_launch(void* const* d_in, const int* in_sizes, int n_in,
                              void* d_out, int out_size)
{
    const float* inputs_q = (const float*)d_in[0];
    const float* pos_emb  = (const float*)d_in[1];
    const float* r_w_bias = (const float*)d_in[2];
    const float* r_r_bias = (const float*)d_in[3];
    const float* Wq = (const float*)d_in[4];
    const float* bq = (const float*)d_in[5];
    const float* Wk = (const float*)d_in[6];
    const float* bk = (const float*)d_in[7];
    const float* Wv = (const float*)d_in[8];
    const float* bv = (const float*)d_in[9];
    const float* Wr = (const float*)d_in[10];
    const float* br = (const float*)d_in[11];
    const float* Wo = (const float*)d_in[12];
    const float* bo = (const float*)d_in[13];
    float* out = (float*)d_out;

    cudaFuncSetAttribute(attn_kernel,
                         cudaFuncAttributeMaxDynamicSharedMemorySize, SMEM_ATTN);
    cudaFuncSetAttribute(proj_bf_kernel,
                         cudaFuncAttributeMaxDynamicSharedMemorySize, GEMM_SMEM_BYTES);
    cudaFuncSetAttribute(out_bf_kernel,
                         cudaFuncAttributeMaxDynamicSharedMemorySize, GEMM_SMEM_BYTES);

    split_kernel<<<(2 * 524288 + 5 * 262144) / 256, 256>>>(
        inputs_q, pos_emb, Wq, Wk, Wv, Wr, Wo);

    proj_bf_kernel<<<dim3(NHD / 128, S / 128, 4), 256, GEMM_SMEM_BYTES>>>(
        bq, bk, bv, br);

    bias_dots_kernel<<<(2 * H * S * 32) / 256, 256>>>(r_w_bias, r_r_bias);

    attn_kernel<<<dim3(S / 64, H), 256, SMEM_ATTN>>>();

    out_bf_kernel<<<dim3(F / 128, S / 128), 256, GEMM_SMEM_BYTES>>>(bo, out);
}

// round 12
// speedup vs baseline: 8.6362x; 1.1775x over previous
#include <cuda_runtime.h>
#include <cuda_bf16.h>
#include <cuda_fp16.h>

#define S 2048
#define F 1024
#define H 16
#define DH 64
#define NHD 1024  // H*DH

typedef unsigned long long u64;
typedef unsigned int u32;

#define LOG2E 1.4426950408889634f
#define SCQ (0.125f * LOG2E)   // folded softmax scale + log2 conversion

// ---- f16 mma ----
__device__ __forceinline__ void mma_f16(float c[4], const u32 a[4], u32 b0, u32 b1) {
    asm volatile(
        "mma.sync.aligned.m16n8k16.row.col.f32.f16.f16.f32 "
        "{%0,%1,%2,%3}, {%4,%5,%6,%7}, {%8,%9}, {%0,%1,%2,%3};\n"
        : "+f"(c[0]), "+f"(c[1]), "+f"(c[2]), "+f"(c[3])
        : "r"(a[0]), "r"(a[1]), "r"(a[2]), "r"(a[3]), "r"(b0), "r"(b1));
}

__device__ __forceinline__ u32 exp2_f16x2(float ylo, float yhi) {
    __half2 h = __floats2half2_rn(ylo, yhi);
    __half2 r = h2exp2(h);
    return *(u32*)&r;
}

__device__ __forceinline__ void ldm2t(u32& d0, u32& d1, u32 saddr) {
    asm volatile("ldmatrix.sync.aligned.m8n8.x2.trans.shared.b16 {%0,%1}, [%2];"
                 : "=r"(d0), "=r"(d1) : "r"(saddr));
}
__device__ __forceinline__ void ldm2(u32& d0, u32& d1, u32 saddr) {
    asm volatile("ldmatrix.sync.aligned.m8n8.x2.shared.b16 {%0,%1}, [%2];"
                 : "=r"(d0), "=r"(d1) : "r"(saddr));
}
__device__ __forceinline__ u32 sptr(const void* p) {
    return (u32)__cvta_generic_to_shared(p);
}
__device__ __forceinline__ void pair_bar(int wp) {
    asm volatile("bar.sync %0, 64;" :: "r"(1 + wp) : "memory");
}
// ---- cp.async (global -> shared, 16B) ----
__device__ __forceinline__ void cpa16(u32 dst, const void* src) {
    asm volatile("cp.async.ca.shared.global [%0], [%1], 16;"
                 :: "r"(dst), "l"(src) : "memory");
}
#define CP_COMMIT() asm volatile("cp.async.commit_group;" ::: "memory")
#define CP_WAIT0()  asm volatile("cp.async.wait_group 0;" ::: "memory")

// Scratch (device globals: allocation-free per harness rules)
__device__ float g_k[S * NHD];   // fp32 for bias_dots
__device__ float g_r[S * NHD];   // fp32 for bias_dots
__device__ float g_ck[H * S];
__device__ float g_cr[H * S];
// f16 attention operands (emitted by proj epilogue)
__device__ __half g_q16[S * NHD];   // pre-scaled by SCQ
__device__ __half g_k16[S * NHD];
__device__ __half g_v16[S * NHD];
__device__ __half g_r16[S * NHD];
// f16 GEMM panels: activations hi/lo, weights single
__device__ __half g_xq_h[S * F],  g_xq_l[S * F];
__device__ __half g_xr_h[S * F],  g_xr_l[S * F];
__device__ __half g_w16[5 * F * NHD];             // Wq,Wk,Wv,Wr,Wo
__device__ __half g_at_h[S * NHD], g_at_l[S * NHD];

// ---------------------------------------------------------------------------
// Convert fp32 operands: activations -> f16 (hi, lo); weights -> f16.
// float4 segments: xq [0,524288), xr [524288,1048576), w0..w4 262144 each.
// ---------------------------------------------------------------------------
__global__ __launch_bounds__(256) void split_kernel(
    const float* __restrict__ xq, const float* __restrict__ xr,
    const float* __restrict__ w0, const float* __restrict__ w1,
    const float* __restrict__ w2, const float* __restrict__ w3,
    const float* __restrict__ w4)
{
    const int i = blockIdx.x * 256 + threadIdx.x;
    if (i < 1048576) {
        const float* src = (i < 524288) ? xq : xr;
        __half* h = (i < 524288) ? g_xq_h : g_xr_h;
        __half* l = (i < 524288) ? g_xq_l : g_xr_l;
        const int off = i & 524287;
        float4 v = ((const float4*)src)[off];
        __half2 h0 = __floats2half2_rn(v.x, v.y);
        __half2 h1 = __floats2half2_rn(v.z, v.w);
        float2 f0 = __half22float2(h0);
        float2 f1 = __half22float2(h1);
        __half2 l0 = __floats2half2_rn(v.x - f0.x, v.y - f0.y);
        __half2 l1 = __floats2half2_rn(v.z - f1.x, v.w - f1.y);
        ((__half2*)h)[off * 2]     = h0;
        ((__half2*)h)[off * 2 + 1] = h1;
        ((__half2*)l)[off * 2]     = l0;
        ((__half2*)l)[off * 2 + 1] = l1;
    } else {
        const int j = i - 1048576;
        const int w = j >> 18;
        const int off = j & 262143;
        const float* ws[5] = {w0, w1, w2, w3, w4};
        float4 v = ((const float4*)ws[w])[off];
        __half2* dst = (__half2*)(g_w16 + (size_t)w * (F * NHD));
        dst[off * 2]     = __floats2half2_rn(v.x, v.y);
        dst[off * 2 + 1] = __floats2half2_rn(v.z, v.w);
    }
}

// ---------------------------------------------------------------------------
// f16 GEMM: C = (Ah + Al) @ B + bias   (2 MMAs per k16)
// CTA 128x128, 8 warps (4m x 2n), K-chunk 32, double-buffered cp.async.
// smem halves: As_h[2][128*40] @0, As_l @10240, Bs[2][32*136] @20480.
// ---------------------------------------------------------------------------
#define GEMM_SMEM_BYTES 58368

__device__ __forceinline__ void gemm_f16_body(
    const __half* __restrict__ Ah, const __half* __restrict__ Al,
    const __half* __restrict__ B,
    const float* __restrict__ bias, float* __restrict__ C,
    __half* __restrict__ C16, float scale,
    int M, int N, int K)
{
    extern __shared__ __half sh[];
    __half* As_h = sh;
    __half* As_l = sh + 10240;
    __half* Bs   = sh + 20480;

    const int t    = threadIdx.x;
    const int lane = t & 31;
    const int w    = t >> 5;
    const int wm   = (w & 3) * 32;
    const int wn   = (w >> 2) * 64;
    const int g    = lane >> 2;
    const int tg   = lane & 3;
    const int m0   = blockIdx.y * 128;
    const int n0   = blockIdx.x * 128;

    float Cr[2][8][4];
#pragma unroll
    for (int mt = 0; mt < 2; mt++)
#pragma unroll
        for (int nt = 0; nt < 8; nt++) {
            Cr[mt][nt][0] = 0.f; Cr[mt][nt][1] = 0.f;
            Cr[mt][nt][2] = 0.f; Cr[mt][nt][3] = 0.f;
        }

    const int fm = t >> 1, fh = (t & 1) * 16;
    const int fk = t >> 3, fv = (t & 7) * 16;

    const __half* gAh = Ah + (size_t)(m0 + fm) * K + fh;
    const __half* gAl = Al + (size_t)(m0 + fm) * K + fh;
    const __half* gB  = B  + (size_t)fk * N + n0 + fv;

    const int sa_off = fm * 40 + fh;
    const int sb_off = fk * 136 + fv;

    {
        u32 d;
        d = sptr(As_h + sa_off); cpa16(d, gAh); cpa16(d + 16, gAh + 8);
        d = sptr(As_l + sa_off); cpa16(d, gAl); cpa16(d + 16, gAl + 8);
        d = sptr(Bs + sb_off);   cpa16(d, gB);  cpa16(d + 16, gB + 8);
        CP_COMMIT();
        CP_WAIT0();
    }
    __syncthreads();

    int buf = 0;
    const int nkc = K / 32;
    for (int kc = 0; kc < nkc; kc++) {
        const bool has = (kc + 1) < nkc;
        if (has) {
            const __half* pAh = gAh + (kc + 1) * 32;
            const __half* pAl = gAl + (kc + 1) * 32;
            const __half* pB  = gB + (size_t)(kc + 1) * 32 * N;
            const int nb = buf ^ 1;
            u32 d;
            d = sptr(As_h + nb * 5120 + sa_off); cpa16(d, pAh); cpa16(d + 16, pAh + 8);
            d = sptr(As_l + nb * 5120 + sa_off); cpa16(d, pAl); cpa16(d + 16, pAl + 8);
            d = sptr(Bs + nb * 4352 + sb_off);   cpa16(d, pB);  cpa16(d + 16, pB + 8);
            CP_COMMIT();
        }
        const __half* Ab_h = As_h + buf * 5120;
        const __half* Ab_l = As_l + buf * 5120;
        const __half* Bb   = Bs + buf * 4352;

#pragma unroll
        for (int ks2 = 0; ks2 < 2; ks2++) {
            const int ks = ks2 * 16;
            u32 ah[2][4], al[2][4];
#pragma unroll
            for (int mt = 0; mt < 2; mt++) {
                const __half* r0 = Ab_h + (wm + mt * 16 + g) * 40 + ks + 2 * tg;
                ah[mt][0] = *(const u32*)r0;
                ah[mt][1] = *(const u32*)(r0 + 8 * 40);
                ah[mt][2] = *(const u32*)(r0 + 8);
                ah[mt][3] = *(const u32*)(r0 + 8 * 40 + 8);
                const __half* r1 = Ab_l + (wm + mt * 16 + g) * 40 + ks + 2 * tg;
                al[mt][0] = *(const u32*)r1;
                al[mt][1] = *(const u32*)(r1 + 8 * 40);
                al[mt][2] = *(const u32*)(r1 + 8);
                al[mt][3] = *(const u32*)(r1 + 8 * 40 + 8);
            }
            const u32 bb = sptr(Bb + (ks + (lane & 15)) * 136 + wn);
#pragma unroll
            for (int nt = 0; nt < 8; nt++) {
                u32 b0, b1;
                ldm2t(b0, b1, bb + nt * 16);
#pragma unroll
                for (int mt = 0; mt < 2; mt++) {
                    mma_f16(Cr[mt][nt], ah[mt], b0, b1);
                    mma_f16(Cr[mt][nt], al[mt], b0, b1);
                }
            }
        }

        if (has) {
            CP_WAIT0();
            __syncthreads();
            buf ^= 1;
        }
    }

#pragma unroll
    for (int mt = 0; mt < 2; mt++) {
        const int row = m0 + wm + mt * 16 + g;
#pragma unroll
        for (int nt = 0; nt < 8; nt++) {
            const int col = n0 + wn + nt * 8 + 2 * tg;
            float2 b01 = *(const float2*)&bias[col];
            const float v00 = Cr[mt][nt][0] + b01.x;
            const float v01 = Cr[mt][nt][1] + b01.y;
            const float v10 = Cr[mt][nt][2] + b01.x;
            const float v11 = Cr[mt][nt][3] + b01.y;
            if (C) {
                *(float2*)(C + (size_t)row * N + col)       = make_float2(v00, v01);
                *(float2*)(C + (size_t)(row + 8) * N + col) = make_float2(v10, v11);
            }
            if (C16) {
                *(__half2*)(C16 + (size_t)row * N + col) =
                    __floats2half2_rn(v00 * scale, v01 * scale);
                *(__half2*)(C16 + (size_t)(row + 8) * N + col) =
                    __floats2half2_rn(v10 * scale, v11 * scale);
            }
        }
    }
}

__global__ __launch_bounds__(256, 2) void proj_f16_kernel(
    const float* __restrict__ bq, const float* __restrict__ bk,
    const float* __restrict__ bv, const float* __restrict__ br)
{
    const int z = blockIdx.z;
    const __half* Ah = (z < 3) ? g_xq_h : g_xr_h;
    const __half* Al = (z < 3) ? g_xq_l : g_xr_l;
    const __half* B  = g_w16 + (size_t)z * (F * NHD);
    const float* bias;
    float* C;
    __half* C16;
    float scale = 1.f;
    switch (z) {
        case 0:  bias = bq; C = nullptr; C16 = g_q16; scale = SCQ; break;
        case 1:  bias = bk; C = g_k;     C16 = g_k16; break;
        case 2:  bias = bv; C = nullptr; C16 = g_v16; break;
        default: bias = br; C = g_r;     C16 = g_r16; break;
    }
    gemm_f16_body(Ah, Al, B, bias, C, C16, scale, S, NHD, F);
}

__global__ __launch_bounds__(256, 2) void out_f16_kernel(
    const float* __restrict__ bo, float* __restrict__ out)
{
    gemm_f16_body(g_at_h, g_at_l, g_w16 + (size_t)4 * (F * NHD),
                  bo, out, nullptr, 1.f, S, F, NHD);
}

// ---------------------------------------------------------------------------
// ck[h][j] = SCQ * rw[h].k[j,h,:],  cr[h][m] = SCQ * rr[h].r[m,h,:]
// ---------------------------------------------------------------------------
__global__ __launch_bounds__(256) void bias_dots_kernel(
    const float* __restrict__ rwb, const float* __restrict__ rrb)
{
    const int gw   = (blockIdx.x * blockDim.x + threadIdx.x) >> 5;
    const int lane = threadIdx.x & 31;
    const int which = gw >= H * S;
    const int idx   = which ? gw - H * S : gw;
    const int hh = idx >> 11;
    const int j  = idx & (S - 1);
    const float* bias = which ? rrb : rwb;
    const float* mat  = which ? g_r : g_k;
    const float b0 = bias[hh * DH + lane];
    const float b1 = bias[hh * DH + 32 + lane];
    const float* row = mat + (size_t)j * NHD + hh * DH;
    float s = fmaf(b0, row[lane], b1 * row[32 + lane]);
#pragma unroll
    for (int off = 16; off > 0; off >>= 1)
        s += __shfl_xor_sync(0xffffffffu, s, off);
    if (lane == 0) {
        float* dst = which ? g_cr : g_ck;
        dst[hh * S + j] = s * SCQ;
    }
}

// ---------------------------------------------------------------------------
// Causal flash attention, all-f16 MMA (k16), log2-domain softmax (unchanged
// from R11 except the epilogue now emits f16 hi/lo panels for out GEMM).
// ---------------------------------------------------------------------------
#define KP16 72
#define GPAD 132
#define PP16 (GPAD * 2)  // P f16 pitch inside G rows
#define SMEM_ATTN ((64*KP16 + 64*KP16 + 128*KP16)*2 + (64*GPAD)*4 + (128+64+128)*4)

__global__ __launch_bounds__(256, 2) void attn_kernel()
{
    const int h   = blockIdx.y;
    const int qi0 = (gridDim.x - 1 - blockIdx.x) * 64;

    extern __shared__ float sm[];
    __half* ks16  = (__half*)sm;                      // 64 x KP16
    __half* vs16  = ks16 + 64 * KP16;                 // 64 x KP16 (+ ones col 64)
    __half* rsl16 = vs16 + 64 * KP16;                 // 128 x KP16 (circular)
    float*  G     = (float*)(rsl16 + 128 * KP16);     // 64 x GPAD; P (f16) reuses rows
    float*  crs_s = G + 64 * GPAD;                    // 128
    float*  cks_s = crs_s + 128;                      // 64
    float*  mx    = cks_s + 64;                       // 128

    const int t    = threadIdx.x;
    const int lane = t & 31;
    const int w    = t >> 5;
    const int wp   = w & 3;            // q-row group
    const int half = w >> 2;           // key-column half
    const int g    = lane >> 2;
    const int tg   = lane & 3;
    const int i0   = wp * 16 + g;
    const int hb   = h * DH;
    const int jbase = half * 32;
    const int tile0 = (half == 0) ? (6 - 2 * wp) : (11 - 2 * wp);

    // ---- persistent Q a-frags (f16, pre-scaled by SCQ) ----
    u32 qa[4][4];
    {
        const __half* q0 = &g_q16[(size_t)(qi0 + i0) * NHD + hb];
        const __half* q1 = q0 + 8 * NHD;
#pragma unroll
        for (int k0 = 0; k0 < 4; k0++) {
            qa[k0][0] = *(const u32*)(q0 + k0 * 16 + 2 * tg);
            qa[k0][1] = *(const u32*)(q1 + k0 * 16 + 2 * tg);
            qa[k0][2] = *(const u32*)(q0 + k0 * 16 + 8 + 2 * tg);
            qa[k0][3] = *(const u32*)(q1 + k0 * 16 + 8 + 2 * tg);
        }
    }

    // ones column for l (cols 64..71 of vs16; never touched by fills)
    if (t < 64) {
        __half* p = &vs16[t * KP16 + 64];
        p[0] = __float2half(1.f);
#pragma unroll
        for (int i = 1; i < 8; i++) p[i] = __float2half(0.f);
    }

    float O[9][4];   // [8] = l column
#pragma unroll
    for (int nt = 0; nt < 9; nt++) {
        O[nt][0] = 0.f; O[nt][1] = 0.f; O[nt][2] = 0.f; O[nt][3] = 0.f;
    }
    float m0 = -1e30f, m1 = -1e30f;

    const int nkt = qi0 / 64 + 1;
    for (int kt = 0; kt < nkt; kt++) {
        const int kj0   = kt * 64;
        const int base  = (S - 1) + kj0 - qi0 - 63;
        const int rbase = base & 127;
        __syncthreads();  // all consumers done before refill

        // ---- K + V fills (cp.async f16) ----
#pragma unroll
        for (int it = 0; it < 2; it++) {
            const int idx = t + it * 256;      // < 512
            const int r = idx >> 3, c8 = (idx & 7) << 3;
            cpa16(sptr(&ks16[r * KP16 + c8]),
                  &g_k16[(size_t)(kj0 + r) * NHD + hb + c8]);
            cpa16(sptr(&vs16[r * KP16 + c8]),
                  &g_v16[(size_t)(kj0 + r) * NHD + hb + c8]);
        }
        // ---- RSL (cp.async f16, circular): only new rows ----
        {
            const int rl0 = (kt == 0) ? 0 : 64;
            const int nit = (kt == 0) ? 4 : 2;
            for (int it = 0; it < nit; it++) {
                const int idx = t + it * 256;
                const int row = rl0 + (idx >> 3);
                const int c8  = (idx & 7) << 3;
                int mg = base + row;
                if (mg > S - 1) mg = S - 1;
                cpa16(sptr(&rsl16[((rbase + row) & 127) * KP16 + c8]),
                      &g_r16[(size_t)mg * NHD + hb + c8]);
            }
        }
        if (t < 64) cks_s[t] = g_ck[h * S + kj0 + t];
        else if (t < 192) {
            const int mm = t - 64;
            int mg = base + mm;
            if (mg > S - 1) mg = S - 1;
            crs_s[mm] = (mm < 127) ? g_cr[h * S + mg] : 0.f;
        }
        CP_COMMIT();
        CP_WAIT0();
        __syncthreads();

        // ---- windowed G = Q @ RSL^T (+cr): 5 tiles, f16 k16 ----
        {
            u32 rb[5];
#pragma unroll
            for (int ni = 0; ni < 5; ni++) {
                const int lrow = (rbase + (tile0 + ni) * 8 + (lane & 7)) & 127;
                rb[ni] = sptr(&rsl16[lrow * KP16 + ((lane >> 3) & 1) * 8]);
            }
            float gc[5][4];
#pragma unroll
            for (int ni = 0; ni < 5; ni++) {
                const int col = (tile0 + ni) * 8 + 2 * tg;
                gc[ni][0] = crs_s[col];
                gc[ni][1] = crs_s[col + 1];
                gc[ni][2] = gc[ni][0];
                gc[ni][3] = gc[ni][1];
            }
#pragma unroll
            for (int k0 = 0; k0 < 4; k0++) {
#pragma unroll
                for (int ni = 0; ni < 5; ni++) {
                    u32 b0, b1;
                    ldm2(b0, b1, rb[ni] + k0 * 32);
                    mma_f16(gc[ni], qa[k0], b0, b1);
                }
            }
#pragma unroll
            for (int ni = 0; ni < 5; ni++) {
                const int col = (tile0 + ni) * 8 + 2 * tg;
                *(float2*)&G[i0 * GPAD + col]       = make_float2(gc[ni][0], gc[ni][1]);
                *(float2*)&G[(i0 + 8) * GPAD + col] = make_float2(gc[ni][2], gc[ni][3]);
            }
        }
        pair_bar(wp);  // pair's G halves visible before gather

        // ---- AC = Q @ K^T (+ck), own 32-key half, f16 k16 ----
        float sc[4][4];
        u32 kb4[4];
#pragma unroll
        for (int nt = 0; nt < 4; nt++) {
            const int col = jbase + nt * 8 + 2 * tg;
            sc[nt][0] = cks_s[col];
            sc[nt][1] = cks_s[col + 1];
            sc[nt][2] = sc[nt][0];
            sc[nt][3] = sc[nt][1];
            kb4[nt] = sptr(&ks16[(jbase + nt * 8 + (lane & 7)) * KP16 +
                                 ((lane >> 3) & 1) * 8]);
        }
#pragma unroll
        for (int k0 = 0; k0 < 4; k0++) {
#pragma unroll
            for (int nt = 0; nt < 4; nt++) {
                u32 b0, b1;
                ldm2(b0, b1, kb4[nt] + k0 * 32);
                mma_f16(sc[nt], qa[k0], b0, b1);
            }
        }

        // ---- BD gather + mask + own-half row max (log2 domain) ----
        const bool diag = (kt == nkt - 1);
        float rmax0 = -1e30f, rmax1 = -1e30f;
#pragma unroll
        for (int nt = 0; nt < 4; nt++) {
            const int j = jbase + nt * 8 + 2 * tg;
            float s00 = sc[nt][0] + G[i0 * GPAD + 63 + j - i0];
            float s01 = sc[nt][1] + G[i0 * GPAD + 64 + j - i0];
            float s10 = sc[nt][2] + G[(i0 + 8) * GPAD + 55 + j - i0];
            float s11 = sc[nt][3] + G[(i0 + 8) * GPAD + 56 + j - i0];
            if (diag) {
                if (kj0 + j     > qi0 + i0)     s00 = -1e30f;
                if (kj0 + j + 1 > qi0 + i0)     s01 = -1e30f;
                if (kj0 + j     > qi0 + i0 + 8) s10 = -1e30f;
                if (kj0 + j + 1 > qi0 + i0 + 8) s11 = -1e30f;
            }
            sc[nt][0] = s00; sc[nt][1] = s01; sc[nt][2] = s10; sc[nt][3] = s11;
            rmax0 = fmaxf(rmax0, fmaxf(s00, s01));
            rmax1 = fmaxf(rmax1, fmaxf(s10, s11));
        }
        rmax0 = fmaxf(rmax0, __shfl_xor_sync(0xffffffffu, rmax0, 1));
        rmax0 = fmaxf(rmax0, __shfl_xor_sync(0xffffffffu, rmax0, 2));
        rmax1 = fmaxf(rmax1, __shfl_xor_sync(0xffffffffu, rmax1, 1));
        rmax1 = fmaxf(rmax1, __shfl_xor_sync(0xffffffffu, rmax1, 2));

        // exchange with partner half (also orders partner gather before P stores)
        mx[2 * i0 + half]       = rmax0;
        mx[2 * (i0 + 8) + half] = rmax1;
        pair_bar(wp);
        rmax0 = fmaxf(rmax0, mx[2 * i0 + (half ^ 1)]);
        rmax1 = fmaxf(rmax1, mx[2 * (i0 + 8) + (half ^ 1)]);

        const float newm0 = fmaxf(m0, rmax0);
        const float newm1 = fmaxf(m1, rmax1);
        const float a0 = exp2f(m0 - newm0);
        const float a1 = exp2f(m1 - newm1);
        m0 = newm0; m1 = newm1;
#pragma unroll
        for (int nt = 0; nt < 9; nt++) {
            O[nt][0] *= a0; O[nt][1] *= a0;
            O[nt][2] *= a1; O[nt][3] *= a1;
        }

        // ---- p = 2^(s-m) via f16x2 MUFU; store packed-f16 P ----
        __half* psb16 = (__half*)G;
#pragma unroll
        for (int nt = 0; nt < 4; nt++) {
            const int col = jbase + nt * 8 + 2 * tg;
            u32 p01 = exp2_f16x2(sc[nt][0] - m0, sc[nt][1] - m0);
            u32 p23 = exp2_f16x2(sc[nt][2] - m1, sc[nt][3] - m1);
            *(u32*)&psb16[i0 * PP16 + col]       = p01;
            *(u32*)&psb16[(i0 + 8) * PP16 + col] = p23;
        }
        __syncwarp();  // P rows/cols are warp-private

        // ---- PV (f16 k16): O += P_half @ [V | 1], l rides in n-tile 8 ----
#pragma unroll
        for (int ki = 0; ki < 2; ki++) {
            const int kb = jbase + ki * 16;
            u32 pa[4];
            pa[0] = *(const u32*)&psb16[i0 * PP16 + kb + 2 * tg];
            pa[1] = *(const u32*)&psb16[(i0 + 8) * PP16 + kb + 2 * tg];
            pa[2] = *(const u32*)&psb16[i0 * PP16 + kb + 8 + 2 * tg];
            pa[3] = *(const u32*)&psb16[(i0 + 8) * PP16 + kb + 8 + 2 * tg];
            const u32 vb = sptr(vs16 + (size_t)(kb + (lane & 15)) * KP16);
#pragma unroll
            for (int nt = 0; nt < 9; nt++) {
                u32 b0, b1;
                ldm2t(b0, b1, vb + nt * 16);
                mma_f16(O[nt], pa, b0, b1);
            }
        }
    }

    // ---- extract l (ones-column accumulator, tg==0 lanes own it) ----
    float l0 = __shfl_sync(0xffffffffu, O[8][0], lane & 28);
    float l1 = __shfl_sync(0xffffffffu, O[8][2], lane & 28);

    // ---- merge the two key-halves (same m-sequence -> plain sums) ----
    __syncthreads();
    if (half == 1) {
#pragma unroll
        for (int nt = 0; nt < 8; nt++) {
            const int col = nt * 8 + 2 * tg;
            *(float2*)&G[i0 * GPAD + col]       = make_float2(O[nt][0], O[nt][1]);
            *(float2*)&G[(i0 + 8) * GPAD + col] = make_float2(O[nt][2], O[nt][3]);
        }
        if (tg == 0) {
            cks_s[i0]     = l0;
            cks_s[i0 + 8] = l1;
        }
    }
    __syncthreads();
    if (half == 0) {
        l0 += cks_s[i0];
        l1 += cks_s[i0 + 8];
        const float inv0 = 1.f / l0;
        const float inv1 = 1.f / l1;
#pragma unroll
        for (int nt = 0; nt < 8; nt++) {
            const int col = nt * 8 + 2 * tg;
            float2 p0 = *(const float2*)&G[i0 * GPAD + col];
            float2 p1 = *(const float2*)&G[(i0 + 8) * GPAD + col];
            float o00 = (O[nt][0] + p0.x) * inv0, o01 = (O[nt][1] + p0.y) * inv0;
            float o10 = (O[nt][2] + p1.x) * inv1, o11 = (O[nt][3] + p1.y) * inv1;
            const size_t idx0 = (size_t)(qi0 + i0) * NHD + hb + col;
            const size_t idx1 = (size_t)(qi0 + i0 + 8) * NHD + hb + col;
            __half2 h0 = __floats2half2_rn(o00, o01);
            __half2 h1 = __floats2half2_rn(o10, o11);
            float2 f0 = __half22float2(h0);
            float2 f1 = __half22float2(h1);
            __half2 L0 = __floats2half2_rn(o00 - f0.x, o01 - f0.y);
            __half2 L1 = __floats2half2_rn(o10 - f1.x, o11 - f1.y);
            *(__half2*)&g_at_h[idx0] = h0;
            *(__half2*)&g_at_l[idx0] = L0;
            *(__half2*)&g_at_h[idx1] = h1;
            *(__half2*)&g_at_l[idx1] = L1;
        }
    }
}

// ---------------------------------------------------------------------------
extern "C" void kernel_launch(void* const* d_in, const int* in_sizes, int n_in,
                              void* d_out, int out_size)
{
    const float* inputs_q = (const float*)d_in[0];
    const float* pos_emb  = (const float*)d_in[1];
    const float* r_w_bias = (const float*)d_in[2];
    const float* r_r_bias = (const float*)d_in[3];
    const float* Wq = (const float*)d_in[4];
    const float* bq = (const float*)d_in[5];
    const float* Wk = (const float*)d_in[6];
    const float* bk = (const float*)d_in[7];
    const float* Wv = (const float*)d_in[8];
    const float* bv = (const float*)d_in[9];
    const float* Wr = (const float*)d_in[10];
    const float* br = (const float*)d_in[11];
    const float* Wo = (const float*)d_in[12];
    const float* bo = (const float*)d_in[13];
    float* out = (float*)d_out;

    cudaFuncSetAttribute(attn_kernel,
                         cudaFuncAttributeMaxDynamicSharedMemorySize, SMEM_ATTN);
    cudaFuncSetAttribute(proj_f16_kernel,
                         cudaFuncAttributeMaxDynamicSharedMemorySize, GEMM_SMEM_BYTES);
    cudaFuncSetAttribute(out_f16_kernel,
                         cudaFuncAttributeMaxDynamicSharedMemorySize, GEMM_SMEM_BYTES);

    split_kernel<<<(2 * 524288 + 5 * 262144) / 256, 256>>>(
        inputs_q, pos_emb, Wq, Wk, Wv, Wr, Wo);

    proj_f16_kernel<<<dim3(NHD / 128, S / 128, 4), 256, GEMM_SMEM_BYTES>>>(
        bq, bk, bv, br);

    bias_dots_kernel<<<(2 * H * S * 32) / 256, 256>>>(r_w_bias, r_r_bias);

    attn_kernel<<<dim3(S / 64, H), 256, SMEM_ATTN>>>();

    out_f16_kernel<<<dim3(F / 128, S / 128), 256, GEMM_SMEM_BYTES>>>(bo, out);
}

// round 13
// speedup vs baseline: 10.1932x; 1.1803x over previous
#include <cuda_runtime.h>
#include <cuda_bf16.h>
#include <cuda_fp16.h>

#define S 2048
#define F 1024
#define H 16
#define DH 64
#define NHD 1024  // H*DH

typedef unsigned long long u64;
typedef unsigned int u32;

#define LOG2E 1.4426950408889634f
#define SCQ (0.125f * LOG2E)   // folded softmax scale + log2 conversion

// ---- f16 mma ----
__device__ __forceinline__ void mma_f16(float c[4], const u32 a[4], u32 b0, u32 b1) {
    asm volatile(
        "mma.sync.aligned.m16n8k16.row.col.f32.f16.f16.f32 "
        "{%0,%1,%2,%3}, {%4,%5,%6,%7}, {%8,%9}, {%0,%1,%2,%3};\n"
        : "+f"(c[0]), "+f"(c[1]), "+f"(c[2]), "+f"(c[3])
        : "r"(a[0]), "r"(a[1]), "r"(a[2]), "r"(a[3]), "r"(b0), "r"(b1));
}

__device__ __forceinline__ u32 exp2_f16x2(float ylo, float yhi) {
    __half2 h = __floats2half2_rn(ylo, yhi);
    __half2 r = h2exp2(h);
    return *(u32*)&r;
}

__device__ __forceinline__ void ldm2t(u32& d0, u32& d1, u32 saddr) {
    asm volatile("ldmatrix.sync.aligned.m8n8.x2.trans.shared.b16 {%0,%1}, [%2];"
                 : "=r"(d0), "=r"(d1) : "r"(saddr));
}
__device__ __forceinline__ void ldm2(u32& d0, u32& d1, u32 saddr) {
    asm volatile("ldmatrix.sync.aligned.m8n8.x2.shared.b16 {%0,%1}, [%2];"
                 : "=r"(d0), "=r"(d1) : "r"(saddr));
}
__device__ __forceinline__ u32 sptr(const void* p) {
    return (u32)__cvta_generic_to_shared(p);
}
__device__ __forceinline__ void pair_bar(int wp) {
    asm volatile("bar.sync %0, 64;" :: "r"(1 + wp) : "memory");
}
// ---- cp.async (global -> shared, 16B) ----
__device__ __forceinline__ void cpa16(u32 dst, const void* src) {
    asm volatile("cp.async.ca.shared.global [%0], [%1], 16;"
                 :: "r"(dst), "l"(src) : "memory");
}
#define CP_COMMIT() asm volatile("cp.async.commit_group;" ::: "memory")
#define CP_WAIT0()  asm volatile("cp.async.wait_group 0;" ::: "memory")

// Scratch (device globals: allocation-free per harness rules)
__device__ float g_k[S * NHD];   // fp32 for bias_dots
__device__ float g_r[S * NHD];   // fp32 for bias_dots
__device__ float g_ck[H * S];
__device__ float g_cr[H * S];
// f16 attention operands (emitted by proj epilogue)
__device__ __half g_q16[S * NHD];   // pre-scaled by SCQ
__device__ __half g_k16[S * NHD];
__device__ __half g_v16[S * NHD];
__device__ __half g_r16[S * NHD];
// f16 GEMM panels
__device__ __half g_xq[S * F];
__device__ __half g_xr[S * F];
__device__ __half g_w16[5 * F * NHD];             // Wq,Wk,Wv,Wr,Wo
__device__ __half g_at_h[S * NHD], g_at_l[S * NHD];

// ---------------------------------------------------------------------------
// Convert fp32 operands -> f16 panels.
// float4 segments: xq [0,524288), xr [524288,1048576), w0..w4 262144 each.
// ---------------------------------------------------------------------------
__global__ __launch_bounds__(256) void split_kernel(
    const float* __restrict__ xq, const float* __restrict__ xr,
    const float* __restrict__ w0, const float* __restrict__ w1,
    const float* __restrict__ w2, const float* __restrict__ w3,
    const float* __restrict__ w4)
{
    const int i = blockIdx.x * 256 + threadIdx.x;
    const float* src;
    __half* dst;
    int off;
    if (i < 1048576) {
        src = (i < 524288) ? xq : xr;
        dst = (i < 524288) ? g_xq : g_xr;
        off = i & 524287;
    } else {
        const int j = i - 1048576;
        const int w = j >> 18;
        off = j & 262143;
        const float* ws[5] = {w0, w1, w2, w3, w4};
        src = ws[w];
        dst = g_w16 + (size_t)w * (F * NHD);
    }
    float4 v = ((const float4*)src)[off];
    ((__half2*)dst)[off * 2]     = __floats2half2_rn(v.x, v.y);
    ((__half2*)dst)[off * 2 + 1] = __floats2half2_rn(v.z, v.w);
}

// ---------------------------------------------------------------------------
// f16 GEMM: C = (Ah [+ Al]) @ B + bias
// CTA 128x128, 8 warps (4m x 2n), K-chunk 32, double-buffered cp.async.
// SPLIT_A=false: 1 MMA per k16 (proj; outputs rounded to f16 anyway).
// SPLIT_A=true : 2 MMAs per k16 (output projection; final accuracy).
// smem: As_h[2][128*40] @0, As_l @10240, Bs[2][32*136] @20480.
// ---------------------------------------------------------------------------
#define GEMM_SMEM_BYTES 58368

template <bool SPLIT_A>
__device__ __forceinline__ void gemm_f16_body(
    const __half* __restrict__ Ah, const __half* __restrict__ Al,
    const __half* __restrict__ B,
    const float* __restrict__ bias, float* __restrict__ C,
    __half* __restrict__ C16, float scale,
    int M, int N, int K)
{
    extern __shared__ __half sh[];
    __half* As_h = sh;
    __half* As_l = sh + 10240;
    __half* Bs   = sh + 20480;

    const int t    = threadIdx.x;
    const int lane = t & 31;
    const int w    = t >> 5;
    const int wm   = (w & 3) * 32;
    const int wn   = (w >> 2) * 64;
    const int g    = lane >> 2;
    const int tg   = lane & 3;
    const int m0   = blockIdx.y * 128;
    const int n0   = blockIdx.x * 128;

    float Cr[2][8][4];
#pragma unroll
    for (int mt = 0; mt < 2; mt++)
#pragma unroll
        for (int nt = 0; nt < 8; nt++) {
            Cr[mt][nt][0] = 0.f; Cr[mt][nt][1] = 0.f;
            Cr[mt][nt][2] = 0.f; Cr[mt][nt][3] = 0.f;
        }

    const int fm = t >> 1, fh = (t & 1) * 16;
    const int fk = t >> 3, fv = (t & 7) * 16;

    const __half* gAh = Ah + (size_t)(m0 + fm) * K + fh;
    const __half* gAl = SPLIT_A ? Al + (size_t)(m0 + fm) * K + fh : nullptr;
    const __half* gB  = B  + (size_t)fk * N + n0 + fv;

    const int sa_off = fm * 40 + fh;
    const int sb_off = fk * 136 + fv;

    {
        u32 d;
        d = sptr(As_h + sa_off); cpa16(d, gAh); cpa16(d + 16, gAh + 8);
        if (SPLIT_A) {
            d = sptr(As_l + sa_off); cpa16(d, gAl); cpa16(d + 16, gAl + 8);
        }
        d = sptr(Bs + sb_off);   cpa16(d, gB);  cpa16(d + 16, gB + 8);
        CP_COMMIT();
        CP_WAIT0();
    }
    __syncthreads();

    int buf = 0;
    const int nkc = K / 32;
    for (int kc = 0; kc < nkc; kc++) {
        const bool has = (kc + 1) < nkc;
        if (has) {
            const __half* pAh = gAh + (kc + 1) * 32;
            const __half* pB  = gB + (size_t)(kc + 1) * 32 * N;
            const int nb = buf ^ 1;
            u32 d;
            d = sptr(As_h + nb * 5120 + sa_off); cpa16(d, pAh); cpa16(d + 16, pAh + 8);
            if (SPLIT_A) {
                const __half* pAl = gAl + (kc + 1) * 32;
                d = sptr(As_l + nb * 5120 + sa_off); cpa16(d, pAl); cpa16(d + 16, pAl + 8);
            }
            d = sptr(Bs + nb * 4352 + sb_off);   cpa16(d, pB);  cpa16(d + 16, pB + 8);
            CP_COMMIT();
        }
        const __half* Ab_h = As_h + buf * 5120;
        const __half* Ab_l = As_l + buf * 5120;
        const __half* Bb   = Bs + buf * 4352;

#pragma unroll
        for (int ks2 = 0; ks2 < 2; ks2++) {
            const int ks = ks2 * 16;
            u32 ah[2][4], al[2][4];
#pragma unroll
            for (int mt = 0; mt < 2; mt++) {
                const __half* r0 = Ab_h + (wm + mt * 16 + g) * 40 + ks + 2 * tg;
                ah[mt][0] = *(const u32*)r0;
                ah[mt][1] = *(const u32*)(r0 + 8 * 40);
                ah[mt][2] = *(const u32*)(r0 + 8);
                ah[mt][3] = *(const u32*)(r0 + 8 * 40 + 8);
                if (SPLIT_A) {
                    const __half* r1 = Ab_l + (wm + mt * 16 + g) * 40 + ks + 2 * tg;
                    al[mt][0] = *(const u32*)r1;
                    al[mt][1] = *(const u32*)(r1 + 8 * 40);
                    al[mt][2] = *(const u32*)(r1 + 8);
                    al[mt][3] = *(const u32*)(r1 + 8 * 40 + 8);
                }
            }
            const u32 bb = sptr(Bb + (ks + (lane & 15)) * 136 + wn);
#pragma unroll
            for (int nt = 0; nt < 8; nt++) {
                u32 b0, b1;
                ldm2t(b0, b1, bb + nt * 16);
#pragma unroll
                for (int mt = 0; mt < 2; mt++) {
                    mma_f16(Cr[mt][nt], ah[mt], b0, b1);
                    if (SPLIT_A) mma_f16(Cr[mt][nt], al[mt], b0, b1);
                }
            }
        }

        if (has) {
            CP_WAIT0();
            __syncthreads();
            buf ^= 1;
        }
    }

#pragma unroll
    for (int mt = 0; mt < 2; mt++) {
        const int row = m0 + wm + mt * 16 + g;
#pragma unroll
        for (int nt = 0; nt < 8; nt++) {
            const int col = n0 + wn + nt * 8 + 2 * tg;
            float2 b01 = *(const float2*)&bias[col];
            const float v00 = Cr[mt][nt][0] + b01.x;
            const float v01 = Cr[mt][nt][1] + b01.y;
            const float v10 = Cr[mt][nt][2] + b01.x;
            const float v11 = Cr[mt][nt][3] + b01.y;
            if (C) {
                *(float2*)(C + (size_t)row * N + col)       = make_float2(v00, v01);
                *(float2*)(C + (size_t)(row + 8) * N + col) = make_float2(v10, v11);
            }
            if (C16) {
                *(__half2*)(C16 + (size_t)row * N + col) =
                    __floats2half2_rn(v00 * scale, v01 * scale);
                *(__half2*)(C16 + (size_t)(row + 8) * N + col) =
                    __floats2half2_rn(v10 * scale, v11 * scale);
            }
        }
    }
}

__global__ __launch_bounds__(256, 2) void proj_f16_kernel(
    const float* __restrict__ bq, const float* __restrict__ bk,
    const float* __restrict__ bv, const float* __restrict__ br)
{
    const int z = blockIdx.z;
    const __half* A = (z < 3) ? g_xq : g_xr;
    const __half* B = g_w16 + (size_t)z * (F * NHD);
    const float* bias;
    float* C;
    __half* C16;
    float scale = 1.f;
    switch (z) {
        case 0:  bias = bq; C = nullptr; C16 = g_q16; scale = SCQ; break;
        case 1:  bias = bk; C = g_k;     C16 = g_k16; break;
        case 2:  bias = bv; C = nullptr; C16 = g_v16; break;
        default: bias = br; C = g_r;     C16 = g_r16; break;
    }
    gemm_f16_body<false>(A, nullptr, B, bias, C, C16, scale, S, NHD, F);
}

__global__ __launch_bounds__(256, 2) void out_f16_kernel(
    const float* __restrict__ bo, float* __restrict__ out)
{
    gemm_f16_body<true>(g_at_h, g_at_l, g_w16 + (size_t)4 * (F * NHD),
                        bo, out, nullptr, 1.f, S, F, NHD);
}

// ---------------------------------------------------------------------------
// ck[h][j] = SCQ * rw[h].k[j,h,:],  cr[h][m] = SCQ * rr[h].r[m,h,:]
// ---------------------------------------------------------------------------
__global__ __launch_bounds__(256) void bias_dots_kernel(
    const float* __restrict__ rwb, const float* __restrict__ rrb)
{
    const int gw   = (blockIdx.x * blockDim.x + threadIdx.x) >> 5;
    const int lane = threadIdx.x & 31;
    const int which = gw >= H * S;
    const int idx   = which ? gw - H * S : gw;
    const int hh = idx >> 11;
    const int j  = idx & (S - 1);
    const float* bias = which ? rrb : rwb;
    const float* mat  = which ? g_r : g_k;
    const float b0 = bias[hh * DH + lane];
    const float b1 = bias[hh * DH + 32 + lane];
    const float* row = mat + (size_t)j * NHD + hh * DH;
    float s = fmaf(b0, row[lane], b1 * row[32 + lane]);
#pragma unroll
    for (int off = 16; off > 0; off >>= 1)
        s += __shfl_xor_sync(0xffffffffu, s, off);
    if (lane == 0) {
        float* dst = which ? g_cr : g_ck;
        dst[hh * S + j] = s * SCQ;
    }
}

// ---------------------------------------------------------------------------
// Causal flash attention, all-f16 MMA (k16), log2-domain softmax.
// (unchanged from R12)
// ---------------------------------------------------------------------------
#define KP16 72
#define GPAD 132
#define PP16 (GPAD * 2)  // P f16 pitch inside G rows
#define SMEM_ATTN ((64*KP16 + 64*KP16 + 128*KP16)*2 + (64*GPAD)*4 + (128+64+128)*4)

__global__ __launch_bounds__(256, 2) void attn_kernel()
{
    const int h   = blockIdx.y;
    const int qi0 = (gridDim.x - 1 - blockIdx.x) * 64;

    extern __shared__ float sm[];
    __half* ks16  = (__half*)sm;                      // 64 x KP16
    __half* vs16  = ks16 + 64 * KP16;                 // 64 x KP16 (+ ones col 64)
    __half* rsl16 = vs16 + 64 * KP16;                 // 128 x KP16 (circular)
    float*  G     = (float*)(rsl16 + 128 * KP16);     // 64 x GPAD; P (f16) reuses rows
    float*  crs_s = G + 64 * GPAD;                    // 128
    float*  cks_s = crs_s + 128;                      // 64
    float*  mx    = cks_s + 64;                       // 128

    const int t    = threadIdx.x;
    const int lane = t & 31;
    const int w    = t >> 5;
    const int wp   = w & 3;            // q-row group
    const int half = w >> 2;           // key-column half
    const int g    = lane >> 2;
    const int tg   = lane & 3;
    const int i0   = wp * 16 + g;
    const int hb   = h * DH;
    const int jbase = half * 32;
    const int tile0 = (half == 0) ? (6 - 2 * wp) : (11 - 2 * wp);

    // ---- persistent Q a-frags (f16, pre-scaled by SCQ) ----
    u32 qa[4][4];
    {
        const __half* q0 = &g_q16[(size_t)(qi0 + i0) * NHD + hb];
        const __half* q1 = q0 + 8 * NHD;
#pragma unroll
        for (int k0 = 0; k0 < 4; k0++) {
            qa[k0][0] = *(const u32*)(q0 + k0 * 16 + 2 * tg);
            qa[k0][1] = *(const u32*)(q1 + k0 * 16 + 2 * tg);
            qa[k0][2] = *(const u32*)(q0 + k0 * 16 + 8 + 2 * tg);
            qa[k0][3] = *(const u32*)(q1 + k0 * 16 + 8 + 2 * tg);
        }
    }

    // ones column for l (cols 64..71 of vs16; never touched by fills)
    if (t < 64) {
        __half* p = &vs16[t * KP16 + 64];
        p[0] = __float2half(1.f);
#pragma unroll
        for (int i = 1; i < 8; i++) p[i] = __float2half(0.f);
    }

    float O[9][4];   // [8] = l column
#pragma unroll
    for (int nt = 0; nt < 9; nt++) {
        O[nt][0] = 0.f; O[nt][1] = 0.f; O[nt][2] = 0.f; O[nt][3] = 0.f;
    }
    float m0 = -1e30f, m1 = -1e30f;

    const int nkt = qi0 / 64 + 1;
    for (int kt = 0; kt < nkt; kt++) {
        const int kj0   = kt * 64;
        const int base  = (S - 1) + kj0 - qi0 - 63;
        const int rbase = base & 127;
        __syncthreads();  // all consumers done before refill

        // ---- K + V fills (cp.async f16) ----
#pragma unroll
        for (int it = 0; it < 2; it++) {
            const int idx = t + it * 256;      // < 512
            const int r = idx >> 3, c8 = (idx & 7) << 3;
            cpa16(sptr(&ks16[r * KP16 + c8]),
                  &g_k16[(size_t)(kj0 + r) * NHD + hb + c8]);
            cpa16(sptr(&vs16[r * KP16 + c8]),
                  &g_v16[(size_t)(kj0 + r) * NHD + hb + c8]);
        }
        // ---- RSL (cp.async f16, circular): only new rows ----
        {
            const int rl0 = (kt == 0) ? 0 : 64;
            const int nit = (kt == 0) ? 4 : 2;
            for (int it = 0; it < nit; it++) {
                const int idx = t + it * 256;
                const int row = rl0 + (idx >> 3);
                const int c8  = (idx & 7) << 3;
                int mg = base + row;
                if (mg > S - 1) mg = S - 1;
                cpa16(sptr(&rsl16[((rbase + row) & 127) * KP16 + c8]),
                      &g_r16[(size_t)mg * NHD + hb + c8]);
            }
        }
        if (t < 64) cks_s[t] = g_ck[h * S + kj0 + t];
        else if (t < 192) {
            const int mm = t - 64;
            int mg = base + mm;
            if (mg > S - 1) mg = S - 1;
            crs_s[mm] = (mm < 127) ? g_cr[h * S + mg] : 0.f;
        }
        CP_COMMIT();
        CP_WAIT0();
        __syncthreads();

        // ---- windowed G = Q @ RSL^T (+cr): 5 tiles, f16 k16 ----
        {
            u32 rb[5];
#pragma unroll
            for (int ni = 0; ni < 5; ni++) {
                const int lrow = (rbase + (tile0 + ni) * 8 + (lane & 7)) & 127;
                rb[ni] = sptr(&rsl16[lrow * KP16 + ((lane >> 3) & 1) * 8]);
            }
            float gc[5][4];
#pragma unroll
            for (int ni = 0; ni < 5; ni++) {
                const int col = (tile0 + ni) * 8 + 2 * tg;
                gc[ni][0] = crs_s[col];
                gc[ni][1] = crs_s[col + 1];
                gc[ni][2] = gc[ni][0];
                gc[ni][3] = gc[ni][1];
            }
#pragma unroll
            for (int k0 = 0; k0 < 4; k0++) {
#pragma unroll
                for (int ni = 0; ni < 5; ni++) {
                    u32 b0, b1;
                    ldm2(b0, b1, rb[ni] + k0 * 32);
                    mma_f16(gc[ni], qa[k0], b0, b1);
                }
            }
#pragma unroll
            for (int ni = 0; ni < 5; ni++) {
                const int col = (tile0 + ni) * 8 + 2 * tg;
                *(float2*)&G[i0 * GPAD + col]       = make_float2(gc[ni][0], gc[ni][1]);
                *(float2*)&G[(i0 + 8) * GPAD + col] = make_float2(gc[ni][2], gc[ni][3]);
            }
        }
        pair_bar(wp);  // pair's G halves visible before gather

        // ---- AC = Q @ K^T (+ck), own 32-key half, f16 k16 ----
        float sc[4][4];
        u32 kb4[4];
#pragma unroll
        for (int nt = 0; nt < 4; nt++) {
            const int col = jbase + nt * 8 + 2 * tg;
            sc[nt][0] = cks_s[col];
            sc[nt][1] = cks_s[col + 1];
            sc[nt][2] = sc[nt][0];
            sc[nt][3] = sc[nt][1];
            kb4[nt] = sptr(&ks16[(jbase + nt * 8 + (lane & 7)) * KP16 +
                                 ((lane >> 3) & 1) * 8]);
        }
#pragma unroll
        for (int k0 = 0; k0 < 4; k0++) {
#pragma unroll
            for (int nt = 0; nt < 4; nt++) {
                u32 b0, b1;
                ldm2(b0, b1, kb4[nt] + k0 * 32);
                mma_f16(sc[nt], qa[k0], b0, b1);
            }
        }

        // ---- BD gather + mask + own-half row max (log2 domain) ----
        const bool diag = (kt == nkt - 1);
        float rmax0 = -1e30f, rmax1 = -1e30f;
#pragma unroll
        for (int nt = 0; nt < 4; nt++) {
            const int j = jbase + nt * 8 + 2 * tg;
            float s00 = sc[nt][0] + G[i0 * GPAD + 63 + j - i0];
            float s01 = sc[nt][1] + G[i0 * GPAD + 64 + j - i0];
            float s10 = sc[nt][2] + G[(i0 + 8) * GPAD + 55 + j - i0];
            float s11 = sc[nt][3] + G[(i0 + 8) * GPAD + 56 + j - i0];
            if (diag) {
                if (kj0 + j     > qi0 + i0)     s00 = -1e30f;
                if (kj0 + j + 1 > qi0 + i0)     s01 = -1e30f;
                if (kj0 + j     > qi0 + i0 + 8) s10 = -1e30f;
                if (kj0 + j + 1 > qi0 + i0 + 8) s11 = -1e30f;
            }
            sc[nt][0] = s00; sc[nt][1] = s01; sc[nt][2] = s10; sc[nt][3] = s11;
            rmax0 = fmaxf(rmax0, fmaxf(s00, s01));
            rmax1 = fmaxf(rmax1, fmaxf(s10, s11));
        }
        rmax0 = fmaxf(rmax0, __shfl_xor_sync(0xffffffffu, rmax0, 1));
        rmax0 = fmaxf(rmax0, __shfl_xor_sync(0xffffffffu, rmax0, 2));
        rmax1 = fmaxf(rmax1, __shfl_xor_sync(0xffffffffu, rmax1, 1));
        rmax1 = fmaxf(rmax1, __shfl_xor_sync(0xffffffffu, rmax1, 2));

        // exchange with partner half (also orders partner gather before P stores)
        mx[2 * i0 + half]       = rmax0;
        mx[2 * (i0 + 8) + half] = rmax1;
        pair_bar(wp);
        rmax0 = fmaxf(rmax0, mx[2 * i0 + (half ^ 1)]);
        rmax1 = fmaxf(rmax1, mx[2 * (i0 + 8) + (half ^ 1)]);

        const float newm0 = fmaxf(m0, rmax0);
        const float newm1 = fmaxf(m1, rmax1);
        const float a0 = exp2f(m0 - newm0);
        const float a1 = exp2f(m1 - newm1);
        m0 = newm0; m1 = newm1;
#pragma unroll
        for (int nt = 0; nt < 9; nt++) {
            O[nt][0] *= a0; O[nt][1] *= a0;
            O[nt][2] *= a1; O[nt][3] *= a1;
        }

        // ---- p = 2^(s-m) via f16x2 MUFU; store packed-f16 P ----
        __half* psb16 = (__half*)G;
#pragma unroll
        for (int nt = 0; nt < 4; nt++) {
            const int col = jbase + nt * 8 + 2 * tg;
            u32 p01 = exp2_f16x2(sc[nt][0] - m0, sc[nt][1] - m0);
            u32 p23 = exp2_f16x2(sc[nt][2] - m1, sc[nt][3] - m1);
            *(u32*)&psb16[i0 * PP16 + col]       = p01;
            *(u32*)&psb16[(i0 + 8) * PP16 + col] = p23;
        }
        __syncwarp();  // P rows/cols are warp-private

        // ---- PV (f16 k16): O += P_half @ [V | 1], l rides in n-tile 8 ----
#pragma unroll
        for (int ki = 0; ki < 2; ki++) {
            const int kb = jbase + ki * 16;
            u32 pa[4];
            pa[0] = *(const u32*)&psb16[i0 * PP16 + kb + 2 * tg];
            pa[1] = *(const u32*)&psb16[(i0 + 8) * PP16 + kb + 2 * tg];
            pa[2] = *(const u32*)&psb16[i0 * PP16 + kb + 8 + 2 * tg];
            pa[3] = *(const u32*)&psb16[(i0 + 8) * PP16 + kb + 8 + 2 * tg];
            const u32 vb = sptr(vs16 + (size_t)(kb + (lane & 15)) * KP16);
#pragma unroll
            for (int nt = 0; nt < 9; nt++) {
                u32 b0, b1;
                ldm2t(b0, b1, vb + nt * 16);
                mma_f16(O[nt], pa, b0, b1);
            }
        }
    }

    // ---- extract l (ones-column accumulator, tg==0 lanes own it) ----
    float l0 = __shfl_sync(0xffffffffu, O[8][0], lane & 28);
    float l1 = __shfl_sync(0xffffffffu, O[8][2], lane & 28);

    // ---- merge the two key-halves (same m-sequence -> plain sums) ----
    __syncthreads();
    if (half == 1) {
#pragma unroll
        for (int nt = 0; nt < 8; nt++) {
            const int col = nt * 8 + 2 * tg;
            *(float2*)&G[i0 * GPAD + col]       = make_float2(O[nt][0], O[nt][1]);
            *(float2*)&G[(i0 + 8) * GPAD + col] = make_float2(O[nt][2], O[nt][3]);
        }
        if (tg == 0) {
            cks_s[i0]     = l0;
            cks_s[i0 + 8] = l1;
        }
    }
    __syncthreads();
    if (half == 0) {
        l0 += cks_s[i0];
        l1 += cks_s[i0 + 8];
        const float inv0 = 1.f / l0;
        const float inv1 = 1.f / l1;
#pragma unroll
        for (int nt = 0; nt < 8; nt++) {
            const int col = nt * 8 + 2 * tg;
            float2 p0 = *(const float2*)&G[i0 * GPAD + col];
            float2 p1 = *(const float2*)&G[(i0 + 8) * GPAD + col];
            float o00 = (O[nt][0] + p0.x) * inv0, o01 = (O[nt][1] + p0.y) * inv0;
            float o10 = (O[nt][2] + p1.x) * inv1, o11 = (O[nt][3] + p1.y) * inv1;
            const size_t idx0 = (size_t)(qi0 + i0) * NHD + hb + col;
            const size_t idx1 = (size_t)(qi0 + i0 + 8) * NHD + hb + col;
            __half2 h0 = __floats2half2_rn(o00, o01);
            __half2 h1 = __floats2half2_rn(o10, o11);
            float2 f0 = __half22float2(h0);
            float2 f1 = __half22float2(h1);
            __half2 L0 = __floats2half2_rn(o00 - f0.x, o01 - f0.y);
            __half2 L1 = __floats2half2_rn(o10 - f1.x, o11 - f1.y);
            *(__half2*)&g_at_h[idx0] = h0;
            *(__half2*)&g_at_l[idx0] = L0;
            *(__half2*)&g_at_h[idx1] = h1;
            *(__half2*)&g_at_l[idx1] = L1;
        }
    }
}

// ---------------------------------------------------------------------------
extern "C" void kernel_launch(void* const* d_in, const int* in_sizes, int n_in,
                              void* d_out, int out_size)
{
    const float* inputs_q = (const float*)d_in[0];
    const float* pos_emb  = (const float*)d_in[1];
    const float* r_w_bias = (const float*)d_in[2];
    const float* r_r_bias = (const float*)d_in[3];
    const float* Wq = (const float*)d_in[4];
    const float* bq = (const float*)d_in[5];
    const float* Wk = (const float*)d_in[6];
    const float* bk = (const float*)d_in[7];
    const float* Wv = (const float*)d_in[8];
    const float* bv = (const float*)d_in[9];
    const float* Wr = (const float*)d_in[10];
    const float* br = (const float*)d_in[11];
    const float* Wo = (const float*)d_in[12];
    const float* bo = (const float*)d_in[13];
    float* out = (float*)d_out;

    cudaFuncSetAttribute(attn_kernel,
                         cudaFuncAttributeMaxDynamicSharedMemorySize, SMEM_ATTN);
    cudaFuncSetAttribute(proj_f16_kernel,
                         cudaFuncAttributeMaxDynamicSharedMemorySize, GEMM_SMEM_BYTES);
    cudaFuncSetAttribute(out_f16_kernel,
                         cudaFuncAttributeMaxDynamicSharedMemorySize, GEMM_SMEM_BYTES);

    split_kernel<<<(2 * 524288 + 5 * 262144) / 256, 256>>>(
        inputs_q, pos_emb, Wq, Wk, Wv, Wr, Wo);

    proj_f16_kernel<<<dim3(NHD / 128, S / 128, 4), 256, GEMM_SMEM_BYTES>>>(
        bq, bk, bv, br);

    bias_dots_kernel<<<(2 * H * S * 32) / 256, 256>>>(r_w_bias, r_r_bias);

    attn_kernel<<<dim3(S / 64, H), 256, SMEM_ATTN>>>();

    out_f16_kernel<<<dim3(F / 128, S / 128), 256, GEMM_SMEM_BYTES>>>(bo, out);
}

// round 15
// speedup vs baseline: 10.2043x; 1.0011x over previous
#include <cuda_runtime.h>
#include <cuda_bf16.h>
#include <cuda_fp16.h>

#define S 2048
#define F 1024
#define H 16
#define DH 64
#define NHD 1024  // H*DH

typedef unsigned long long u64;
typedef unsigned int u32;

#define LOG2E 1.4426950408889634f
#define SCQ (0.125f * LOG2E)   // folded softmax scale + log2 conversion

// ---- f16 mma ----
__device__ __forceinline__ void mma_f16(float c[4], const u32 a[4], u32 b0, u32 b1) {
    asm volatile(
        "mma.sync.aligned.m16n8k16.row.col.f32.f16.f16.f32 "
        "{%0,%1,%2,%3}, {%4,%5,%6,%7}, {%8,%9}, {%0,%1,%2,%3};\n"
        : "+f"(c[0]), "+f"(c[1]), "+f"(c[2]), "+f"(c[3])
        : "r"(a[0]), "r"(a[1]), "r"(a[2]), "r"(a[3]), "r"(b0), "r"(b1));
}

__device__ __forceinline__ u32 exp2_f16x2(float ylo, float yhi) {
    __half2 h = __floats2half2_rn(ylo, yhi);
    __half2 r = h2exp2(h);
    return *(u32*)&r;
}

// Packed fp32x2 polynomial 2^x for a pair of scores (x <= 0), f16x2 result.
// Range reduce: n = round(x) via 1.5*2^23 trick, f = x-n in [-0.5,0.5];
// 2^f by degree-4 Taylor (rel err < 6e-5); scale 2^n rebuilt with one IMAD.
// Runs on the FMA/ALU pipes to offload the saturated MUFU pipe.
__device__ __forceinline__ u32 exp2_poly_pair(float x0, float x1) {
    u32 r;
    asm("{\n\t"
        ".reg .f32 a0, a1;\n\t"
        ".reg .b32 e0, e1, p0, p1;\n\t"
        ".reg .b64 X, Y, N, Fv, T, E, P, CC;\n\t"
        "max.f32 a0, %1, 0fC1A00000;\n\t"              // clamp at -20
        "max.f32 a1, %2, 0fC1A00000;\n\t"
        "mov.b64 X, {a0, a1};\n\t"
        "mov.b64 CC, {0f4B400000, 0f4B400000};\n\t"    // 1.5*2^23
        "add.rn.f32x2 Y, X, CC;\n\t"
        "mov.b64 CC, {0fCB400000, 0fCB400000};\n\t"
        "add.rn.f32x2 N, Y, CC;\n\t"                   // n = round(x)
        "mov.b64 CC, {0fBF800000, 0fBF800000};\n\t"
        "fma.rn.f32x2 Fv, N, CC, X;\n\t"               // f = x - n
        "mov.b64 T, {0f3C1D9585, 0f3C1D9585};\n\t"     // ln2^4/24
        "mov.b64 E, {0f3D635879, 0f3D635879};\n\t"     // ln2^3/6
        "fma.rn.f32x2 T, Fv, T, E;\n\t"
        "mov.b64 E, {0f3E75FDF0, 0f3E75FDF0};\n\t"     // ln2^2/2
        "fma.rn.f32x2 T, Fv, T, E;\n\t"
        "mov.b64 E, {0f3F317218, 0f3F317218};\n\t"     // ln2
        "fma.rn.f32x2 T, Fv, T, E;\n\t"
        "mov.b64 E, {0f3F800000, 0f3F800000};\n\t"     // 1.0
        "fma.rn.f32x2 T, Fv, T, E;\n\t"                // 2^f
        "mov.b64 {e0, e1}, Y;\n\t"
        "mad.lo.s32 e0, e0, 8388608, 1065353216;\n\t"  // (n<<23)+0x3F800000
        "mad.lo.s32 e1, e1, 8388608, 1065353216;\n\t"
        "mov.b64 E, {e0, e1};\n\t"
        "mul.rn.f32x2 P, T, E;\n\t"                    // 2^f * 2^n
        "mov.b64 {p0, p1}, P;\n\t"
        "cvt.rn.f16x2.f32 %0, p1, p0;\n\t"             // lo=p0, hi=p1
        "}"
        : "=r"(r) : "f"(x0), "f"(x1));
    return r;
}

__device__ __forceinline__ void ldm2t(u32& d0, u32& d1, u32 saddr) {
    asm volatile("ldmatrix.sync.aligned.m8n8.x2.trans.shared.b16 {%0,%1}, [%2];"
                 : "=r"(d0), "=r"(d1) : "r"(saddr));
}
__device__ __forceinline__ void ldm2(u32& d0, u32& d1, u32 saddr) {
    asm volatile("ldmatrix.sync.aligned.m8n8.x2.shared.b16 {%0,%1}, [%2];"
                 : "=r"(d0), "=r"(d1) : "r"(saddr));
}
__device__ __forceinline__ u32 sptr(const void* p) {
    return (u32)__cvta_generic_to_shared(p);
}
__device__ __forceinline__ void pair_bar(int wp) {
    asm volatile("bar.sync %0, 64;" :: "r"(1 + wp) : "memory");
}
// ---- cp.async (global -> shared, 16B) ----
__device__ __forceinline__ void cpa16(u32 dst, const void* src) {
    asm volatile("cp.async.ca.shared.global [%0], [%1], 16;"
                 :: "r"(dst), "l"(src) : "memory");
}
#define CP_COMMIT() asm volatile("cp.async.commit_group;" ::: "memory")
#define CP_WAIT0()  asm volatile("cp.async.wait_group 0;" ::: "memory")

// Scratch (device globals: allocation-free per harness rules)
__device__ float g_k[S * NHD];   // fp32 for bias_dots
__device__ float g_r[S * NHD];   // fp32 for bias_dots
__device__ float g_ck[H * S];
__device__ float g_cr[H * S];
// f16 attention operands (emitted by proj epilogue)
__device__ __half g_q16[S * NHD];   // pre-scaled by SCQ
__device__ __half g_k16[S * NHD];
__device__ __half g_v16[S * NHD];
__device__ __half g_r16[S * NHD];
// f16 GEMM panels
__device__ __half g_xq[S * F];
__device__ __half g_xr[S * F];
__device__ __half g_w16[5 * F * NHD];             // Wq,Wk,Wv,Wr,Wo
__device__ __half g_at_h[S * NHD], g_at_l[S * NHD];

// ---------------------------------------------------------------------------
// Convert fp32 operands -> f16 panels.
// float4 segments: xq [0,524288), xr [524288,1048576), w0..w4 262144 each.
// ---------------------------------------------------------------------------
__global__ __launch_bounds__(256) void split_kernel(
    const float* __restrict__ xq, const float* __restrict__ xr,
    const float* __restrict__ w0, const float* __restrict__ w1,
    const float* __restrict__ w2, const float* __restrict__ w3,
    const float* __restrict__ w4)
{
    const int i = blockIdx.x * 256 + threadIdx.x;
    const float* src;
    __half* dst;
    int off;
    if (i < 1048576) {
        src = (i < 524288) ? xq : xr;
        dst = (i < 524288) ? g_xq : g_xr;
        off = i & 524287;
    } else {
        const int j = i - 1048576;
        const int w = j >> 18;
        off = j & 262143;
        const float* ws[5] = {w0, w1, w2, w3, w4};
        src = ws[w];
        dst = g_w16 + (size_t)w * (F * NHD);
    }
    float4 v = ((const float4*)src)[off];
    ((__half2*)dst)[off * 2]     = __floats2half2_rn(v.x, v.y);
    ((__half2*)dst)[off * 2 + 1] = __floats2half2_rn(v.z, v.w);
}

// ---------------------------------------------------------------------------
// f16 GEMM: C = (Ah [+ Al]) @ B + bias
// CTA 128x128, 8 warps (4m x 2n), K-chunk 32, double-buffered cp.async.
// SPLIT_A=false: 1 MMA per k16 (proj; outputs rounded to f16 anyway).
// SPLIT_A=true : 2 MMAs per k16 (output projection; final accuracy).
// ---------------------------------------------------------------------------
#define GEMM_SMEM_BYTES 58368

template <bool SPLIT_A>
__device__ __forceinline__ void gemm_f16_body(
    const __half* __restrict__ Ah, const __half* __restrict__ Al,
    const __half* __restrict__ B,
    const float* __restrict__ bias, float* __restrict__ C,
    __half* __restrict__ C16, float scale,
    int M, int N, int K)
{
    extern __shared__ __half sh[];
    __half* As_h = sh;
    __half* As_l = sh + 10240;
    __half* Bs   = sh + 20480;

    const int t    = threadIdx.x;
    const int lane = t & 31;
    const int w    = t >> 5;
    const int wm   = (w & 3) * 32;
    const int wn   = (w >> 2) * 64;
    const int g    = lane >> 2;
    const int tg   = lane & 3;
    const int m0   = blockIdx.y * 128;
    const int n0   = blockIdx.x * 128;

    float Cr[2][8][4];
#pragma unroll
    for (int mt = 0; mt < 2; mt++)
#pragma unroll
        for (int nt = 0; nt < 8; nt++) {
            Cr[mt][nt][0] = 0.f; Cr[mt][nt][1] = 0.f;
            Cr[mt][nt][2] = 0.f; Cr[mt][nt][3] = 0.f;
        }

    const int fm = t >> 1, fh = (t & 1) * 16;
    const int fk = t >> 3, fv = (t & 7) * 16;

    const __half* gAh = Ah + (size_t)(m0 + fm) * K + fh;
    const __half* gAl = SPLIT_A ? Al + (size_t)(m0 + fm) * K + fh : nullptr;
    const __half* gB  = B  + (size_t)fk * N + n0 + fv;

    const int sa_off = fm * 40 + fh;
    const int sb_off = fk * 136 + fv;

    {
        u32 d;
        d = sptr(As_h + sa_off); cpa16(d, gAh); cpa16(d + 16, gAh + 8);
        if (SPLIT_A) {
            d = sptr(As_l + sa_off); cpa16(d, gAl); cpa16(d + 16, gAl + 8);
        }
        d = sptr(Bs + sb_off);   cpa16(d, gB);  cpa16(d + 16, gB + 8);
        CP_COMMIT();
        CP_WAIT0();
    }
    __syncthreads();

    int buf = 0;
    const int nkc = K / 32;
    for (int kc = 0; kc < nkc; kc++) {
        const bool has = (kc + 1) < nkc;
        if (has) {
            const __half* pAh = gAh + (kc + 1) * 32;
            const __half* pB  = gB + (size_t)(kc + 1) * 32 * N;
            const int nb = buf ^ 1;
            u32 d;
            d = sptr(As_h + nb * 5120 + sa_off); cpa16(d, pAh); cpa16(d + 16, pAh + 8);
            if (SPLIT_A) {
                const __half* pAl = gAl + (kc + 1) * 32;
                d = sptr(As_l + nb * 5120 + sa_off); cpa16(d, pAl); cpa16(d + 16, pAl + 8);
            }
            d = sptr(Bs + nb * 4352 + sb_off);   cpa16(d, pB);  cpa16(d + 16, pB + 8);
            CP_COMMIT();
        }
        const __half* Ab_h = As_h + buf * 5120;
        const __half* Ab_l = As_l + buf * 5120;
        const __half* Bb   = Bs + buf * 4352;

#pragma unroll
        for (int ks2 = 0; ks2 < 2; ks2++) {
            const int ks = ks2 * 16;
            u32 ah[2][4], al[2][4];
#pragma unroll
            for (int mt = 0; mt < 2; mt++) {
                const __half* r0 = Ab_h + (wm + mt * 16 + g) * 40 + ks + 2 * tg;
                ah[mt][0] = *(const u32*)r0;
                ah[mt][1] = *(const u32*)(r0 + 8 * 40);
                ah[mt][2] = *(const u32*)(r0 + 8);
                ah[mt][3] = *(const u32*)(r0 + 8 * 40 + 8);
                if (SPLIT_A) {
                    const __half* r1 = Ab_l + (wm + mt * 16 + g) * 40 + ks + 2 * tg;
                    al[mt][0] = *(const u32*)r1;
                    al[mt][1] = *(const u32*)(r1 + 8 * 40);
                    al[mt][2] = *(const u32*)(r1 + 8);
                    al[mt][3] = *(const u32*)(r1 + 8 * 40 + 8);
                }
            }
            const u32 bb = sptr(Bb + (ks + (lane & 15)) * 136 + wn);
#pragma unroll
            for (int nt = 0; nt < 8; nt++) {
                u32 b0, b1;
                ldm2t(b0, b1, bb + nt * 16);
#pragma unroll
                for (int mt = 0; mt < 2; mt++) {
                    mma_f16(Cr[mt][nt], ah[mt], b0, b1);
                    if (SPLIT_A) mma_f16(Cr[mt][nt], al[mt], b0, b1);
                }
            }
        }

        if (has) {
            CP_WAIT0();
            __syncthreads();
            buf ^= 1;
        }
    }

#pragma unroll
    for (int mt = 0; mt < 2; mt++) {
        const int row = m0 + wm + mt * 16 + g;
#pragma unroll
        for (int nt = 0; nt < 8; nt++) {
            const int col = n0 + wn + nt * 8 + 2 * tg;
            float2 b01 = *(const float2*)&bias[col];
            const float v00 = Cr[mt][nt][0] + b01.x;
            const float v01 = Cr[mt][nt][1] + b01.y;
            const float v10 = Cr[mt][nt][2] + b01.x;
            const float v11 = Cr[mt][nt][3] + b01.y;
            if (C) {
                *(float2*)(C + (size_t)row * N + col)       = make_float2(v00, v01);
                *(float2*)(C + (size_t)(row + 8) * N + col) = make_float2(v10, v11);
            }
            if (C16) {
                *(__half2*)(C16 + (size_t)row * N + col) =
                    __floats2half2_rn(v00 * scale, v01 * scale);
                *(__half2*)(C16 + (size_t)(row + 8) * N + col) =
                    __floats2half2_rn(v10 * scale, v11 * scale);
            }
        }
    }
}

__global__ __launch_bounds__(256, 2) void proj_f16_kernel(
    const float* __restrict__ bq, const float* __restrict__ bk,
    const float* __restrict__ bv, const float* __restrict__ br)
{
    const int z = blockIdx.z;
    const __half* A = (z < 3) ? g_xq : g_xr;
    const __half* B = g_w16 + (size_t)z * (F * NHD);
    const float* bias;
    float* C;
    __half* C16;
    float scale = 1.f;
    switch (z) {
        case 0:  bias = bq; C = nullptr; C16 = g_q16; scale = SCQ; break;
        case 1:  bias = bk; C = g_k;     C16 = g_k16; break;
        case 2:  bias = bv; C = nullptr; C16 = g_v16; break;
        default: bias = br; C = g_r;     C16 = g_r16; break;
    }
    gemm_f16_body<false>(A, nullptr, B, bias, C, C16, scale, S, NHD, F);
}

__global__ __launch_bounds__(256, 2) void out_f16_kernel(
    const float* __restrict__ bo, float* __restrict__ out)
{
    gemm_f16_body<true>(g_at_h, g_at_l, g_w16 + (size_t)4 * (F * NHD),
                        bo, out, nullptr, 1.f, S, F, NHD);
}

// ---------------------------------------------------------------------------
// ck[h][j] = SCQ * rw[h].k[j,h,:],  cr[h][m] = SCQ * rr[h].r[m,h,:]
// ---------------------------------------------------------------------------
__global__ __launch_bounds__(256) void bias_dots_kernel(
    const float* __restrict__ rwb, const float* __restrict__ rrb)
{
    const int gw   = (blockIdx.x * blockDim.x + threadIdx.x) >> 5;
    const int lane = threadIdx.x & 31;
    const int which = gw >= H * S;
    const int idx   = which ? gw - H * S : gw;
    const int hh = idx >> 11;
    const int j  = idx & (S - 1);
    const float* bias = which ? rrb : rwb;
    const float* mat  = which ? g_r : g_k;
    const float b0 = bias[hh * DH + lane];
    const float b1 = bias[hh * DH + 32 + lane];
    const float* row = mat + (size_t)j * NHD + hh * DH;
    float s = fmaf(b0, row[lane], b1 * row[32 + lane]);
#pragma unroll
    for (int off = 16; off > 0; off >>= 1)
        s += __shfl_xor_sync(0xffffffffu, s, off);
    if (lane == 0) {
        float* dst = which ? g_cr : g_ck;
        dst[hh * S + j] = s * SCQ;
    }
}

// ---------------------------------------------------------------------------
// Causal flash attention, all-f16 MMA (k16), log2-domain softmax.
// R15: exp pipeline split — nt==0 pairs through FFMA2 poly (FMA pipe),
// nt 1..3 through h2exp2 (MUFU) -> ~25% MUFU offload.
// ---------------------------------------------------------------------------
#define KP16 72
#define GPAD 132
#define PP16 (GPAD * 2)
#define SMEM_ATTN ((64*KP16 + 64*KP16 + 128*KP16)*2 + (64*GPAD)*4 + (128+64+128)*4)

__global__ __launch_bounds__(256, 2) void attn_kernel()
{
    const int h   = blockIdx.y;
    const int qi0 = (gridDim.x - 1 - blockIdx.x) * 64;

    extern __shared__ float sm[];
    __half* ks16  = (__half*)sm;
    __half* vs16  = ks16 + 64 * KP16;
    __half* rsl16 = vs16 + 64 * KP16;
    float*  G     = (float*)(rsl16 + 128 * KP16);
    float*  crs_s = G + 64 * GPAD;
    float*  cks_s = crs_s + 128;
    float*  mx    = cks_s + 64;

    const int t    = threadIdx.x;
    const int lane = t & 31;
    const int w    = t >> 5;
    const int wp   = w & 3;
    const int half = w >> 2;
    const int g    = lane >> 2;
    const int tg   = lane & 3;
    const int i0   = wp * 16 + g;
    const int hb   = h * DH;
    const int jbase = half * 32;
    const int tile0 = (half == 0) ? (6 - 2 * wp) : (11 - 2 * wp);

    u32 qa[4][4];
    {
        const __half* q0 = &g_q16[(size_t)(qi0 + i0) * NHD + hb];
        const __half* q1 = q0 + 8 * NHD;
#pragma unroll
        for (int k0 = 0; k0 < 4; k0++) {
            qa[k0][0] = *(const u32*)(q0 + k0 * 16 + 2 * tg);
            qa[k0][1] = *(const u32*)(q1 + k0 * 16 + 2 * tg);
            qa[k0][2] = *(const u32*)(q0 + k0 * 16 + 8 + 2 * tg);
            qa[k0][3] = *(const u32*)(q1 + k0 * 16 + 8 + 2 * tg);
        }
    }

    if (t < 64) {
        __half* p = &vs16[t * KP16 + 64];
        p[0] = __float2half(1.f);
#pragma unroll
        for (int i = 1; i < 8; i++) p[i] = __float2half(0.f);
    }

    float O[9][4];
#pragma unroll
    for (int nt = 0; nt < 9; nt++) {
        O[nt][0] = 0.f; O[nt][1] = 0.f; O[nt][2] = 0.f; O[nt][3] = 0.f;
    }
    float m0 = -1e30f, m1 = -1e30f;

    const int nkt = qi0 / 64 + 1;
    for (int kt = 0; kt < nkt; kt++) {
        const int kj0   = kt * 64;
        const int base  = (S - 1) + kj0 - qi0 - 63;
        const int rbase = base & 127;
        __syncthreads();

#pragma unroll
        for (int it = 0; it < 2; it++) {
            const int idx = t + it * 256;
            const int r = idx >> 3, c8 = (idx & 7) << 3;
            cpa16(sptr(&ks16[r * KP16 + c8]),
                  &g_k16[(size_t)(kj0 + r) * NHD + hb + c8]);
            cpa16(sptr(&vs16[r * KP16 + c8]),
                  &g_v16[(size_t)(kj0 + r) * NHD + hb + c8]);
        }
        {
            const int rl0 = (kt == 0) ? 0 : 64;
            const int nit = (kt == 0) ? 4 : 2;
            for (int it = 0; it < nit; it++) {
                const int idx = t + it * 256;
                const int row = rl0 + (idx >> 3);
                const int c8  = (idx & 7) << 3;
                int mg = base + row;
                if (mg > S - 1) mg = S - 1;
                cpa16(sptr(&rsl16[((rbase + row) & 127) * KP16 + c8]),
                      &g_r16[(size_t)mg * NHD + hb + c8]);
            }
        }
        if (t < 64) cks_s[t] = g_ck[h * S + kj0 + t];
        else if (t < 192) {
            const int mm = t - 64;
            int mg = base + mm;
            if (mg > S - 1) mg = S - 1;
            crs_s[mm] = (mm < 127) ? g_cr[h * S + mg] : 0.f;
        }
        CP_COMMIT();
        CP_WAIT0();
        __syncthreads();

        {
            u32 rb[5];
#pragma unroll
            for (int ni = 0; ni < 5; ni++) {
                const int lrow = (rbase + (tile0 + ni) * 8 + (lane & 7)) & 127;
                rb[ni] = sptr(&rsl16[lrow * KP16 + ((lane >> 3) & 1) * 8]);
            }
            float gc[5][4];
#pragma unroll
            for (int ni = 0; ni < 5; ni++) {
                const int col = (tile0 + ni) * 8 + 2 * tg;
                gc[ni][0] = crs_s[col];
                gc[ni][1] = crs_s[col + 1];
                gc[ni][2] = gc[ni][0];
                gc[ni][3] = gc[ni][1];
            }
#pragma unroll
            for (int k0 = 0; k0 < 4; k0++) {
#pragma unroll
                for (int ni = 0; ni < 5; ni++) {
                    u32 b0, b1;
                    ldm2(b0, b1, rb[ni] + k0 * 32);
                    mma_f16(gc[ni], qa[k0], b0, b1);
                }
            }
#pragma unroll
            for (int ni = 0; ni < 5; ni++) {
                const int col = (tile0 + ni) * 8 + 2 * tg;
                *(float2*)&G[i0 * GPAD + col]       = make_float2(gc[ni][0], gc[ni][1]);
                *(float2*)&G[(i0 + 8) * GPAD + col] = make_float2(gc[ni][2], gc[ni][3]);
            }
        }
        pair_bar(wp);

        float sc[4][4];
        u32 kb4[4];
#pragma unroll
        for (int nt = 0; nt < 4; nt++) {
            const int col = jbase + nt * 8 + 2 * tg;
            sc[nt][0] = cks_s[col];
            sc[nt][1] = cks_s[col + 1];
            sc[nt][2] = sc[nt][0];
            sc[nt][3] = sc[nt][1];
            kb4[nt] = sptr(&ks16[(jbase + nt * 8 + (lane & 7)) * KP16 +
                                 ((lane >> 3) & 1) * 8]);
        }
#pragma unroll
        for (int k0 = 0; k0 < 4; k0++) {
#pragma unroll
            for (int nt = 0; nt < 4; nt++) {
                u32 b0, b1;
                ldm2(b0, b1, kb4[nt] + k0 * 32);
                mma_f16(sc[nt], qa[k0], b0, b1);
            }
        }

        const bool diag = (kt == nkt - 1);
        float rmax0 = -1e30f, rmax1 = -1e30f;
#pragma unroll
        for (int nt = 0; nt < 4; nt++) {
            const int j = jbase + nt * 8 + 2 * tg;
            float s00 = sc[nt][0] + G[i0 * GPAD + 63 + j - i0];
            float s01 = sc[nt][1] + G[i0 * GPAD + 64 + j - i0];
            float s10 = sc[nt][2] + G[(i0 + 8) * GPAD + 55 + j - i0];
            float s11 = sc[nt][3] + G[(i0 + 8) * GPAD + 56 + j - i0];
            if (diag) {
                if (kj0 + j     > qi0 + i0)     s00 = -1e30f;
                if (kj0 + j + 1 > qi0 + i0)     s01 = -1e30f;
                if (kj0 + j     > qi0 + i0 + 8) s10 = -1e30f;
                if (kj0 + j + 1 > qi0 + i0 + 8) s11 = -1e30f;
            }
            sc[nt][0] = s00; sc[nt][1] = s01; sc[nt][2] = s10; sc[nt][3] = s11;
            rmax0 = fmaxf(rmax0, fmaxf(s00, s01));
            rmax1 = fmaxf(rmax1, fmaxf(s10, s11));
        }
        rmax0 = fmaxf(rmax0, __shfl_xor_sync(0xffffffffu, rmax0, 1));
        rmax0 = fmaxf(rmax0, __shfl_xor_sync(0xffffffffu, rmax0, 2));
        rmax1 = fmaxf(rmax1, __shfl_xor_sync(0xffffffffu, rmax1, 1));
        rmax1 = fmaxf(rmax1, __shfl_xor_sync(0xffffffffu, rmax1, 2));

        mx[2 * i0 + half]       = rmax0;
        mx[2 * (i0 + 8) + half] = rmax1;
        pair_bar(wp);
        rmax0 = fmaxf(rmax0, mx[2 * i0 + (half ^ 1)]);
        rmax1 = fmaxf(rmax1, mx[2 * (i0 + 8) + (half ^ 1)]);

        const float newm0 = fmaxf(m0, rmax0);
        const float newm1 = fmaxf(m1, rmax1);
        const float a0 = exp2f(m0 - newm0);
        const float a1 = exp2f(m1 - newm1);
        m0 = newm0; m1 = newm1;
#pragma unroll
        for (int nt = 0; nt < 9; nt++) {
            O[nt][0] *= a0; O[nt][1] *= a0;
            O[nt][2] *= a1; O[nt][3] *= a1;
        }

        // ---- p = 2^(s-m): nt==0 via FFMA2 poly (FMA pipe), rest via MUFU ----
        __half* psb16 = (__half*)G;
#pragma unroll
        for (int nt = 0; nt < 4; nt++) {
            const int col = jbase + nt * 8 + 2 * tg;
            u32 p01, p23;
            if (nt == 0) {
                p01 = exp2_poly_pair(sc[nt][0] - m0, sc[nt][1] - m0);
                p23 = exp2_poly_pair(sc[nt][2] - m1, sc[nt][3] - m1);
            } else {
                p01 = exp2_f16x2(sc[nt][0] - m0, sc[nt][1] - m0);
                p23 = exp2_f16x2(sc[nt][2] - m1, sc[nt][3] - m1);
            }
            *(u32*)&psb16[i0 * PP16 + col]       = p01;
            *(u32*)&psb16[(i0 + 8) * PP16 + col] = p23;
        }
        __syncwarp();

#pragma unroll
        for (int ki = 0; ki < 2; ki++) {
            const int kb = jbase + ki * 16;
            u32 pa[4];
            pa[0] = *(const u32*)&psb16[i0 * PP16 + kb + 2 * tg];
            pa[1] = *(const u32*)&psb16[(i0 + 8) * PP16 + kb + 2 * tg];
            pa[2] = *(const u32*)&psb16[i0 * PP16 + kb + 8 + 2 * tg];
            pa[3] = *(const u32*)&psb16[(i0 + 8) * PP16 + kb + 8 + 2 * tg];
            const u32 vb = sptr(vs16 + (size_t)(kb + (lane & 15)) * KP16);
#pragma unroll
            for (int nt = 0; nt < 9; nt++) {
                u32 b0, b1;
                ldm2t(b0, b1, vb + nt * 16);
                mma_f16(O[nt], pa, b0, b1);
            }
        }
    }

    float l0 = __shfl_sync(0xffffffffu, O[8][0], lane & 28);
    float l1 = __shfl_sync(0xffffffffu, O[8][2], lane & 28);

    __syncthreads();
    if (half == 1) {
#pragma unroll
        for (int nt = 0; nt < 8; nt++) {
            const int col = nt * 8 + 2 * tg;
            *(float2*)&G[i0 * GPAD + col]       = make_float2(O[nt][0], O[nt][1]);
            *(float2*)&G[(i0 + 8) * GPAD + col] = make_float2(O[nt][2], O[nt][3]);
        }
        if (tg == 0) {
            cks_s[i0]     = l0;
            cks_s[i0 + 8] = l1;
        }
    }
    __syncthreads();
    if (half == 0) {
        l0 += cks_s[i0];
        l1 += cks_s[i0 + 8];
        const float inv0 = 1.f / l0;
        const float inv1 = 1.f / l1;
#pragma unroll
        for (int nt = 0; nt < 8; nt++) {
            const int col = nt * 8 + 2 * tg;
            float2 p0 = *(const float2*)&G[i0 * GPAD + col];
            float2 p1 = *(const float2*)&G[(i0 + 8) * GPAD + col];
            float o00 = (O[nt][0] + p0.x) * inv0, o01 = (O[nt][1] + p0.y) * inv0;
            float o10 = (O[nt][2] + p1.x) * inv1, o11 = (O[nt][3] + p1.y) * inv1;
            const size_t idx0 = (size_t)(qi0 + i0) * NHD + hb + col;
            const size_t idx1 = (size_t)(qi0 + i0 + 8) * NHD + hb + col;
            __half2 h0 = __floats2half2_rn(o00, o01);
            __half2 h1 = __floats2half2_rn(o10, o11);
            float2 f0 = __half22float2(h0);
            float2 f1 = __half22float2(h1);
            __half2 L0 = __floats2half2_rn(o00 - f0.x, o01 - f0.y);
            __half2 L1 = __floats2half2_rn(o10 - f1.x, o11 - f1.y);
            *(__half2*)&g_at_h[idx0] = h0;
            *(__half2*)&g_at_l[idx0] = L0;
            *(__half2*)&g_at_h[idx1] = h1;
            *(__half2*)&g_at_l[idx1] = L1;
        }
    }
}

// ---------------------------------------------------------------------------
extern "C" void kernel_launch(void* const* d_in, const int* in_sizes, int n_in,
                              void* d_out, int out_size)
{
    const float* inputs_q = (const float*)d_in[0];
    const float* pos_emb  = (const float*)d_in[1];
    const float* r_w_bias = (const float*)d_in[2];
    const float* r_r_bias = (const float*)d_in[3];
    const float* Wq = (const float*)d_in[4];
    const float* bq = (const float*)d_in[5];
    const float* Wk = (const float*)d_in[6];
    const float* bk = (const float*)d_in[7];
    const float* Wv = (const float*)d_in[8];
    const float* bv = (const float*)d_in[9];
    const float* Wr = (const float*)d_in[10];
    const float* br = (const float*)d_in[11];
    const float* Wo = (const float*)d_in[12];
    const float* bo = (const float*)d_in[13];
    float* out = (float*)d_out;

    cudaFuncSetAttribute(attn_kernel,
                         cudaFuncAttributeMaxDynamicSharedMemorySize, SMEM_ATTN);
    cudaFuncSetAttribute(proj_f16_kernel,
                         cudaFuncAttributeMaxDynamicSharedMemorySize, GEMM_SMEM_BYTES);
    cudaFuncSetAttribute(out_f16_kernel,
                         cudaFuncAttributeMaxDynamicSharedMemorySize, GEMM_SMEM_BYTES);

    split_kernel<<<(2 * 524288 + 5 * 262144) / 256, 256>>>(
        inputs_q, pos_emb, Wq, Wk, Wv, Wr, Wo);

    proj_f16_kernel<<<dim3(NHD / 128, S / 128, 4), 256, GEMM_SMEM_BYTES>>>(
        bq, bk, bv, br);

    bias_dots_kernel<<<(2 * H * S * 32) / 256, 256>>>(r_w_bias, r_r_bias);

    attn_kernel<<<dim3(S / 64, H), 256, SMEM_ATTN>>>();

    out_f16_kernel<<<dim3(F / 128, S / 128), 256, GEMM_SMEM_BYTES>>>(bo, out);
}

// round 16
// speedup vs baseline: 10.4606x; 1.0251x over previous
#include <cuda_runtime.h>
#include <cuda_bf16.h>
#include <cuda_fp16.h>

#define S 2048
#define F 1024
#define H 16
#define DH 64
#define NHD 1024  // H*DH

typedef unsigned long long u64;
typedef unsigned int u32;

#define LOG2E 1.4426950408889634f
#define SCQ (0.125f * LOG2E)   // folded softmax scale + log2 conversion

// ---- f16 mma ----
__device__ __forceinline__ void mma_f16(float c[4], const u32 a[4], u32 b0, u32 b1) {
    asm volatile(
        "mma.sync.aligned.m16n8k16.row.col.f32.f16.f16.f32 "
        "{%0,%1,%2,%3}, {%4,%5,%6,%7}, {%8,%9}, {%0,%1,%2,%3};\n"
        : "+f"(c[0]), "+f"(c[1]), "+f"(c[2]), "+f"(c[3])
        : "r"(a[0]), "r"(a[1]), "r"(a[2]), "r"(a[3]), "r"(b0), "r"(b1));
}

__device__ __forceinline__ u32 exp2_f16x2(float ylo, float yhi) {
    __half2 h = __floats2half2_rn(ylo, yhi);
    __half2 r = h2exp2(h);
    return *(u32*)&r;
}

__device__ __forceinline__ void ldm2t(u32& d0, u32& d1, u32 saddr) {
    asm volatile("ldmatrix.sync.aligned.m8n8.x2.trans.shared.b16 {%0,%1}, [%2];"
                 : "=r"(d0), "=r"(d1) : "r"(saddr));
}
__device__ __forceinline__ void ldm2(u32& d0, u32& d1, u32 saddr) {
    asm volatile("ldmatrix.sync.aligned.m8n8.x2.shared.b16 {%0,%1}, [%2];"
                 : "=r"(d0), "=r"(d1) : "r"(saddr));
}
__device__ __forceinline__ u32 sptr(const void* p) {
    return (u32)__cvta_generic_to_shared(p);
}
__device__ __forceinline__ void pair_bar(int wp) {
    asm volatile("bar.sync %0, 64;" :: "r"(1 + wp) : "memory");
}
// ---- cp.async (global -> shared, 16B) ----
__device__ __forceinline__ void cpa16(u32 dst, const void* src) {
    asm volatile("cp.async.ca.shared.global [%0], [%1], 16;"
                 :: "r"(dst), "l"(src) : "memory");
}
#define CP_COMMIT() asm volatile("cp.async.commit_group;" ::: "memory")
#define CP_WAIT0()  asm volatile("cp.async.wait_group 0;" ::: "memory")

// Scratch (device globals: allocation-free per harness rules)
__device__ float g_ck[H * S];
__device__ float g_cr[H * S];
// f16 attention operands (emitted by proj epilogue)
__device__ __half g_q16[S * NHD];   // pre-scaled by SCQ
__device__ __half g_k16[S * NHD];
__device__ __half g_v16[S * NHD];
__device__ __half g_r16[S * NHD];
// f16 GEMM panels
__device__ __half g_xq[S * F];
__device__ __half g_xr[S * F];
__device__ __half g_w16[5 * F * NHD];             // Wq,Wk,Wv,Wr,Wo
__device__ __half g_at_h[S * NHD], g_at_l[S * NHD];

// ---------------------------------------------------------------------------
// Convert fp32 operands -> f16 panels.
// ---------------------------------------------------------------------------
__global__ __launch_bounds__(256) void split_kernel(
    const float* __restrict__ xq, const float* __restrict__ xr,
    const float* __restrict__ w0, const float* __restrict__ w1,
    const float* __restrict__ w2, const float* __restrict__ w3,
    const float* __restrict__ w4)
{
    const int i = blockIdx.x * 256 + threadIdx.x;
    const float* src;
    __half* dst;
    int off;
    if (i < 1048576) {
        src = (i < 524288) ? xq : xr;
        dst = (i < 524288) ? g_xq : g_xr;
        off = i & 524287;
    } else {
        const int j = i - 1048576;
        const int w = j >> 18;
        off = j & 262143;
        const float* ws[5] = {w0, w1, w2, w3, w4};
        src = ws[w];
        dst = g_w16 + (size_t)w * (F * NHD);
    }
    float4 v = ((const float4*)src)[off];
    ((__half2*)dst)[off * 2]     = __floats2half2_rn(v.x, v.y);
    ((__half2*)dst)[off * 2 + 1] = __floats2half2_rn(v.z, v.w);
}

// ---------------------------------------------------------------------------
// f16 GEMM: C = (Ah [+ Al]) @ B + bias
// ---------------------------------------------------------------------------
#define GEMM_SMEM_BYTES 58368

template <bool SPLIT_A>
__device__ __forceinline__ void gemm_f16_body(
    const __half* __restrict__ Ah, const __half* __restrict__ Al,
    const __half* __restrict__ B,
    const float* __restrict__ bias, float* __restrict__ C,
    __half* __restrict__ C16, float scale,
    int M, int N, int K)
{
    extern __shared__ __half sh[];
    __half* As_h = sh;
    __half* As_l = sh + 10240;
    __half* Bs   = sh + 20480;

    const int t    = threadIdx.x;
    const int lane = t & 31;
    const int w    = t >> 5;
    const int wm   = (w & 3) * 32;
    const int wn   = (w >> 2) * 64;
    const int g    = lane >> 2;
    const int tg   = lane & 3;
    const int m0   = blockIdx.y * 128;
    const int n0   = blockIdx.x * 128;

    float Cr[2][8][4];
#pragma unroll
    for (int mt = 0; mt < 2; mt++)
#pragma unroll
        for (int nt = 0; nt < 8; nt++) {
            Cr[mt][nt][0] = 0.f; Cr[mt][nt][1] = 0.f;
            Cr[mt][nt][2] = 0.f; Cr[mt][nt][3] = 0.f;
        }

    const int fm = t >> 1, fh = (t & 1) * 16;
    const int fk = t >> 3, fv = (t & 7) * 16;

    const __half* gAh = Ah + (size_t)(m0 + fm) * K + fh;
    const __half* gAl = SPLIT_A ? Al + (size_t)(m0 + fm) * K + fh : nullptr;
    const __half* gB  = B  + (size_t)fk * N + n0 + fv;

    const int sa_off = fm * 40 + fh;
    const int sb_off = fk * 136 + fv;

    {
        u32 d;
        d = sptr(As_h + sa_off); cpa16(d, gAh); cpa16(d + 16, gAh + 8);
        if (SPLIT_A) {
            d = sptr(As_l + sa_off); cpa16(d, gAl); cpa16(d + 16, gAl + 8);
        }
        d = sptr(Bs + sb_off);   cpa16(d, gB);  cpa16(d + 16, gB + 8);
        CP_COMMIT();
        CP_WAIT0();
    }
    __syncthreads();

    int buf = 0;
    const int nkc = K / 32;
    for (int kc = 0; kc < nkc; kc++) {
        const bool has = (kc + 1) < nkc;
        if (has) {
            const __half* pAh = gAh + (kc + 1) * 32;
            const __half* pB  = gB + (size_t)(kc + 1) * 32 * N;
            const int nb = buf ^ 1;
            u32 d;
            d = sptr(As_h + nb * 5120 + sa_off); cpa16(d, pAh); cpa16(d + 16, pAh + 8);
            if (SPLIT_A) {
                const __half* pAl = gAl + (kc + 1) * 32;
                d = sptr(As_l + nb * 5120 + sa_off); cpa16(d, pAl); cpa16(d + 16, pAl + 8);
            }
            d = sptr(Bs + nb * 4352 + sb_off);   cpa16(d, pB);  cpa16(d + 16, pB + 8);
            CP_COMMIT();
        }
        const __half* Ab_h = As_h + buf * 5120;
        const __half* Ab_l = As_l + buf * 5120;
        const __half* Bb   = Bs + buf * 4352;

#pragma unroll
        for (int ks2 = 0; ks2 < 2; ks2++) {
            const int ks = ks2 * 16;
            u32 ah[2][4], al[2][4];
#pragma unroll
            for (int mt = 0; mt < 2; mt++) {
                const __half* r0 = Ab_h + (wm + mt * 16 + g) * 40 + ks + 2 * tg;
                ah[mt][0] = *(const u32*)r0;
                ah[mt][1] = *(const u32*)(r0 + 8 * 40);
                ah[mt][2] = *(const u32*)(r0 + 8);
                ah[mt][3] = *(const u32*)(r0 + 8 * 40 + 8);
                if (SPLIT_A) {
                    const __half* r1 = Ab_l + (wm + mt * 16 + g) * 40 + ks + 2 * tg;
                    al[mt][0] = *(const u32*)r1;
                    al[mt][1] = *(const u32*)(r1 + 8 * 40);
                    al[mt][2] = *(const u32*)(r1 + 8);
                    al[mt][3] = *(const u32*)(r1 + 8 * 40 + 8);
                }
            }
            const u32 bb = sptr(Bb + (ks + (lane & 15)) * 136 + wn);
#pragma unroll
            for (int nt = 0; nt < 8; nt++) {
                u32 b0, b1;
                ldm2t(b0, b1, bb + nt * 16);
#pragma unroll
                for (int mt = 0; mt < 2; mt++) {
                    mma_f16(Cr[mt][nt], ah[mt], b0, b1);
                    if (SPLIT_A) mma_f16(Cr[mt][nt], al[mt], b0, b1);
                }
            }
        }

        if (has) {
            CP_WAIT0();
            __syncthreads();
            buf ^= 1;
        }
    }

#pragma unroll
    for (int mt = 0; mt < 2; mt++) {
        const int row = m0 + wm + mt * 16 + g;
#pragma unroll
        for (int nt = 0; nt < 8; nt++) {
            const int col = n0 + wn + nt * 8 + 2 * tg;
            float2 b01 = *(const float2*)&bias[col];
            const float v00 = Cr[mt][nt][0] + b01.x;
            const float v01 = Cr[mt][nt][1] + b01.y;
            const float v10 = Cr[mt][nt][2] + b01.x;
            const float v11 = Cr[mt][nt][3] + b01.y;
            if (C) {
                *(float2*)(C + (size_t)row * N + col)       = make_float2(v00, v01);
                *(float2*)(C + (size_t)(row + 8) * N + col) = make_float2(v10, v11);
            }
            if (C16) {
                *(__half2*)(C16 + (size_t)row * N + col) =
                    __floats2half2_rn(v00 * scale, v01 * scale);
                *(__half2*)(C16 + (size_t)(row + 8) * N + col) =
                    __floats2half2_rn(v10 * scale, v11 * scale);
            }
        }
    }
}

__global__ __launch_bounds__(256, 2) void proj_f16_kernel(
    const float* __restrict__ bq, const float* __restrict__ bk,
    const float* __restrict__ bv, const float* __restrict__ br)
{
    const int z = blockIdx.z;
    const __half* A = (z < 3) ? g_xq : g_xr;
    const __half* B = g_w16 + (size_t)z * (F * NHD);
    const float* bias;
    __half* C16;
    float scale = 1.f;
    switch (z) {
        case 0:  bias = bq; C16 = g_q16; scale = SCQ; break;
        case 1:  bias = bk; C16 = g_k16; break;
        case 2:  bias = bv; C16 = g_v16; break;
        default: bias = br; C16 = g_r16; break;
    }
    gemm_f16_body<false>(A, nullptr, B, bias, nullptr, C16, scale, S, NHD, F);
}

__global__ __launch_bounds__(256, 2) void out_f16_kernel(
    const float* __restrict__ bo, float* __restrict__ out)
{
    gemm_f16_body<true>(g_at_h, g_at_l, g_w16 + (size_t)4 * (F * NHD),
                        bo, out, nullptr, 1.f, S, F, NHD);
}

// ---------------------------------------------------------------------------
// ck[h][j] = SCQ * rw[h].k16[j,h,:],  cr[h][m] = SCQ * rr[h].r16[m,h,:]
// (reads the same f16 operands the attention MMA consumes)
// ---------------------------------------------------------------------------
__global__ __launch_bounds__(256) void bias_dots_kernel(
    const float* __restrict__ rwb, const float* __restrict__ rrb)
{
    const int gw   = (blockIdx.x * blockDim.x + threadIdx.x) >> 5;
    const int lane = threadIdx.x & 31;
    const int which = gw >= H * S;
    const int idx   = which ? gw - H * S : gw;
    const int hh = idx >> 11;
    const int j  = idx & (S - 1);
    const float* bias = which ? rrb : rwb;
    const __half* mat = which ? g_r16 : g_k16;
    const float b0 = bias[hh * DH + lane];
    const float b1 = bias[hh * DH + 32 + lane];
    const __half* row = mat + (size_t)j * NHD + hh * DH;
    float s = fmaf(b0, __half2float(row[lane]),
                   b1 * __half2float(row[32 + lane]));
#pragma unroll
    for (int off = 16; off > 0; off >>= 1)
        s += __shfl_xor_sync(0xffffffffu, s, off);
    if (lane == 0) {
        float* dst = which ? g_cr : g_ck;
        dst[hh * S + j] = s * SCQ;
    }
}

// ---------------------------------------------------------------------------
// Causal flash attention, all-f16 MMA (k16), log2-domain softmax.
// R16: exp results feed PV a-frags DIRECTLY from registers (layout match);
// P smem staging + syncwarp deleted.
// ---------------------------------------------------------------------------
#define KP16 72
#define GPAD 132
#define SMEM_ATTN ((64*KP16 + 64*KP16 + 128*KP16)*2 + (64*GPAD)*4 + (128+64+128)*4)

__global__ __launch_bounds__(256, 2) void attn_kernel()
{
    const int h   = blockIdx.y;
    const int qi0 = (gridDim.x - 1 - blockIdx.x) * 64;

    extern __shared__ float sm[];
    __half* ks16  = (__half*)sm;
    __half* vs16  = ks16 + 64 * KP16;
    __half* rsl16 = vs16 + 64 * KP16;
    float*  G     = (float*)(rsl16 + 128 * KP16);
    float*  crs_s = G + 64 * GPAD;
    float*  cks_s = crs_s + 128;
    float*  mx    = cks_s + 64;

    const int t    = threadIdx.x;
    const int lane = t & 31;
    const int w    = t >> 5;
    const int wp   = w & 3;
    const int half = w >> 2;
    const int g    = lane >> 2;
    const int tg   = lane & 3;
    const int i0   = wp * 16 + g;
    const int hb   = h * DH;
    const int jbase = half * 32;
    const int tile0 = (half == 0) ? (6 - 2 * wp) : (11 - 2 * wp);

    u32 qa[4][4];
    {
        const __half* q0 = &g_q16[(size_t)(qi0 + i0) * NHD + hb];
        const __half* q1 = q0 + 8 * NHD;
#pragma unroll
        for (int k0 = 0; k0 < 4; k0++) {
            qa[k0][0] = *(const u32*)(q0 + k0 * 16 + 2 * tg);
            qa[k0][1] = *(const u32*)(q1 + k0 * 16 + 2 * tg);
            qa[k0][2] = *(const u32*)(q0 + k0 * 16 + 8 + 2 * tg);
            qa[k0][3] = *(const u32*)(q1 + k0 * 16 + 8 + 2 * tg);
        }
    }

    if (t < 64) {
        __half* p = &vs16[t * KP16 + 64];
        p[0] = __float2half(1.f);
#pragma unroll
        for (int i = 1; i < 8; i++) p[i] = __float2half(0.f);
    }

    float O[9][4];
#pragma unroll
    for (int nt = 0; nt < 9; nt++) {
        O[nt][0] = 0.f; O[nt][1] = 0.f; O[nt][2] = 0.f; O[nt][3] = 0.f;
    }
    float m0 = -1e30f, m1 = -1e30f;

    const int nkt = qi0 / 64 + 1;
    for (int kt = 0; kt < nkt; kt++) {
        const int kj0   = kt * 64;
        const int base  = (S - 1) + kj0 - qi0 - 63;
        const int rbase = base & 127;
        __syncthreads();

#pragma unroll
        for (int it = 0; it < 2; it++) {
            const int idx = t + it * 256;
            const int r = idx >> 3, c8 = (idx & 7) << 3;
            cpa16(sptr(&ks16[r * KP16 + c8]),
                  &g_k16[(size_t)(kj0 + r) * NHD + hb + c8]);
            cpa16(sptr(&vs16[r * KP16 + c8]),
                  &g_v16[(size_t)(kj0 + r) * NHD + hb + c8]);
        }
        {
            const int rl0 = (kt == 0) ? 0 : 64;
            const int nit = (kt == 0) ? 4 : 2;
            for (int it = 0; it < nit; it++) {
                const int idx = t + it * 256;
                const int row = rl0 + (idx >> 3);
                const int c8  = (idx & 7) << 3;
                int mg = base + row;
                if (mg > S - 1) mg = S - 1;
                cpa16(sptr(&rsl16[((rbase + row) & 127) * KP16 + c8]),
                      &g_r16[(size_t)mg * NHD + hb + c8]);
            }
        }
        if (t < 64) cks_s[t] = g_ck[h * S + kj0 + t];
        else if (t < 192) {
            const int mm = t - 64;
            int mg = base + mm;
            if (mg > S - 1) mg = S - 1;
            crs_s[mm] = (mm < 127) ? g_cr[h * S + mg] : 0.f;
        }
        CP_COMMIT();
        CP_WAIT0();
        __syncthreads();

        // ---- windowed G = Q @ RSL^T (+cr): 5 tiles, f16 k16 ----
        {
            u32 rb[5];
#pragma unroll
            for (int ni = 0; ni < 5; ni++) {
                const int lrow = (rbase + (tile0 + ni) * 8 + (lane & 7)) & 127;
                rb[ni] = sptr(&rsl16[lrow * KP16 + ((lane >> 3) & 1) * 8]);
            }
            float gc[5][4];
#pragma unroll
            for (int ni = 0; ni < 5; ni++) {
                const int col = (tile0 + ni) * 8 + 2 * tg;
                gc[ni][0] = crs_s[col];
                gc[ni][1] = crs_s[col + 1];
                gc[ni][2] = gc[ni][0];
                gc[ni][3] = gc[ni][1];
            }
#pragma unroll
            for (int k0 = 0; k0 < 4; k0++) {
#pragma unroll
                for (int ni = 0; ni < 5; ni++) {
                    u32 b0, b1;
                    ldm2(b0, b1, rb[ni] + k0 * 32);
                    mma_f16(gc[ni], qa[k0], b0, b1);
                }
            }
#pragma unroll
            for (int ni = 0; ni < 5; ni++) {
                const int col = (tile0 + ni) * 8 + 2 * tg;
                *(float2*)&G[i0 * GPAD + col]       = make_float2(gc[ni][0], gc[ni][1]);
                *(float2*)&G[(i0 + 8) * GPAD + col] = make_float2(gc[ni][2], gc[ni][3]);
            }
        }
        pair_bar(wp);

        // ---- AC = Q @ K^T (+ck), own 32-key half ----
        float sc[4][4];
        u32 kb4[4];
#pragma unroll
        for (int nt = 0; nt < 4; nt++) {
            const int col = jbase + nt * 8 + 2 * tg;
            sc[nt][0] = cks_s[col];
            sc[nt][1] = cks_s[col + 1];
            sc[nt][2] = sc[nt][0];
            sc[nt][3] = sc[nt][1];
            kb4[nt] = sptr(&ks16[(jbase + nt * 8 + (lane & 7)) * KP16 +
                                 ((lane >> 3) & 1) * 8]);
        }
#pragma unroll
        for (int k0 = 0; k0 < 4; k0++) {
#pragma unroll
            for (int nt = 0; nt < 4; nt++) {
                u32 b0, b1;
                ldm2(b0, b1, kb4[nt] + k0 * 32);
                mma_f16(sc[nt], qa[k0], b0, b1);
            }
        }

        // ---- BD gather + mask + own-half row max ----
        const bool diag = (kt == nkt - 1);
        float rmax0 = -1e30f, rmax1 = -1e30f;
#pragma unroll
        for (int nt = 0; nt < 4; nt++) {
            const int j = jbase + nt * 8 + 2 * tg;
            float s00 = sc[nt][0] + G[i0 * GPAD + 63 + j - i0];
            float s01 = sc[nt][1] + G[i0 * GPAD + 64 + j - i0];
            float s10 = sc[nt][2] + G[(i0 + 8) * GPAD + 55 + j - i0];
            float s11 = sc[nt][3] + G[(i0 + 8) * GPAD + 56 + j - i0];
            if (diag) {
                if (kj0 + j     > qi0 + i0)     s00 = -1e30f;
                if (kj0 + j + 1 > qi0 + i0)     s01 = -1e30f;
                if (kj0 + j     > qi0 + i0 + 8) s10 = -1e30f;
                if (kj0 + j + 1 > qi0 + i0 + 8) s11 = -1e30f;
            }
            sc[nt][0] = s00; sc[nt][1] = s01; sc[nt][2] = s10; sc[nt][3] = s11;
            rmax0 = fmaxf(rmax0, fmaxf(s00, s01));
            rmax1 = fmaxf(rmax1, fmaxf(s10, s11));
        }
        rmax0 = fmaxf(rmax0, __shfl_xor_sync(0xffffffffu, rmax0, 1));
        rmax0 = fmaxf(rmax0, __shfl_xor_sync(0xffffffffu, rmax0, 2));
        rmax1 = fmaxf(rmax1, __shfl_xor_sync(0xffffffffu, rmax1, 1));
        rmax1 = fmaxf(rmax1, __shfl_xor_sync(0xffffffffu, rmax1, 2));

        mx[2 * i0 + half]       = rmax0;
        mx[2 * (i0 + 8) + half] = rmax1;
        pair_bar(wp);
        rmax0 = fmaxf(rmax0, mx[2 * i0 + (half ^ 1)]);
        rmax1 = fmaxf(rmax1, mx[2 * (i0 + 8) + (half ^ 1)]);

        const float newm0 = fmaxf(m0, rmax0);
        const float newm1 = fmaxf(m1, rmax1);
        const float a0 = exp2f(m0 - newm0);
        const float a1 = exp2f(m1 - newm1);
        m0 = newm0; m1 = newm1;
#pragma unroll
        for (int nt = 0; nt < 9; nt++) {
            O[nt][0] *= a0; O[nt][1] *= a0;
            O[nt][2] *= a1; O[nt][3] *= a1;
        }

        // ---- p = 2^(s-m): results ARE the PV a-frag pairs (no smem) ----
        u32 pp[4][2];
#pragma unroll
        for (int nt = 0; nt < 4; nt++) {
            pp[nt][0] = exp2_f16x2(sc[nt][0] - m0, sc[nt][1] - m0);  // rows i0
            pp[nt][1] = exp2_f16x2(sc[nt][2] - m1, sc[nt][3] - m1);  // rows i0+8
        }

        // ---- PV (f16 k16): O += P_half @ [V | 1], a-frags from registers ----
#pragma unroll
        for (int ki = 0; ki < 2; ki++) {
            const int kb = jbase + ki * 16;
            u32 pa[4];
            pa[0] = pp[2 * ki][0];
            pa[1] = pp[2 * ki][1];
            pa[2] = pp[2 * ki + 1][0];
            pa[3] = pp[2 * ki + 1][1];
            const u32 vb = sptr(vs16 + (size_t)(kb + (lane & 15)) * KP16);
#pragma unroll
            for (int nt = 0; nt < 9; nt++) {
                u32 b0, b1;
                ldm2t(b0, b1, vb + nt * 16);
                mma_f16(O[nt], pa, b0, b1);
            }
        }
    }

    float l0 = __shfl_sync(0xffffffffu, O[8][0], lane & 28);
    float l1 = __shfl_sync(0xffffffffu, O[8][2], lane & 28);

    __syncthreads();
    if (half == 1) {
#pragma unroll
        for (int nt = 0; nt < 8; nt++) {
            const int col = nt * 8 + 2 * tg;
            *(float2*)&G[i0 * GPAD + col]       = make_float2(O[nt][0], O[nt][1]);
            *(float2*)&G[(i0 + 8) * GPAD + col] = make_float2(O[nt][2], O[nt][3]);
        }
        if (tg == 0) {
            cks_s[i0]     = l0;
            cks_s[i0 + 8] = l1;
        }
    }
    __syncthreads();
    if (half == 0) {
        l0 += cks_s[i0];
        l1 += cks_s[i0 + 8];
        const float inv0 = 1.f / l0;
        const float inv1 = 1.f / l1;
#pragma unroll
        for (int nt = 0; nt < 8; nt++) {
            const int col = nt * 8 + 2 * tg;
            float2 p0 = *(const float2*)&G[i0 * GPAD + col];
            float2 p1 = *(const float2*)&G[(i0 + 8) * GPAD + col];
            float o00 = (O[nt][0] + p0.x) * inv0, o01 = (O[nt][1] + p0.y) * inv0;
            float o10 = (O[nt][2] + p1.x) * inv1, o11 = (O[nt][3] + p1.y) * inv1;
            const size_t idx0 = (size_t)(qi0 + i0) * NHD + hb + col;
            const size_t idx1 = (size_t)(qi0 + i0 + 8) * NHD + hb + col;
            __half2 h0 = __floats2half2_rn(o00, o01);
            __half2 h1 = __floats2half2_rn(o10, o11);
            float2 f0 = __half22float2(h0);
            float2 f1 = __half22float2(h1);
            __half2 L0 = __floats2half2_rn(o00 - f0.x, o01 - f0.y);
            __half2 L1 = __floats2half2_rn(o10 - f1.x, o11 - f1.y);
            *(__half2*)&g_at_h[idx0] = h0;
            *(__half2*)&g_at_l[idx0] = L0;
            *(__half2*)&g_at_h[idx1] = h1;
            *(__half2*)&g_at_l[idx1] = L1;
        }
    }
}

// ---------------------------------------------------------------------------
extern "C" void kernel_launch(void* const* d_in, const int* in_sizes, int n_in,
                              void* d_out, int out_size)
{
    const float* inputs_q = (const float*)d_in[0];
    const float* pos_emb  = (const float*)d_in[1];
    const float* r_w_bias = (const float*)d_in[2];
    const float* r_r_bias = (const float*)d_in[3];
    const float* Wq = (const float*)d_in[4];
    const float* bq = (const float*)d_in[5];
    const float* Wk = (const float*)d_in[6];
    const float* bk = (const float*)d_in[7];
    const float* Wv = (const float*)d_in[8];
    const float* bv = (const float*)d_in[9];
    const float* Wr = (const float*)d_in[10];
    const float* br = (const float*)d_in[11];
    const float* Wo = (const float*)d_in[12];
    const float* bo = (const float*)d_in[13];
    float* out = (float*)d_out;

    cudaFuncSetAttribute(attn_kernel,
                         cudaFuncAttributeMaxDynamicSharedMemorySize, SMEM_ATTN);
    cudaFuncSetAttribute(proj_f16_kernel,
                         cudaFuncAttributeMaxDynamicSharedMemorySize, GEMM_SMEM_BYTES);
    cudaFuncSetAttribute(out_f16_kernel,
                         cudaFuncAttributeMaxDynamicSharedMemorySize, GEMM_SMEM_BYTES);

    split_kernel<<<(2 * 524288 + 5 * 262144) / 256, 256>>>(
        inputs_q, pos_emb, Wq, Wk, Wv, Wr, Wo);

    proj_f16_kernel<<<dim3(NHD / 128, S / 128, 4), 256, GEMM_SMEM_BYTES>>>(
        bq, bk, bv, br);

    bias_dots_kernel<<<(2 * H * S * 32) / 256, 256>>>(r_w_bias, r_r_bias);

    attn_kernel<<<dim3(S / 64, H), 256, SMEM_ATTN>>>();

    out_f16_kernel<<<dim3(F / 128, S / 128), 256, GEMM_SMEM_BYTES>>>(bo, out);
}